// round 4
// baseline (speedup 1.0000x reference)
#include <cuda_runtime.h>

#define MAX_NODES 20000
#define MAX_EDGES 160000
#define HID 256
#define NUM_GRAPHS 16

// ---------------- device scratch (static, no runtime alloc) ----------------
__device__ float g_bufA[MAX_NODES * HID];   // y_nbr projections
__device__ float g_bufB[MAX_NODES * HID];   // y_self projections (+bias)
__device__ float g_bufC[MAX_NODES * HID];   // h1 / h2
__device__ int   g_deg[MAX_NODES];
__device__ int   g_rowstart[MAX_NODES + 1];
__device__ int   g_cursor[MAX_NODES];
__device__ int   g_csr[MAX_EDGES];
__device__ float g_pool[NUM_GRAPHS * HID];
__device__ int   g_is64;                    // 1 if index inputs are int64

// ---------------- dtype-agnostic index accessors ----------------
__device__ __forceinline__ int getIdx(const void* p, int i, int is64) {
    if (is64) return (int)((const long long*)p)[i];
    return ((const int*)p)[i];
}

// probe: decide whether the edge buffer is int64 or int32.
// If data is int32, int64-interpretation of (src,dst) pairs is out of range.
__global__ void probe_dtype(const void* ei, int ne, int n) {
    __shared__ int bad;
    if (threadIdx.x == 0) bad = 0;
    __syncthreads();
    int local = 0;
    for (int e = threadIdx.x; e < ne; e += blockDim.x) {
        long long v = ((const long long*)ei)[e];
        if (v < 0 || v >= (long long)n) local = 1;
    }
    if (local) bad = 1;
    __syncthreads();
    if (threadIdx.x == 0) g_is64 = bad ? 0 : 1;
}

// ---------------- misc kernels ----------------
__global__ void zero_kernel(int n_nodes) {
    int i = blockIdx.x * blockDim.x + threadIdx.x;
    if (i < n_nodes) g_deg[i] = 0;
    if (i < NUM_GRAPHS * HID) g_pool[i] = 0.0f;
}

__global__ void edge_hist(const void* __restrict__ ei, int ne) {
    int e = blockIdx.x * blockDim.x + threadIdx.x;
    int is64 = g_is64;
    if (e < ne) {
        int d = getIdx(ei, ne + e, is64);   // dst row
        atomicAdd(&g_deg[d], 1);
    }
}

// single-block exclusive scan of g_deg -> g_rowstart (+cursor copy)
__global__ void scan_deg(int n) {
    __shared__ int partial[1024];
    int t = threadIdx.x;
    const int per = (n + 1023) / 1024;
    int base = t * per;
    int sum = 0;
    for (int k = 0; k < per; k++) {
        int idx = base + k;
        if (idx < n) sum += g_deg[idx];
    }
    partial[t] = sum;
    __syncthreads();
    for (int off = 1; off < 1024; off <<= 1) {
        int v = (t >= off) ? partial[t - off] : 0;
        __syncthreads();
        partial[t] += v;
        __syncthreads();
    }
    int run = (t == 0) ? 0 : partial[t - 1];
    for (int k = 0; k < per; k++) {
        int idx = base + k;
        if (idx < n) {
            int d = g_deg[idx];
            g_rowstart[idx] = run;
            g_cursor[idx] = run;
            run += d;
        }
    }
    if (t == 1023) g_rowstart[n] = run;
}

__global__ void csr_fill(const void* __restrict__ ei, int ne) {
    int e = blockIdx.x * blockDim.x + threadIdx.x;
    int is64 = g_is64;
    if (e < ne) {
        int s = getIdx(ei, e, is64);        // src
        int d = getIdx(ei, ne + e, is64);   // dst
        int p = atomicAdd(&g_cursor[d], 1);
        g_csr[p] = s;
    }
}

// ---------------- dual GEMM: g_bufA = A@Wn ; g_bufB = A@Ws + bias ----------
// A is selected inside the kernel: src_sel==0 -> external x, else g_bufC.
#define BM 128
#define BN 128
#define BK 16

__global__ __launch_bounds__(256, 2) void gemm_dual(
    const float* __restrict__ Xext, int src_sel, int M, int K,
    const float* __restrict__ Wn, const float* __restrict__ Ws,
    const float* __restrict__ bias) {
    __shared__ float As[BK][BM];
    __shared__ float Bs[BK][BN];

    const float* A = src_sel ? (const float*)g_bufC : Xext;

    const int bm = blockIdx.x * BM;
    const int by = blockIdx.y;                 // 0..3 over combined N=512
    const bool isS = by >= 2;
    const float* W = isS ? Ws : Wn;
    float* Y = isS ? (float*)g_bufB : (float*)g_bufA;
    const int bn = (isS ? by - 2 : by) * BN;   // 0 or 128 within 256-wide output

    const int tid = threadIdx.x;
    const int tx = tid & 15;
    const int ty = tid >> 4;

    float acc[8][8];
#pragma unroll
    for (int i = 0; i < 8; i++)
#pragma unroll
        for (int j = 0; j < 8; j++) acc[i][j] = 0.0f;

    for (int k0 = 0; k0 < K; k0 += BK) {
        // load A tile (BM x BK), store transposed As[k][m]
#pragma unroll
        for (int r = 0; r < 2; r++) {
            int lin = tid + r * 256;           // 512 float4 slots
            int row = lin >> 2;
            int kq = lin & 3;
            int gr = bm + row;
            float4 v = make_float4(0.f, 0.f, 0.f, 0.f);
            if (gr < M) v = *(const float4*)(A + (size_t)gr * K + k0 + kq * 4);
            As[kq * 4 + 0][row] = v.x;
            As[kq * 4 + 1][row] = v.y;
            As[kq * 4 + 2][row] = v.z;
            As[kq * 4 + 3][row] = v.w;
        }
        // load B tile (BK x BN)
#pragma unroll
        for (int r = 0; r < 2; r++) {
            int lin = tid + r * 256;           // 512 float4 slots
            int kr = lin >> 5;
            int c4 = lin & 31;
            float4 w = *(const float4*)(W + (size_t)(k0 + kr) * HID + bn + c4 * 4);
            *(float4*)&Bs[kr][c4 * 4] = w;
        }
        __syncthreads();

#pragma unroll
        for (int kk = 0; kk < BK; kk++) {
            float a[8], b[8];
            float4 a0 = *(const float4*)&As[kk][ty * 8];
            float4 a1 = *(const float4*)&As[kk][ty * 8 + 4];
            a[0] = a0.x; a[1] = a0.y; a[2] = a0.z; a[3] = a0.w;
            a[4] = a1.x; a[5] = a1.y; a[6] = a1.z; a[7] = a1.w;
            float4 b0 = *(const float4*)&Bs[kk][tx * 8];
            float4 b1 = *(const float4*)&Bs[kk][tx * 8 + 4];
            b[0] = b0.x; b[1] = b0.y; b[2] = b0.z; b[3] = b0.w;
            b[4] = b1.x; b[5] = b1.y; b[6] = b1.z; b[7] = b1.w;
#pragma unroll
            for (int i = 0; i < 8; i++)
#pragma unroll
                for (int j = 0; j < 8; j++)
                    acc[i][j] = fmaf(a[i], b[j], acc[i][j]);
        }
        __syncthreads();
    }

    // epilogue
    float bb[8];
#pragma unroll
    for (int j = 0; j < 8; j++) bb[j] = 0.f;
    if (isS) {
        float4 t0 = *(const float4*)(bias + bn + tx * 8);
        float4 t1 = *(const float4*)(bias + bn + tx * 8 + 4);
        bb[0] = t0.x; bb[1] = t0.y; bb[2] = t0.z; bb[3] = t0.w;
        bb[4] = t1.x; bb[5] = t1.y; bb[6] = t1.z; bb[7] = t1.w;
    }
#pragma unroll
    for (int i = 0; i < 8; i++) {
        int gm = bm + ty * 8 + i;
        if (gm >= M) continue;
        float* yrow = Y + (size_t)gm * HID + bn + tx * 8;
        float4 o0, o1;
        o0.x = acc[i][0] + bb[0]; o0.y = acc[i][1] + bb[1];
        o0.z = acc[i][2] + bb[2]; o0.w = acc[i][3] + bb[3];
        o1.x = acc[i][4] + bb[4]; o1.y = acc[i][5] + bb[5];
        o1.z = acc[i][6] + bb[6]; o1.w = acc[i][7] + bb[7];
        *(float4*)(yrow)     = o0;
        *(float4*)(yrow + 4) = o1;
    }
}

// ---- aggregation: g_bufC[i] = relu( mean_{s in N(i)} g_bufA[s] + g_bufB[i] )
__global__ void sage_aggregate() {
    int i = blockIdx.x;
    int c = threadIdx.x;  // 256
    int s0 = g_rowstart[i];
    int s1 = g_rowstart[i + 1];
    float acc = 0.f;
    for (int j = s0; j < s1; j++) {
        int s = g_csr[j];
        acc += g_bufA[(size_t)s * HID + c];
    }
    int d = s1 - s0;
    float inv = 1.0f / (float)(d > 0 ? d : 1);
    float v = acc * inv + g_bufB[(size_t)i * HID + c];
    g_bufC[(size_t)i * HID + c] = fmaxf(v, 0.f);
}

// ---------------- pooling ----------------
__device__ __forceinline__ int lower_bound_idx(const void* a, int n,
                                               int v, int is64) {
    int lo = 0, hi = n;
    while (lo < hi) {
        int mid = (lo + hi) >> 1;
        if (getIdx(a, mid, is64) < v) lo = mid + 1; else hi = mid;
    }
    return lo;
}

__global__ void pool_kernel(const void* __restrict__ batch, int n) {
    int g = blockIdx.x;
    int s = blockIdx.y;
    int S = gridDim.y;
    int is64 = g_is64;
    int lo = lower_bound_idx(batch, n, g, is64);
    int hi = lower_bound_idx(batch, n, g + 1, is64);
    int cnt = hi - lo;
    int chunk = (cnt + S - 1) / S;
    int a = lo + s * chunk;
    int b = a + chunk;
    if (b > hi) b = hi;
    int c = threadIdx.x;
    float acc = 0.f;
    for (int i = a; i < b; i++) acc += g_bufC[(size_t)i * HID + c];
    if (a < b) atomicAdd(&g_pool[g * HID + c], acc);
}

// ---------------- head MLP ----------------
__global__ void head_kernel(const void* __restrict__ batch, int n,
                            const float* __restrict__ fc1w,
                            const float* __restrict__ fc1b,
                            const float* __restrict__ fc2w,
                            const float* __restrict__ fc2b,
                            float* __restrict__ out) {
    __shared__ float pooled[HID];
    __shared__ float t1[HID / 2];
    int t = threadIdx.x;  // 256
    int is64 = g_is64;
    for (int g = 0; g < NUM_GRAPHS; g++) {
        int lo = lower_bound_idx(batch, n, g, is64);
        int hi = lower_bound_idx(batch, n, g + 1, is64);
        float cnt = fmaxf((float)(hi - lo), 1.0f);
        pooled[t] = g_pool[g * HID + t] / cnt;
        __syncthreads();
        if (t < HID / 2) {
            float s = fc1b[t];
            for (int c = 0; c < HID; c++) s += pooled[c] * fc1w[c * (HID / 2) + t];
            t1[t] = fmaxf(s, 0.f);
        }
        __syncthreads();
        if (t < 2) {
            float s = fc2b[t];
            for (int j = 0; j < HID / 2; j++) s += t1[j] * fc2w[j * 2 + t];
            out[g * 2 + t] = s;
        }
        __syncthreads();
    }
}

// ---------------- launch ----------------
extern "C" void kernel_launch(void* const* d_in, const int* in_sizes, int n_in,
                              void* d_out, int out_size) {
    const float* x = (const float*)d_in[0];
    const void* ei = d_in[1];
    const void* batch = d_in[2];
    const float* W1n = (const float*)d_in[3];
    const float* W1s = (const float*)d_in[4];
    const float* b1 = (const float*)d_in[5];
    const float* W2n = (const float*)d_in[6];
    const float* W2s = (const float*)d_in[7];
    const float* b2 = (const float*)d_in[8];
    const float* fc1w = (const float*)d_in[9];
    const float* fc1b = (const float*)d_in[10];
    const float* fc2w = (const float*)d_in[11];
    const float* fc2b = (const float*)d_in[12];
    float* out = (float*)d_out;

    const int n = in_sizes[2];            // 20000 nodes
    const int in_dim = in_sizes[0] / n;   // 512
    const int ne = in_sizes[1] / 2;       // 160000 edges

    // dtype probe + CSR build + zero scratch
    probe_dtype<<<1, 1024>>>(ei, ne, n);
    zero_kernel<<<(n + 255) / 256, 256>>>(n);
    edge_hist<<<(ne + 255) / 256, 256>>>(ei, ne);
    scan_deg<<<1, 1024>>>(n);
    csr_fill<<<(ne + 255) / 256, 256>>>(ei, ne);

    dim3 g1((n + BM - 1) / BM, 4);

    // Layer 1: project first (linearity of segment-sum), then aggregate
    gemm_dual<<<g1, 256>>>(x, 0, n, in_dim, W1n, W1s, b1);
    sage_aggregate<<<n, HID>>>();                  // h1 -> g_bufC

    // Layer 2
    gemm_dual<<<g1, 256>>>(x, 1, n, HID, W2n, W2s, b2);
    sage_aggregate<<<n, HID>>>();                  // h2 -> g_bufC

    // Pool + head
    dim3 gp(NUM_GRAPHS, 32);
    pool_kernel<<<gp, HID>>>(batch, n);
    head_kernel<<<1, HID>>>(batch, n, fc1w, fc1b, fc2w, fc2b, out);
}

// round 5
// speedup vs baseline: 1.1097x; 1.1097x over previous
#include <cuda_runtime.h>

#define MAX_NODES 20000
#define MAX_EDGES 160000
#define HID 256
#define NUM_GRAPHS 16

// ---------------- device scratch (static, no runtime alloc) ----------------
__device__ float g_bufA[MAX_NODES * HID];   // y_nbr projections
__device__ float g_bufB[MAX_NODES * HID];   // y_self projections (+bias)
__device__ float g_bufC[MAX_NODES * HID];   // h1 / h2
__device__ int   g_deg[MAX_NODES];
__device__ int   g_rowstart[MAX_NODES + 1];
__device__ int   g_cursor[MAX_NODES];
__device__ int   g_csr[MAX_EDGES];
__device__ float g_pool[NUM_GRAPHS * HID];
__device__ int   g_is64;                    // 1 if index inputs are int64

// ---------------- f32x2 packed helpers (PTX-only, sm_100+) ----------------
__device__ __forceinline__ unsigned long long pack2(float x) {
    unsigned long long r;
    unsigned u = __float_as_uint(x);
    asm("mov.b64 %0, {%1, %1};" : "=l"(r) : "r"(u));
    return r;
}
__device__ __forceinline__ unsigned long long fma2(unsigned long long a,
                                                   unsigned long long b,
                                                   unsigned long long c) {
    unsigned long long d;
    asm("fma.rn.f32x2 %0, %1, %2, %3;" : "=l"(d) : "l"(a), "l"(b), "l"(c));
    return d;
}
__device__ __forceinline__ float2 unpack2(unsigned long long v) {
    unsigned lo, hi;
    asm("mov.b64 {%0, %1}, %2;" : "=r"(lo), "=r"(hi) : "l"(v));
    return make_float2(__uint_as_float(lo), __uint_as_float(hi));
}

// ---------------- dtype-agnostic index accessors ----------------
__device__ __forceinline__ int getIdx(const void* p, int i, int is64) {
    if (is64) return (int)((const long long*)p)[i];
    return ((const int*)p)[i];
}

// probe: decide whether the edge buffer is int64 or int32.
__global__ void probe_dtype(const void* ei, int ne, int n) {
    __shared__ int bad;
    if (threadIdx.x == 0) bad = 0;
    __syncthreads();
    int local = 0;
    for (int e = threadIdx.x; e < ne; e += blockDim.x) {
        long long v = ((const long long*)ei)[e];
        if (v < 0 || v >= (long long)n) local = 1;
    }
    if (local) bad = 1;
    __syncthreads();
    if (threadIdx.x == 0) g_is64 = bad ? 0 : 1;
}

// ---------------- misc kernels ----------------
__global__ void zero_kernel(int n_nodes) {
    int i = blockIdx.x * blockDim.x + threadIdx.x;
    if (i < n_nodes) g_deg[i] = 0;
    if (i < NUM_GRAPHS * HID) g_pool[i] = 0.0f;
}

__global__ void edge_hist(const void* __restrict__ ei, int ne) {
    int e = blockIdx.x * blockDim.x + threadIdx.x;
    int is64 = g_is64;
    if (e < ne) {
        int d = getIdx(ei, ne + e, is64);   // dst row
        atomicAdd(&g_deg[d], 1);
    }
}

// single-block exclusive scan of g_deg -> g_rowstart (+cursor copy)
__global__ void scan_deg(int n) {
    __shared__ int partial[1024];
    int t = threadIdx.x;
    const int per = (n + 1023) / 1024;
    int base = t * per;
    int sum = 0;
    for (int k = 0; k < per; k++) {
        int idx = base + k;
        if (idx < n) sum += g_deg[idx];
    }
    partial[t] = sum;
    __syncthreads();
    for (int off = 1; off < 1024; off <<= 1) {
        int v = (t >= off) ? partial[t - off] : 0;
        __syncthreads();
        partial[t] += v;
        __syncthreads();
    }
    int run = (t == 0) ? 0 : partial[t - 1];
    for (int k = 0; k < per; k++) {
        int idx = base + k;
        if (idx < n) {
            int d = g_deg[idx];
            g_rowstart[idx] = run;
            g_cursor[idx] = run;
            run += d;
        }
    }
    if (t == 1023) g_rowstart[n] = run;
}

__global__ void csr_fill(const void* __restrict__ ei, int ne) {
    int e = blockIdx.x * blockDim.x + threadIdx.x;
    int is64 = g_is64;
    if (e < ne) {
        int s = getIdx(ei, e, is64);        // src
        int d = getIdx(ei, ne + e, is64);   // dst
        int p = atomicAdd(&g_cursor[d], 1);
        g_csr[p] = s;
    }
}

// ---------------- dual GEMM: g_bufA = A@Wn ; g_bufB = A@Ws + bias ----------
// A is selected inside the kernel: src_sel==0 -> external x, else g_bufC.
#define BM 128
#define BN 128
#define BK 16

__global__ __launch_bounds__(256, 2) void gemm_dual(
    const float* __restrict__ Xext, int src_sel, int M, int K,
    const float* __restrict__ Wn, const float* __restrict__ Ws,
    const float* __restrict__ bias) {
    __shared__ float As[BK][BM];
    __shared__ float Bs[BK][BN];

    const float* A = src_sel ? (const float*)g_bufC : Xext;

    const int bm = blockIdx.x * BM;
    const int by = blockIdx.y;                 // 0..3 over combined N=512
    const bool isS = by >= 2;
    const float* W = isS ? Ws : Wn;
    float* Y = isS ? (float*)g_bufB : (float*)g_bufA;
    const int bn = (isS ? by - 2 : by) * BN;   // 0 or 128 within 256-wide output

    const int tid = threadIdx.x;
    const int tx = tid & 15;
    const int ty = tid >> 4;

    unsigned long long acc[8][4];
#pragma unroll
    for (int i = 0; i < 8; i++)
#pragma unroll
        for (int j = 0; j < 4; j++) acc[i][j] = 0ull;

    for (int k0 = 0; k0 < K; k0 += BK) {
        // load A tile (BM x BK), store transposed As[k][m]
#pragma unroll
        for (int r = 0; r < 2; r++) {
            int lin = tid + r * 256;           // 512 float4 slots
            int row = lin >> 2;
            int kq = lin & 3;
            int gr = bm + row;
            float4 v = make_float4(0.f, 0.f, 0.f, 0.f);
            if (gr < M) v = *(const float4*)(A + (size_t)gr * K + k0 + kq * 4);
            As[kq * 4 + 0][row] = v.x;
            As[kq * 4 + 1][row] = v.y;
            As[kq * 4 + 2][row] = v.z;
            As[kq * 4 + 3][row] = v.w;
        }
        // load B tile (BK x BN)
#pragma unroll
        for (int r = 0; r < 2; r++) {
            int lin = tid + r * 256;           // 512 float4 slots
            int kr = lin >> 5;
            int c4 = lin & 31;
            float4 w = *(const float4*)(W + (size_t)(k0 + kr) * HID + bn + c4 * 4);
            *(float4*)&Bs[kr][c4 * 4] = w;
        }
        __syncthreads();

#pragma unroll
        for (int kk = 0; kk < BK; kk++) {
            float4 a0 = *(const float4*)&As[kk][ty * 8];
            float4 a1 = *(const float4*)&As[kk][ty * 8 + 4];
            unsigned long long ap[8];
            ap[0] = pack2(a0.x); ap[1] = pack2(a0.y);
            ap[2] = pack2(a0.z); ap[3] = pack2(a0.w);
            ap[4] = pack2(a1.x); ap[5] = pack2(a1.y);
            ap[6] = pack2(a1.z); ap[7] = pack2(a1.w);
            const unsigned long long* bp =
                (const unsigned long long*)&Bs[kk][tx * 8];
            unsigned long long b0 = bp[0], b1 = bp[1], b2 = bp[2], b3 = bp[3];
#pragma unroll
            for (int i = 0; i < 8; i++) {
                acc[i][0] = fma2(ap[i], b0, acc[i][0]);
                acc[i][1] = fma2(ap[i], b1, acc[i][1]);
                acc[i][2] = fma2(ap[i], b2, acc[i][2]);
                acc[i][3] = fma2(ap[i], b3, acc[i][3]);
            }
        }
        __syncthreads();
    }

    // epilogue
    float bb[8];
#pragma unroll
    for (int j = 0; j < 8; j++) bb[j] = 0.f;
    if (isS) {
        float4 t0 = *(const float4*)(bias + bn + tx * 8);
        float4 t1 = *(const float4*)(bias + bn + tx * 8 + 4);
        bb[0] = t0.x; bb[1] = t0.y; bb[2] = t0.z; bb[3] = t0.w;
        bb[4] = t1.x; bb[5] = t1.y; bb[6] = t1.z; bb[7] = t1.w;
    }
#pragma unroll
    for (int i = 0; i < 8; i++) {
        int gm = bm + ty * 8 + i;
        if (gm >= M) continue;
        float* yrow = Y + (size_t)gm * HID + bn + tx * 8;
        float o[8];
#pragma unroll
        for (int j = 0; j < 4; j++) {
            float2 v = unpack2(acc[i][j]);
            o[2 * j]     = v.x + bb[2 * j];
            o[2 * j + 1] = v.y + bb[2 * j + 1];
        }
        *(float4*)(yrow)     = make_float4(o[0], o[1], o[2], o[3]);
        *(float4*)(yrow + 4) = make_float4(o[4], o[5], o[6], o[7]);
    }
}

// ---- aggregation: g_bufC[i] = relu( mean_{s in N(i)} g_bufA[s] + g_bufB[i] )
__global__ void sage_aggregate() {
    int i = blockIdx.x;
    int c = threadIdx.x;  // 256
    int s0 = g_rowstart[i];
    int s1 = g_rowstart[i + 1];
    float acc = 0.f;
    for (int j = s0; j < s1; j++) {
        int s = g_csr[j];
        acc += g_bufA[(size_t)s * HID + c];
    }
    int d = s1 - s0;
    float inv = 1.0f / (float)(d > 0 ? d : 1);
    float v = acc * inv + g_bufB[(size_t)i * HID + c];
    g_bufC[(size_t)i * HID + c] = fmaxf(v, 0.f);
}

// ---------------- pooling ----------------
__device__ __forceinline__ int lower_bound_idx(const void* a, int n,
                                               int v, int is64) {
    int lo = 0, hi = n;
    while (lo < hi) {
        int mid = (lo + hi) >> 1;
        if (getIdx(a, mid, is64) < v) lo = mid + 1; else hi = mid;
    }
    return lo;
}

__global__ void pool_kernel(const void* __restrict__ batch, int n) {
    int g = blockIdx.x;
    int s = blockIdx.y;
    int S = gridDim.y;
    int is64 = g_is64;
    int lo = lower_bound_idx(batch, n, g, is64);
    int hi = lower_bound_idx(batch, n, g + 1, is64);
    int cnt = hi - lo;
    int chunk = (cnt + S - 1) / S;
    int a = lo + s * chunk;
    int b = a + chunk;
    if (b > hi) b = hi;
    int c = threadIdx.x;
    float acc = 0.f;
    for (int i = a; i < b; i++) acc += g_bufC[(size_t)i * HID + c];
    if (a < b) atomicAdd(&g_pool[g * HID + c], acc);
}

// ---------------- head MLP ----------------
__global__ void head_kernel(const void* __restrict__ batch, int n,
                            const float* __restrict__ fc1w,
                            const float* __restrict__ fc1b,
                            const float* __restrict__ fc2w,
                            const float* __restrict__ fc2b,
                            float* __restrict__ out) {
    __shared__ float pooled[HID];
    __shared__ float t1[HID / 2];
    int t = threadIdx.x;  // 256
    int is64 = g_is64;
    for (int g = 0; g < NUM_GRAPHS; g++) {
        int lo = lower_bound_idx(batch, n, g, is64);
        int hi = lower_bound_idx(batch, n, g + 1, is64);
        float cnt = fmaxf((float)(hi - lo), 1.0f);
        pooled[t] = g_pool[g * HID + t] / cnt;
        __syncthreads();
        if (t < HID / 2) {
            float s = fc1b[t];
            for (int c = 0; c < HID; c++) s += pooled[c] * fc1w[c * (HID / 2) + t];
            t1[t] = fmaxf(s, 0.f);
        }
        __syncthreads();
        if (t < 2) {
            float s = fc2b[t];
            for (int j = 0; j < HID / 2; j++) s += t1[j] * fc2w[j * 2 + t];
            out[g * 2 + t] = s;
        }
        __syncthreads();
    }
}

// ---------------- launch ----------------
extern "C" void kernel_launch(void* const* d_in, const int* in_sizes, int n_in,
                              void* d_out, int out_size) {
    const float* x = (const float*)d_in[0];
    const void* ei = d_in[1];
    const void* batch = d_in[2];
    const float* W1n = (const float*)d_in[3];
    const float* W1s = (const float*)d_in[4];
    const float* b1 = (const float*)d_in[5];
    const float* W2n = (const float*)d_in[6];
    const float* W2s = (const float*)d_in[7];
    const float* b2 = (const float*)d_in[8];
    const float* fc1w = (const float*)d_in[9];
    const float* fc1b = (const float*)d_in[10];
    const float* fc2w = (const float*)d_in[11];
    const float* fc2b = (const float*)d_in[12];
    float* out = (float*)d_out;

    const int n = in_sizes[2];            // 20000 nodes
    const int in_dim = in_sizes[0] / n;   // 512
    const int ne = in_sizes[1] / 2;       // 160000 edges

    // dtype probe + CSR build + zero scratch
    probe_dtype<<<1, 1024>>>(ei, ne, n);
    zero_kernel<<<(n + 255) / 256, 256>>>(n);
    edge_hist<<<(ne + 255) / 256, 256>>>(ei, ne);
    scan_deg<<<1, 1024>>>(n);
    csr_fill<<<(ne + 255) / 256, 256>>>(ei, ne);

    dim3 g1((n + BM - 1) / BM, 4);

    // Layer 1: project first (linearity of segment-sum), then aggregate
    gemm_dual<<<g1, 256>>>(x, 0, n, in_dim, W1n, W1s, b1);
    sage_aggregate<<<n, HID>>>();                  // h1 -> g_bufC

    // Layer 2
    gemm_dual<<<g1, 256>>>(x, 1, n, HID, W2n, W2s, b2);
    sage_aggregate<<<n, HID>>>();                  // h2 -> g_bufC

    // Pool + head
    dim3 gp(NUM_GRAPHS, 32);
    pool_kernel<<<gp, HID>>>(batch, n);
    head_kernel<<<1, HID>>>(batch, n, fc1w, fc1b, fc2w, fc2b, out);
}

// round 7
// speedup vs baseline: 1.4434x; 1.3008x over previous
#include <cuda_runtime.h>
#include <cuda_bf16.h>
#include <cstdint>

#define MAX_NODES 20000
#define MAX_EDGES 160000
#define HID 256
#define NUM_GRAPHS 16

// ---------------- device scratch (static, no runtime alloc) ----------------
__device__ float g_bufA[MAX_NODES * HID];   // y_nbr projections
__device__ float g_bufB[MAX_NODES * HID];   // y_self projections (+bias)
__device__ float g_bufC[MAX_NODES * HID];   // h1 / h2
__device__ int   g_deg[MAX_NODES];
__device__ int   g_rowstart[MAX_NODES + 1];
__device__ int   g_cursor[MAX_NODES];
__device__ int   g_csr[MAX_EDGES];
__device__ float g_pool[NUM_GRAPHS * HID];
__device__ int   g_is64;                    // 1 if index inputs are int64

// transposed + hi/lo-split weights: WT[n][k] (n in [0,512): 0-255 = Wn cols,
// 256-511 = Ws cols), K-major bf16
__device__ __nv_bfloat16 g_WT1h[512 * 512];
__device__ __nv_bfloat16 g_WT1l[512 * 512];
__device__ __nv_bfloat16 g_WT2h[512 * 256];
__device__ __nv_bfloat16 g_WT2l[512 * 256];

// ---------------- dtype-agnostic index accessors ----------------
__device__ __forceinline__ int getIdx(const void* p, int i, int is64) {
    if (is64) return (int)((const long long*)p)[i];
    return ((const int*)p)[i];
}

__global__ void probe_dtype(const void* ei, int ne, int n) {
    __shared__ int bad;
    if (threadIdx.x == 0) bad = 0;
    __syncthreads();
    int local = 0;
    for (int e = threadIdx.x; e < ne; e += blockDim.x) {
        long long v = ((const long long*)ei)[e];
        if (v < 0 || v >= (long long)n) local = 1;
    }
    if (local) bad = 1;
    __syncthreads();
    if (threadIdx.x == 0) g_is64 = bad ? 0 : 1;
}

// ---------------- CSR build ----------------
__global__ void zero_kernel(int n_nodes) {
    int i = blockIdx.x * blockDim.x + threadIdx.x;
    if (i < n_nodes) g_deg[i] = 0;
    if (i < NUM_GRAPHS * HID) g_pool[i] = 0.0f;
}

__global__ void edge_hist(const void* __restrict__ ei, int ne) {
    int e = blockIdx.x * blockDim.x + threadIdx.x;
    int is64 = g_is64;
    if (e < ne) {
        int d = getIdx(ei, ne + e, is64);
        atomicAdd(&g_deg[d], 1);
    }
}

__global__ void scan_deg(int n) {
    __shared__ int partial[1024];
    int t = threadIdx.x;
    const int per = (n + 1023) / 1024;
    int base = t * per;
    int sum = 0;
    for (int k = 0; k < per; k++) {
        int idx = base + k;
        if (idx < n) sum += g_deg[idx];
    }
    partial[t] = sum;
    __syncthreads();
    for (int off = 1; off < 1024; off <<= 1) {
        int v = (t >= off) ? partial[t - off] : 0;
        __syncthreads();
        partial[t] += v;
        __syncthreads();
    }
    int run = (t == 0) ? 0 : partial[t - 1];
    for (int k = 0; k < per; k++) {
        int idx = base + k;
        if (idx < n) {
            int d = g_deg[idx];
            g_rowstart[idx] = run;
            g_cursor[idx] = run;
            run += d;
        }
    }
    if (t == 1023) g_rowstart[n] = run;
}

__global__ void csr_fill(const void* __restrict__ ei, int ne) {
    int e = blockIdx.x * blockDim.x + threadIdx.x;
    int is64 = g_is64;
    if (e < ne) {
        int s = getIdx(ei, e, is64);
        int d = getIdx(ei, ne + e, is64);
        int p = atomicAdd(&g_cursor[d], 1);
        g_csr[p] = s;
    }
}

// ---------------- weight prep: transpose + hi/lo bf16 split ----------------
__global__ void prep_w(const float* __restrict__ Wn,
                       const float* __restrict__ Ws, int K, int layer) {
    __nv_bfloat16* WTh = layer ? g_WT2h : g_WT1h;
    __nv_bfloat16* WTl = layer ? g_WT2l : g_WT1l;
    int idx = blockIdx.x * blockDim.x + threadIdx.x;
    int total = 512 * K;
    if (idx >= total) return;
    int nrow = idx / K;
    int k = idx % K;
    float v = (nrow < 256) ? Wn[(size_t)k * 256 + nrow]
                           : Ws[(size_t)k * 256 + (nrow - 256)];
    __nv_bfloat16 h = __float2bfloat16(v);
    WTh[idx] = h;
    WTl[idx] = __float2bfloat16(v - __bfloat162float(h));
}

// ---------------- HMMA (mma.sync) dual GEMM, bf16 hi/lo 3-pass -------------
// Block tile 128x128, 8 warps (2 m x 4 n), warp tile 64x32, K chunk 32.
// Output cols [0,256) -> g_bufA ; [256,512) -> g_bufB (+bias).

__device__ __forceinline__ void mma16816(float* c, const uint32_t* a,
                                         const uint32_t* b) {
    asm volatile(
        "mma.sync.aligned.m16n8k16.row.col.f32.bf16.bf16.f32 "
        "{%0,%1,%2,%3}, {%4,%5,%6,%7}, {%8,%9}, {%0,%1,%2,%3};"
        : "+f"(c[0]), "+f"(c[1]), "+f"(c[2]), "+f"(c[3])
        : "r"(a[0]), "r"(a[1]), "r"(a[2]), "r"(a[3]), "r"(b[0]), "r"(b[1]));
}

#define SROW 20  // u32 stride per row (40 bf16) -> conflict-free LDS

__global__ __launch_bounds__(256, 1) void gemm_mma(
    const float* __restrict__ Xext, int src_sel, int M, int K, int layer,
    const float* __restrict__ bias) {
    __shared__ uint32_t sAh[128 * SROW];
    __shared__ uint32_t sAl[128 * SROW];
    __shared__ uint32_t sBh[128 * SROW];
    __shared__ uint32_t sBl[128 * SROW];

    const float* A = src_sel ? (const float*)g_bufC : Xext;
    const __nv_bfloat16* WTh = layer ? g_WT2h : g_WT1h;
    const __nv_bfloat16* WTl = layer ? g_WT2l : g_WT1l;

    const int tid = threadIdx.x;
    const int wid = tid >> 5;
    const int lane = tid & 31;
    const int g = lane >> 2;       // group id 0..7
    const int tg = lane & 3;       // thread-in-group
    const int wm = wid >> 2;       // 0..1  (m)
    const int wn = wid & 3;        // 0..3  (n)
    const int bm = blockIdx.x * 128;
    const int bn = blockIdx.y * 128;

    float acc[4][4][4];            // [mt][nt][4]
#pragma unroll
    for (int i = 0; i < 4; i++)
#pragma unroll
        for (int j = 0; j < 4; j++)
#pragma unroll
            for (int q = 0; q < 4; q++) acc[i][j][q] = 0.f;

    const int nch = K >> 5;        // K/32
    for (int ch = 0; ch < nch; ch++) {
        const int k0 = ch << 5;
        // ---- A tile: 128 rows x 32 floats -> bf16 hi/lo ----
#pragma unroll
        for (int r = 0; r < 4; r++) {
            int lin = tid + r * 256;          // 1024 float4 slots
            int row = lin >> 3;
            int q = lin & 7;
            int gr = bm + row;
            float4 v = make_float4(0.f, 0.f, 0.f, 0.f);
            if (gr < M) v = *(const float4*)(A + (size_t)gr * K + k0 + q * 4);
            __nv_bfloat16 h0 = __float2bfloat16(v.x);
            __nv_bfloat16 h1 = __float2bfloat16(v.y);
            __nv_bfloat16 h2 = __float2bfloat16(v.z);
            __nv_bfloat16 h3 = __float2bfloat16(v.w);
            __nv_bfloat16 l0 = __float2bfloat16(v.x - __bfloat162float(h0));
            __nv_bfloat16 l1 = __float2bfloat16(v.y - __bfloat162float(h1));
            __nv_bfloat16 l2 = __float2bfloat16(v.z - __bfloat162float(h2));
            __nv_bfloat16 l3 = __float2bfloat16(v.w - __bfloat162float(h3));
            int o = row * SROW + q * 2;
            sAh[o]     = (uint32_t)__bfloat16_as_ushort(h0) |
                         ((uint32_t)__bfloat16_as_ushort(h1) << 16);
            sAh[o + 1] = (uint32_t)__bfloat16_as_ushort(h2) |
                         ((uint32_t)__bfloat16_as_ushort(h3) << 16);
            sAl[o]     = (uint32_t)__bfloat16_as_ushort(l0) |
                         ((uint32_t)__bfloat16_as_ushort(l1) << 16);
            sAl[o + 1] = (uint32_t)__bfloat16_as_ushort(l2) |
                         ((uint32_t)__bfloat16_as_ushort(l3) << 16);
        }
        // ---- B tile: 128 n-rows x 32 k (bf16 u32 pairs) ----
#pragma unroll
        for (int r = 0; r < 8; r++) {
            int lin = tid + r * 256;          // 2048 u32 slots
            int row = lin >> 4;
            int p = lin & 15;
            size_t gofs = (size_t)(bn + row) * K + k0 + p * 2;
            sBh[row * SROW + p] = *(const uint32_t*)(WTh + gofs);
            sBl[row * SROW + p] = *(const uint32_t*)(WTl + gofs);
        }
        __syncthreads();

#pragma unroll
        for (int ks = 0; ks < 2; ks++) {
            const int kb = ks * 8;
            uint32_t ah[4][4], al[4][4], bh[4][2], bl[4][2];
#pragma unroll
            for (int mt = 0; mt < 4; mt++) {
                int r0 = (wm * 64 + mt * 16 + g) * SROW;
                int r8 = r0 + 8 * SROW;
                ah[mt][0] = sAh[r0 + kb + tg];
                ah[mt][1] = sAh[r8 + kb + tg];
                ah[mt][2] = sAh[r0 + kb + tg + 4];
                ah[mt][3] = sAh[r8 + kb + tg + 4];
                al[mt][0] = sAl[r0 + kb + tg];
                al[mt][1] = sAl[r8 + kb + tg];
                al[mt][2] = sAl[r0 + kb + tg + 4];
                al[mt][3] = sAl[r8 + kb + tg + 4];
            }
#pragma unroll
            for (int nt = 0; nt < 4; nt++) {
                int rb = (wn * 32 + nt * 8 + g) * SROW;
                bh[nt][0] = sBh[rb + kb + tg];
                bh[nt][1] = sBh[rb + kb + tg + 4];
                bl[nt][0] = sBl[rb + kb + tg];
                bl[nt][1] = sBl[rb + kb + tg + 4];
            }
#pragma unroll
            for (int mt = 0; mt < 4; mt++)
#pragma unroll
                for (int nt = 0; nt < 4; nt++) {
                    mma16816(acc[mt][nt], ah[mt], bh[nt]);
                    mma16816(acc[mt][nt], ah[mt], bl[nt]);
                    mma16816(acc[mt][nt], al[mt], bh[nt]);
                }
        }
        __syncthreads();
    }

    // ---- epilogue ----
#pragma unroll
    for (int mt = 0; mt < 4; mt++) {
        int r0 = bm + wm * 64 + mt * 16 + g;
#pragma unroll
        for (int nt = 0; nt < 4; nt++) {
            int c = bn + wn * 32 + nt * 8 + tg * 2;
            float b0 = 0.f, b1 = 0.f;
            float* dst;
            int cc = c;
            if (c >= 256) {
                cc = c - 256;
                b0 = bias[cc];
                b1 = bias[cc + 1];
                dst = g_bufB;
            } else {
                dst = g_bufA;
            }
            if (r0 < M) {
                float2 v = make_float2(acc[mt][nt][0] + b0, acc[mt][nt][1] + b1);
                *(float2*)(dst + (size_t)r0 * HID + cc) = v;
            }
            if (r0 + 8 < M) {
                float2 v = make_float2(acc[mt][nt][2] + b0, acc[mt][nt][3] + b1);
                *(float2*)(dst + (size_t)(r0 + 8) * HID + cc) = v;
            }
        }
    }
}

// ---- aggregation: g_bufC[i] = relu( mean_{s in N(i)} g_bufA[s] + g_bufB[i] )
__global__ void sage_aggregate() {
    int i = blockIdx.x;
    int c = threadIdx.x;  // 256
    int s0 = g_rowstart[i];
    int s1 = g_rowstart[i + 1];
    float acc = 0.f;
    for (int j = s0; j < s1; j++) {
        int s = g_csr[j];
        acc += g_bufA[(size_t)s * HID + c];
    }
    int d = s1 - s0;
    float inv = 1.0f / (float)(d > 0 ? d : 1);
    float v = acc * inv + g_bufB[(size_t)i * HID + c];
    g_bufC[(size_t)i * HID + c] = fmaxf(v, 0.f);
}

// ---------------- pooling ----------------
__device__ __forceinline__ int lower_bound_idx(const void* a, int n,
                                               int v, int is64) {
    int lo = 0, hi = n;
    while (lo < hi) {
        int mid = (lo + hi) >> 1;
        if (getIdx(a, mid, is64) < v) lo = mid + 1; else hi = mid;
    }
    return lo;
}

__global__ void pool_kernel(const void* __restrict__ batch, int n) {
    int g = blockIdx.x;
    int s = blockIdx.y;
    int S = gridDim.y;
    int is64 = g_is64;
    int lo = lower_bound_idx(batch, n, g, is64);
    int hi = lower_bound_idx(batch, n, g + 1, is64);
    int cnt = hi - lo;
    int chunk = (cnt + S - 1) / S;
    int a = lo + s * chunk;
    int b = a + chunk;
    if (b > hi) b = hi;
    int c = threadIdx.x;
    float acc = 0.f;
    for (int i = a; i < b; i++) acc += g_bufC[(size_t)i * HID + c];
    if (a < b) atomicAdd(&g_pool[g * HID + c], acc);
}

// ---------------- head MLP ----------------
__global__ void head_kernel(const void* __restrict__ batch, int n,
                            const float* __restrict__ fc1w,
                            const float* __restrict__ fc1b,
                            const float* __restrict__ fc2w,
                            const float* __restrict__ fc2b,
                            float* __restrict__ out) {
    __shared__ float pooled[HID];
    __shared__ float t1[HID / 2];
    int t = threadIdx.x;  // 256
    int is64 = g_is64;
    for (int g = 0; g < NUM_GRAPHS; g++) {
        int lo = lower_bound_idx(batch, n, g, is64);
        int hi = lower_bound_idx(batch, n, g + 1, is64);
        float cnt = fmaxf((float)(hi - lo), 1.0f);
        pooled[t] = g_pool[g * HID + t] / cnt;
        __syncthreads();
        if (t < HID / 2) {
            float s = fc1b[t];
            for (int c = 0; c < HID; c++) s += pooled[c] * fc1w[c * (HID / 2) + t];
            t1[t] = fmaxf(s, 0.f);
        }
        __syncthreads();
        if (t < 2) {
            float s = fc2b[t];
            for (int j = 0; j < HID / 2; j++) s += t1[j] * fc2w[j * 2 + t];
            out[g * 2 + t] = s;
        }
        __syncthreads();
    }
}

// ---------------- launch ----------------
extern "C" void kernel_launch(void* const* d_in, const int* in_sizes, int n_in,
                              void* d_out, int out_size) {
    const float* x = (const float*)d_in[0];
    const void* ei = d_in[1];
    const void* batch = d_in[2];
    const float* W1n = (const float*)d_in[3];
    const float* W1s = (const float*)d_in[4];
    const float* b1 = (const float*)d_in[5];
    const float* W2n = (const float*)d_in[6];
    const float* W2s = (const float*)d_in[7];
    const float* b2 = (const float*)d_in[8];
    const float* fc1w = (const float*)d_in[9];
    const float* fc1b = (const float*)d_in[10];
    const float* fc2w = (const float*)d_in[11];
    const float* fc2b = (const float*)d_in[12];
    float* out = (float*)d_out;

    const int n = in_sizes[2];            // 20000 nodes
    const int in_dim = in_sizes[0] / n;   // 512
    const int ne = in_sizes[1] / 2;       // 160000 edges

    // dtype probe + CSR build + zero scratch + weight prep
    probe_dtype<<<1, 1024>>>(ei, ne, n);
    zero_kernel<<<(n + 255) / 256, 256>>>(n);
    edge_hist<<<(ne + 255) / 256, 256>>>(ei, ne);
    scan_deg<<<1, 1024>>>(n);
    csr_fill<<<(ne + 255) / 256, 256>>>(ei, ne);
    prep_w<<<(512 * in_dim + 255) / 256, 256>>>(W1n, W1s, in_dim, 0);
    prep_w<<<(512 * HID + 255) / 256, 256>>>(W2n, W2s, HID, 1);

    dim3 g1((n + 127) / 128, 4);

    // Layer 1: project first (linearity of segment-sum), then aggregate
    gemm_mma<<<g1, 256>>>(x, 0, n, in_dim, 0, b1);
    sage_aggregate<<<n, HID>>>();                  // h1 -> g_bufC

    // Layer 2
    gemm_mma<<<g1, 256>>>(x, 1, n, HID, 1, b2);
    sage_aggregate<<<n, HID>>>();                  // h2 -> g_bufC

    // Pool + head
    dim3 gp(NUM_GRAPHS, 32);
    pool_kernel<<<gp, HID>>>(batch, n);
    head_kernel<<<1, HID>>>(batch, n, fc1w, fc1b, fc2w, fc2b, out);
}

// round 8
// speedup vs baseline: 1.5870x; 1.0995x over previous
#include <cuda_runtime.h>
#include <cuda_bf16.h>
#include <cstdint>

#define MAX_NODES 20000
#define MAX_EDGES 160000
#define HID 256
#define NUM_GRAPHS 16

// ---------------- device scratch (static, no runtime alloc) ----------------
__device__ float g_bufA[MAX_NODES * HID];   // y_nbr projections
__device__ float g_bufB[MAX_NODES * HID];   // y_self projections (+bias)
__device__ float g_bufC[MAX_NODES * HID];   // h (fp32, for pooling)
__device__ int   g_deg[MAX_NODES];
__device__ int   g_rowstart[MAX_NODES + 1];
__device__ int   g_cursor[MAX_NODES];
__device__ int   g_csr[MAX_EDGES];
__device__ float g_pool[NUM_GRAPHS * HID];
__device__ int   g_is64;
__device__ int   g_bsum[128];

// A operand, bf16 hi/lo split (layer1: 20000x512, layer2: 20000x256)
__device__ __nv_bfloat16 g_Ah[MAX_NODES * 512];
__device__ __nv_bfloat16 g_Al[MAX_NODES * 512];

// transposed + hi/lo-split weights: WT[n][k], n in [0,512)
__device__ __nv_bfloat16 g_WT1h[512 * 512];
__device__ __nv_bfloat16 g_WT1l[512 * 512];
__device__ __nv_bfloat16 g_WT2h[512 * 256];
__device__ __nv_bfloat16 g_WT2l[512 * 256];

// ---------------- helpers ----------------
__device__ __forceinline__ uint32_t smem_u32(const void* p) {
    uint32_t a;
    asm("{ .reg .u64 t; cvta.to.shared.u64 t, %1; cvt.u32.u64 %0, t; }"
        : "=r"(a) : "l"(p));
    return a;
}
#define CP_ASYNC16(dst_u32, src_ptr) \
    asm volatile("cp.async.cg.shared.global [%0], [%1], 16;" \
                 :: "r"(dst_u32), "l"(src_ptr))
#define CP_COMMIT() asm volatile("cp.async.commit_group;" ::: "memory")
#define CP_WAIT(N) asm volatile("cp.async.wait_group %0;" :: "n"(N) : "memory")

__device__ __forceinline__ int getIdx(const void* p, int i, int is64) {
    if (is64) return (int)((const long long*)p)[i];
    return ((const int*)p)[i];
}

__global__ void probe_dtype(const void* ei, int ne, int n) {
    __shared__ int bad;
    if (threadIdx.x == 0) bad = 0;
    __syncthreads();
    int local = 0;
    for (int e = threadIdx.x; e < ne; e += blockDim.x) {
        long long v = ((const long long*)ei)[e];
        if (v < 0 || v >= (long long)n) local = 1;
    }
    if (local) bad = 1;
    __syncthreads();
    if (threadIdx.x == 0) g_is64 = bad ? 0 : 1;
}

// ---------------- CSR build ----------------
__global__ void zero_kernel(int n_nodes) {
    int i = blockIdx.x * blockDim.x + threadIdx.x;
    if (i < n_nodes) g_deg[i] = 0;
    if (i < NUM_GRAPHS * HID) g_pool[i] = 0.0f;
}

__global__ void edge_hist(const void* __restrict__ ei, int ne) {
    int e = blockIdx.x * blockDim.x + threadIdx.x;
    int is64 = g_is64;
    if (e < ne) {
        int d = getIdx(ei, ne + e, is64);
        atomicAdd(&g_deg[d], 1);
    }
}

// parallel scan: per-block sums -> scan sums -> fill
#define SCB 256
__global__ void block_sums(int n) {
    __shared__ int sh[SCB];
    int i = blockIdx.x * SCB + threadIdx.x;
    sh[threadIdx.x] = (i < n) ? g_deg[i] : 0;
    __syncthreads();
    for (int off = SCB / 2; off > 0; off >>= 1) {
        if (threadIdx.x < off) sh[threadIdx.x] += sh[threadIdx.x + off];
        __syncthreads();
    }
    if (threadIdx.x == 0) g_bsum[blockIdx.x] = sh[0];
}

__global__ void scan_bsums(int nb) {   // 1 block of 128
    __shared__ int sh[128];
    int t = threadIdx.x;
    sh[t] = (t < nb) ? g_bsum[t] : 0;
    __syncthreads();
    for (int off = 1; off < 128; off <<= 1) {
        int v = (t >= off) ? sh[t - off] : 0;
        __syncthreads();
        sh[t] += v;
        __syncthreads();
    }
    if (t < nb) g_bsum[t] = (t == 0) ? 0 : sh[t - 1];  // exclusive
}

__global__ void fill_rows(int n) {
    __shared__ int sh[SCB];
    int i = blockIdx.x * SCB + threadIdx.x;
    int d = (i < n) ? g_deg[i] : 0;
    sh[threadIdx.x] = d;
    __syncthreads();
    for (int off = 1; off < SCB; off <<= 1) {
        int v = (threadIdx.x >= off) ? sh[threadIdx.x - off] : 0;
        __syncthreads();
        sh[threadIdx.x] += v;
        __syncthreads();
    }
    int excl = sh[threadIdx.x] - d;       // exclusive within block
    int base = g_bsum[blockIdx.x];
    if (i < n) {
        g_rowstart[i] = base + excl;
        g_cursor[i] = base + excl;
        if (i == n - 1) g_rowstart[n] = base + excl + d;
    }
}

__global__ void csr_fill(const void* __restrict__ ei, int ne) {
    int e = blockIdx.x * blockDim.x + threadIdx.x;
    int is64 = g_is64;
    if (e < ne) {
        int s = getIdx(ei, e, is64);
        int d = getIdx(ei, ne + e, is64);
        int p = atomicAdd(&g_cursor[d], 1);
        g_csr[p] = s;
    }
}

// ---------------- operand prep ----------------
__global__ void prep_w(const float* __restrict__ Wn,
                       const float* __restrict__ Ws, int K, int layer) {
    __nv_bfloat16* WTh = layer ? g_WT2h : g_WT1h;
    __nv_bfloat16* WTl = layer ? g_WT2l : g_WT1l;
    int idx = blockIdx.x * blockDim.x + threadIdx.x;
    int total = 512 * K;
    if (idx >= total) return;
    int nrow = idx / K;
    int k = idx % K;
    float v = (nrow < 256) ? Wn[(size_t)k * 256 + nrow]
                           : Ws[(size_t)k * 256 + (nrow - 256)];
    __nv_bfloat16 h = __float2bfloat16(v);
    WTh[idx] = h;
    WTl[idx] = __float2bfloat16(v - __bfloat162float(h));
}

// split fp32 x -> g_Ah/g_Al (element count = n*K)
__global__ void split_x(const float* __restrict__ src, int total) {
    int i = blockIdx.x * blockDim.x + threadIdx.x;
    if (i >= total) return;
    float v = src[i];
    __nv_bfloat16 h = __float2bfloat16(v);
    g_Ah[i] = h;
    g_Al[i] = __float2bfloat16(v - __bfloat162float(h));
}

// ---------------- HMMA dual GEMM, cp.async double-buffered ----------------
__device__ __forceinline__ void mma16816(float* c, const uint32_t* a,
                                         const uint32_t* b) {
    asm volatile(
        "mma.sync.aligned.m16n8k16.row.col.f32.bf16.bf16.f32 "
        "{%0,%1,%2,%3}, {%4,%5,%6,%7}, {%8,%9}, {%0,%1,%2,%3};"
        : "+f"(c[0]), "+f"(c[1]), "+f"(c[2]), "+f"(c[3])
        : "r"(a[0]), "r"(a[1]), "r"(a[2]), "r"(a[3]), "r"(b[0]), "r"(b[1]));
}

#define SROW 20                       // u32 per row (80 B, 16B-aligned)
#define TILE_U32 (128 * SROW)         // 2560 u32 = 10240 B
#define STAGE_U32 (4 * TILE_U32)      // 4 tiles
#define GEMM_SMEM (2 * STAGE_U32 * 4) // 81920 B

__global__ __launch_bounds__(256, 2) void gemm_mma(
    int M, int K, int layer, const float* __restrict__ bias) {
    extern __shared__ uint32_t smem[];
    const uint32_t sb = smem_u32(smem);

    const __nv_bfloat16* Ah = g_Ah;
    const __nv_bfloat16* Al = g_Al;
    const __nv_bfloat16* WTh = layer ? g_WT2h : g_WT1h;
    const __nv_bfloat16* WTl = layer ? g_WT2l : g_WT1l;

    const int tid = threadIdx.x;
    const int wid = tid >> 5;
    const int lane = tid & 31;
    const int g = lane >> 2;
    const int tg = lane & 3;
    const int wm = wid >> 2;
    const int wn = wid & 3;
    const int bm = blockIdx.x * 128;
    const int bn = blockIdx.y * 128;

    float acc[4][4][4];
#pragma unroll
    for (int i = 0; i < 4; i++)
#pragma unroll
        for (int j = 0; j < 4; j++)
#pragma unroll
            for (int q = 0; q < 4; q++) acc[i][j][q] = 0.f;

    const int nch = K >> 5;

    // issue async loads for chunk ch into stage stg
    auto load_chunk = [&](int ch, int stg) {
        const int k0 = ch << 5;
        const uint32_t sbase = sb + stg * (STAGE_U32 * 4);
#pragma unroll
        for (int r = 0; r < 2; r++) {
            int lin = tid + r * 256;     // 512 slots
            int row = lin >> 2;
            int q = lin & 3;
            uint32_t o = (row * SROW + q * 4) * 4;
            int gr = bm + row;
            uint32_t dAh = sbase + o;
            uint32_t dAl = dAh + TILE_U32 * 4;
            if (gr < M) {
                const __nv_bfloat16* pa = Ah + (size_t)gr * K + k0 + q * 8;
                const __nv_bfloat16* pl = Al + (size_t)gr * K + k0 + q * 8;
                CP_ASYNC16(dAh, pa);
                CP_ASYNC16(dAl, pl);
            } else {
                asm volatile("st.shared.v4.b32 [%0], {%1,%1,%1,%1};"
                             :: "r"(dAh), "r"(0u));
                asm volatile("st.shared.v4.b32 [%0], {%1,%1,%1,%1};"
                             :: "r"(dAl), "r"(0u));
            }
            size_t gofs = (size_t)(bn + row) * K + k0 + q * 8;
            uint32_t dBh = sbase + TILE_U32 * 8 + o;
            uint32_t dBl = sbase + TILE_U32 * 12 + o;
            CP_ASYNC16(dBh, WTh + gofs);
            CP_ASYNC16(dBl, WTl + gofs);
        }
    };

    load_chunk(0, 0);
    CP_COMMIT();

    for (int ch = 0; ch < nch; ch++) {
        if (ch + 1 < nch) {
            load_chunk(ch + 1, (ch + 1) & 1);
            CP_COMMIT();
            CP_WAIT(1);
        } else {
            CP_WAIT(0);
        }
        __syncthreads();

        const uint32_t* sAh = smem + (ch & 1) * STAGE_U32;
        const uint32_t* sAl = sAh + TILE_U32;
        const uint32_t* sBh = sAh + 2 * TILE_U32;
        const uint32_t* sBl = sAh + 3 * TILE_U32;

#pragma unroll
        for (int ks = 0; ks < 2; ks++) {
            const int kb = ks * 8;
            uint32_t ah[4][4], al[4][4], bh[4][2], bl[4][2];
#pragma unroll
            for (int mt = 0; mt < 4; mt++) {
                int r0 = (wm * 64 + mt * 16 + g) * SROW;
                int r8 = r0 + 8 * SROW;
                ah[mt][0] = sAh[r0 + kb + tg];
                ah[mt][1] = sAh[r8 + kb + tg];
                ah[mt][2] = sAh[r0 + kb + tg + 4];
                ah[mt][3] = sAh[r8 + kb + tg + 4];
                al[mt][0] = sAl[r0 + kb + tg];
                al[mt][1] = sAl[r8 + kb + tg];
                al[mt][2] = sAl[r0 + kb + tg + 4];
                al[mt][3] = sAl[r8 + kb + tg + 4];
            }
#pragma unroll
            for (int nt = 0; nt < 4; nt++) {
                int rb = (wn * 32 + nt * 8 + g) * SROW;
                bh[nt][0] = sBh[rb + kb + tg];
                bh[nt][1] = sBh[rb + kb + tg + 4];
                bl[nt][0] = sBl[rb + kb + tg];
                bl[nt][1] = sBl[rb + kb + tg + 4];
            }
#pragma unroll
            for (int mt = 0; mt < 4; mt++)
#pragma unroll
                for (int nt = 0; nt < 4; nt++) {
                    mma16816(acc[mt][nt], ah[mt], bh[nt]);
                    mma16816(acc[mt][nt], ah[mt], bl[nt]);
                    mma16816(acc[mt][nt], al[mt], bh[nt]);
                }
        }
        __syncthreads();
    }

    // ---- epilogue ----
#pragma unroll
    for (int mt = 0; mt < 4; mt++) {
        int r0 = bm + wm * 64 + mt * 16 + g;
#pragma unroll
        for (int nt = 0; nt < 4; nt++) {
            int c = bn + wn * 32 + nt * 8 + tg * 2;
            float b0 = 0.f, b1 = 0.f;
            float* dst;
            int cc = c;
            if (c >= 256) {
                cc = c - 256;
                b0 = bias[cc];
                b1 = bias[cc + 1];
                dst = g_bufB;
            } else {
                dst = g_bufA;
            }
            if (r0 < M) {
                float2 v = make_float2(acc[mt][nt][0] + b0, acc[mt][nt][1] + b1);
                *(float2*)(dst + (size_t)r0 * HID + cc) = v;
            }
            if (r0 + 8 < M) {
                float2 v = make_float2(acc[mt][nt][2] + b0, acc[mt][nt][3] + b1);
                *(float2*)(dst + (size_t)(r0 + 8) * HID + cc) = v;
            }
        }
    }
}

// ---- aggregation: h[i] = relu(mean nbr g_bufA + g_bufB[i]); writes fp32 h to
// g_bufC and bf16 hi/lo split to g_Ah/g_Al (row stride HID) for the next GEMM.
__global__ void sage_aggregate() {
    int i = blockIdx.x;
    int c = threadIdx.x;  // 256
    int s0 = g_rowstart[i];
    int s1 = g_rowstart[i + 1];
    float acc = 0.f;
    for (int j = s0; j < s1; j++) {
        int s = g_csr[j];
        acc += g_bufA[(size_t)s * HID + c];
    }
    int d = s1 - s0;
    float inv = 1.0f / (float)(d > 0 ? d : 1);
    float v = acc * inv + g_bufB[(size_t)i * HID + c];
    v = fmaxf(v, 0.f);
    size_t o = (size_t)i * HID + c;
    g_bufC[o] = v;
    __nv_bfloat16 h = __float2bfloat16(v);
    g_Ah[o] = h;
    g_Al[o] = __float2bfloat16(v - __bfloat162float(h));
}

// ---------------- pooling ----------------
__device__ __forceinline__ int lower_bound_idx(const void* a, int n,
                                               int v, int is64) {
    int lo = 0, hi = n;
    while (lo < hi) {
        int mid = (lo + hi) >> 1;
        if (getIdx(a, mid, is64) < v) lo = mid + 1; else hi = mid;
    }
    return lo;
}

__global__ void pool_kernel(const void* __restrict__ batch, int n) {
    int g = blockIdx.x;
    int s = blockIdx.y;
    int S = gridDim.y;
    int is64 = g_is64;
    int lo = lower_bound_idx(batch, n, g, is64);
    int hi = lower_bound_idx(batch, n, g + 1, is64);
    int cnt = hi - lo;
    int chunk = (cnt + S - 1) / S;
    int a = lo + s * chunk;
    int b = a + chunk;
    if (b > hi) b = hi;
    int c = threadIdx.x;
    float acc = 0.f;
    for (int i = a; i < b; i++) acc += g_bufC[(size_t)i * HID + c];
    if (a < b) atomicAdd(&g_pool[g * HID + c], acc);
}

// ---------------- head MLP ----------------
__global__ void head_kernel(const void* __restrict__ batch, int n,
                            const float* __restrict__ fc1w,
                            const float* __restrict__ fc1b,
                            const float* __restrict__ fc2w,
                            const float* __restrict__ fc2b,
                            float* __restrict__ out) {
    __shared__ float pooled[HID];
    __shared__ float t1[HID / 2];
    int t = threadIdx.x;  // 256
    int is64 = g_is64;
    for (int g = 0; g < NUM_GRAPHS; g++) {
        int lo = lower_bound_idx(batch, n, g, is64);
        int hi = lower_bound_idx(batch, n, g + 1, is64);
        float cnt = fmaxf((float)(hi - lo), 1.0f);
        pooled[t] = g_pool[g * HID + t] / cnt;
        __syncthreads();
        if (t < HID / 2) {
            float s = fc1b[t];
            for (int c = 0; c < HID; c++) s += pooled[c] * fc1w[c * (HID / 2) + t];
            t1[t] = fmaxf(s, 0.f);
        }
        __syncthreads();
        if (t < 2) {
            float s = fc2b[t];
            for (int j = 0; j < HID / 2; j++) s += t1[j] * fc2w[j * 2 + t];
            out[g * 2 + t] = s;
        }
        __syncthreads();
    }
}

// ---------------- launch ----------------
extern "C" void kernel_launch(void* const* d_in, const int* in_sizes, int n_in,
                              void* d_out, int out_size) {
    const float* x = (const float*)d_in[0];
    const void* ei = d_in[1];
    const void* batch = d_in[2];
    const float* W1n = (const float*)d_in[3];
    const float* W1s = (const float*)d_in[4];
    const float* b1 = (const float*)d_in[5];
    const float* W2n = (const float*)d_in[6];
    const float* W2s = (const float*)d_in[7];
    const float* b2 = (const float*)d_in[8];
    const float* fc1w = (const float*)d_in[9];
    const float* fc1b = (const float*)d_in[10];
    const float* fc2w = (const float*)d_in[11];
    const float* fc2b = (const float*)d_in[12];
    float* out = (float*)d_out;

    const int n = in_sizes[2];            // 20000 nodes
    const int in_dim = in_sizes[0] / n;   // 512
    const int ne = in_sizes[1] / 2;       // 160000 edges

    static int attr_set = 0;
    if (!attr_set) {
        cudaFuncSetAttribute(gemm_mma,
                             cudaFuncAttributeMaxDynamicSharedMemorySize,
                             GEMM_SMEM);
        attr_set = 1;
    }

    const int nb = (n + SCB - 1) / SCB;

    probe_dtype<<<1, 1024>>>(ei, ne, n);
    zero_kernel<<<(n + 255) / 256, 256>>>(n);
    edge_hist<<<(ne + 255) / 256, 256>>>(ei, ne);
    block_sums<<<nb, SCB>>>(n);
    scan_bsums<<<1, 128>>>(nb);
    fill_rows<<<nb, SCB>>>(n);
    csr_fill<<<(ne + 255) / 256, 256>>>(ei, ne);
    prep_w<<<(512 * in_dim + 255) / 256, 256>>>(W1n, W1s, in_dim, 0);
    prep_w<<<(512 * HID + 255) / 256, 256>>>(W2n, W2s, HID, 1);
    split_x<<<(n * in_dim + 255) / 256, 256>>>(x, n * in_dim);

    dim3 g1((n + 127) / 128, 4);

    gemm_mma<<<g1, 256, GEMM_SMEM>>>(n, in_dim, 0, b1);
    sage_aggregate<<<n, HID>>>();     // h1 -> g_bufC + bf16 splits

    gemm_mma<<<g1, 256, GEMM_SMEM>>>(n, HID, 1, b2);
    sage_aggregate<<<n, HID>>>();     // h2 -> g_bufC

    dim3 gp(NUM_GRAPHS, 32);
    pool_kernel<<<gp, HID>>>(batch, n);
    head_kernel<<<1, HID>>>(batch, n, fc1w, fc1b, fc2w, fc2b, out);
}

// round 9
// speedup vs baseline: 1.9835x; 1.2498x over previous
#include <cuda_runtime.h>
#include <cuda_bf16.h>
#include <cstdint>

#define MAX_NODES 20000
#define MAX_EDGES 160000
#define HID 256
#define NUM_GRAPHS 16

// ---------------- device scratch (static, no runtime alloc) ----------------
__device__ float g_bufA[MAX_NODES * HID];   // y_nbr projections
__device__ float g_bufB[MAX_NODES * HID];   // y_self projections (+bias)
__device__ float g_bufC[MAX_NODES * HID];   // h (fp32, for pooling)
__device__ int   g_deg[MAX_NODES];
__device__ int   g_rowstart[MAX_NODES + 1];
__device__ int   g_cursor[MAX_NODES];
__device__ int   g_csr[MAX_EDGES];
__device__ float g_pool[NUM_GRAPHS * HID];
__device__ int   g_bad;                     // !=0 -> index inputs are int32
__device__ int   g_bsum[128];

// A operand, bf16 hi/lo split
__device__ __nv_bfloat16 g_Ah[MAX_NODES * 512];
__device__ __nv_bfloat16 g_Al[MAX_NODES * 512];

// transposed + hi/lo-split weights
__device__ __nv_bfloat16 g_WT1h[512 * 512];
__device__ __nv_bfloat16 g_WT1l[512 * 512];
__device__ __nv_bfloat16 g_WT2h[512 * 256];
__device__ __nv_bfloat16 g_WT2l[512 * 256];

// ---------------- helpers ----------------
__device__ __forceinline__ uint32_t smem_u32(const void* p) {
    uint32_t a;
    asm("{ .reg .u64 t; cvta.to.shared.u64 t, %1; cvt.u32.u64 %0, t; }"
        : "=r"(a) : "l"(p));
    return a;
}
#define CP_ASYNC16(dst_u32, src_ptr) \
    asm volatile("cp.async.cg.shared.global [%0], [%1], 16;" \
                 :: "r"(dst_u32), "l"(src_ptr))
#define CP_COMMIT() asm volatile("cp.async.commit_group;" ::: "memory")
#define CP_WAIT(N) asm volatile("cp.async.wait_group %0;" :: "n"(N) : "memory")

__device__ __forceinline__ void ldsm_x4(uint32_t* r, uint32_t addr) {
    asm volatile(
        "ldmatrix.sync.aligned.m8n8.x4.shared.b16 {%0,%1,%2,%3}, [%4];"
        : "=r"(r[0]), "=r"(r[1]), "=r"(r[2]), "=r"(r[3]) : "r"(addr));
}

__device__ __forceinline__ int getIdx(const void* p, int i, int is64) {
    if (is64) return (int)((const long long*)p)[i];
    return ((const int*)p)[i];
}

// ---------------- probe + zero ----------------
__global__ void zero_kernel(int n_nodes) {
    int i = blockIdx.x * blockDim.x + threadIdx.x;
    if (i < n_nodes) g_deg[i] = 0;
    if (i < NUM_GRAPHS * HID) g_pool[i] = 0.0f;
    if (i == 0) g_bad = 0;
}

__global__ void probe_dtype(const void* ei, int ne, int n) {
    int i = blockIdx.x * blockDim.x + threadIdx.x;
    int stride = gridDim.x * blockDim.x;
    int local = 0;
    for (int e = i; e < ne; e += stride) {
        long long v = ((const long long*)ei)[e];
        if (v < 0 || v >= (long long)n) local = 1;
    }
    if (__syncthreads_or(local)) {
        if (threadIdx.x == 0) atomicOr(&g_bad, 1);
    }
}

// ---------------- CSR build ----------------
__global__ void edge_hist(const void* __restrict__ ei, int ne) {
    int e = blockIdx.x * blockDim.x + threadIdx.x;
    int is64 = (g_bad == 0);
    if (e < ne) {
        int d = getIdx(ei, ne + e, is64);
        atomicAdd(&g_deg[d], 1);
    }
}

#define SCB 256
__global__ void block_sums(int n) {
    __shared__ int sh[SCB];
    int i = blockIdx.x * SCB + threadIdx.x;
    sh[threadIdx.x] = (i < n) ? g_deg[i] : 0;
    __syncthreads();
    for (int off = SCB / 2; off > 0; off >>= 1) {
        if (threadIdx.x < off) sh[threadIdx.x] += sh[threadIdx.x + off];
        __syncthreads();
    }
    if (threadIdx.x == 0) g_bsum[blockIdx.x] = sh[0];
}

__global__ void scan_bsums(int nb) {   // 1 block of 128
    __shared__ int sh[128];
    int t = threadIdx.x;
    sh[t] = (t < nb) ? g_bsum[t] : 0;
    __syncthreads();
    for (int off = 1; off < 128; off <<= 1) {
        int v = (t >= off) ? sh[t - off] : 0;
        __syncthreads();
        sh[t] += v;
        __syncthreads();
    }
    if (t < nb) g_bsum[t] = (t == 0) ? 0 : sh[t - 1];  // exclusive
}

__global__ void fill_rows(int n) {
    __shared__ int sh[SCB];
    int i = blockIdx.x * SCB + threadIdx.x;
    int d = (i < n) ? g_deg[i] : 0;
    sh[threadIdx.x] = d;
    __syncthreads();
    for (int off = 1; off < SCB; off <<= 1) {
        int v = (threadIdx.x >= off) ? sh[threadIdx.x - off] : 0;
        __syncthreads();
        sh[threadIdx.x] += v;
        __syncthreads();
    }
    int excl = sh[threadIdx.x] - d;
    int base = g_bsum[blockIdx.x];
    if (i < n) {
        g_rowstart[i] = base + excl;
        g_cursor[i] = base + excl;
        if (i == n - 1) g_rowstart[n] = base + excl + d;
    }
}

__global__ void csr_fill(const void* __restrict__ ei, int ne) {
    int e = blockIdx.x * blockDim.x + threadIdx.x;
    int is64 = (g_bad == 0);
    if (e < ne) {
        int s = getIdx(ei, e, is64);
        int d = getIdx(ei, ne + e, is64);
        int p = atomicAdd(&g_cursor[d], 1);
        g_csr[p] = s;
    }
}

// ---------------- operand prep ----------------
// one launch covers both layers: idx < 512*K1 -> layer1, else layer2
__global__ void prep_w(const float* __restrict__ W1n,
                       const float* __restrict__ W1s,
                       const float* __restrict__ W2n,
                       const float* __restrict__ W2s, int K1) {
    int idx = blockIdx.x * blockDim.x + threadIdx.x;
    int t1 = 512 * K1;
    int total = t1 + 512 * HID;
    if (idx >= total) return;
    float v;
    __nv_bfloat16 *dh, *dl;
    int o;
    if (idx < t1) {
        int nrow = idx / K1, k = idx % K1;
        v = (nrow < 256) ? W1n[(size_t)k * 256 + nrow]
                         : W1s[(size_t)k * 256 + (nrow - 256)];
        dh = g_WT1h; dl = g_WT1l; o = idx;
    } else {
        int j = idx - t1;
        int nrow = j / HID, k = j % HID;
        v = (nrow < 256) ? W2n[(size_t)k * 256 + nrow]
                         : W2s[(size_t)k * 256 + (nrow - 256)];
        dh = g_WT2h; dl = g_WT2l; o = j;
    }
    __nv_bfloat16 h = __float2bfloat16(v);
    dh[o] = h;
    dl[o] = __float2bfloat16(v - __bfloat162float(h));
}

__global__ void split_x(const float* __restrict__ src, int total4) {
    int i = blockIdx.x * blockDim.x + threadIdx.x;
    if (i >= total4) return;
    float4 v = ((const float4*)src)[i];
    __nv_bfloat16 h0 = __float2bfloat16(v.x);
    __nv_bfloat16 h1 = __float2bfloat16(v.y);
    __nv_bfloat16 h2 = __float2bfloat16(v.z);
    __nv_bfloat16 h3 = __float2bfloat16(v.w);
    uint32_t uh0 = (uint32_t)__bfloat16_as_ushort(h0) |
                   ((uint32_t)__bfloat16_as_ushort(h1) << 16);
    uint32_t uh1 = (uint32_t)__bfloat16_as_ushort(h2) |
                   ((uint32_t)__bfloat16_as_ushort(h3) << 16);
    __nv_bfloat16 l0 = __float2bfloat16(v.x - __bfloat162float(h0));
    __nv_bfloat16 l1 = __float2bfloat16(v.y - __bfloat162float(h1));
    __nv_bfloat16 l2 = __float2bfloat16(v.z - __bfloat162float(h2));
    __nv_bfloat16 l3 = __float2bfloat16(v.w - __bfloat162float(h3));
    uint32_t ul0 = (uint32_t)__bfloat16_as_ushort(l0) |
                   ((uint32_t)__bfloat16_as_ushort(l1) << 16);
    uint32_t ul1 = (uint32_t)__bfloat16_as_ushort(l2) |
                   ((uint32_t)__bfloat16_as_ushort(l3) << 16);
    ((uint2*)g_Ah)[i] = make_uint2(uh0, uh1);
    ((uint2*)g_Al)[i] = make_uint2(ul0, ul1);
}

// ---------------- HMMA dual GEMM, cp.async + ldmatrix ----------------
__device__ __forceinline__ void mma16816(float* c, const uint32_t* a,
                                         const uint32_t* b) {
    asm volatile(
        "mma.sync.aligned.m16n8k16.row.col.f32.bf16.bf16.f32 "
        "{%0,%1,%2,%3}, {%4,%5,%6,%7}, {%8,%9}, {%0,%1,%2,%3};"
        : "+f"(c[0]), "+f"(c[1]), "+f"(c[2]), "+f"(c[3])
        : "r"(a[0]), "r"(a[1]), "r"(a[2]), "r"(a[3]), "r"(b[0]), "r"(b[1]));
}

#define SROW 20                       // u32 per row (80 B)
#define SROWB 80
#define TILE_U32 (128 * SROW)
#define STAGE_U32 (4 * TILE_U32)
#define GEMM_SMEM (2 * STAGE_U32 * 4) // 81920 B

__global__ __launch_bounds__(256, 2) void gemm_mma(
    int M, int K, int layer, const float* __restrict__ bias) {
    extern __shared__ uint32_t smem[];
    const uint32_t sb = smem_u32(smem);

    const __nv_bfloat16* Ah = g_Ah;
    const __nv_bfloat16* Al = g_Al;
    const __nv_bfloat16* WTh = layer ? g_WT2h : g_WT1h;
    const __nv_bfloat16* WTl = layer ? g_WT2l : g_WT1l;

    const int tid = threadIdx.x;
    const int wid = tid >> 5;
    const int lane = tid & 31;
    const int g = lane >> 2;
    const int tg = lane & 3;
    const int wm = wid >> 2;
    const int wn = wid & 3;
    const int bm = blockIdx.x * 128;
    const int bn = blockIdx.y * 128;

    // ldmatrix per-thread address components
    const int sub = lane >> 3;        // 0..3
    const int rin = lane & 7;
    // A x4: row = base + rin + (sub&1)*8 ; k-part = (sub>>1)*16B
    const uint32_t a_row_off = (uint32_t)(rin + (sub & 1) * 8) * SROWB +
                               (uint32_t)(sub >> 1) * 16;
    // B x4 (two n-blocks): row = base + rin + (sub>>1)*8 ; k-part = (sub&1)*16B
    const uint32_t b_row_off = (uint32_t)(rin + (sub >> 1) * 8) * SROWB +
                               (uint32_t)(sub & 1) * 16;

    float acc[4][4][4];
#pragma unroll
    for (int i = 0; i < 4; i++)
#pragma unroll
        for (int j = 0; j < 4; j++)
#pragma unroll
            for (int q = 0; q < 4; q++) acc[i][j][q] = 0.f;

    const int nch = K >> 5;

    auto load_chunk = [&](int ch, int stg) {
        const int k0 = ch << 5;
        const uint32_t sbase = sb + stg * (STAGE_U32 * 4);
#pragma unroll
        for (int r = 0; r < 2; r++) {
            int lin = tid + r * 256;
            int row = lin >> 2;
            int q = lin & 3;
            uint32_t o = (row * SROW + q * 4) * 4;
            int gr = bm + row;
            uint32_t dAh = sbase + o;
            uint32_t dAl = dAh + TILE_U32 * 4;
            if (gr < M) {
                const __nv_bfloat16* pa = Ah + (size_t)gr * K + k0 + q * 8;
                const __nv_bfloat16* pl = Al + (size_t)gr * K + k0 + q * 8;
                CP_ASYNC16(dAh, pa);
                CP_ASYNC16(dAl, pl);
            } else {
                asm volatile("st.shared.v4.b32 [%0], {%1,%1,%1,%1};"
                             :: "r"(dAh), "r"(0u));
                asm volatile("st.shared.v4.b32 [%0], {%1,%1,%1,%1};"
                             :: "r"(dAl), "r"(0u));
            }
            size_t gofs = (size_t)(bn + row) * K + k0 + q * 8;
            uint32_t dBh = sbase + TILE_U32 * 8 + o;
            uint32_t dBl = sbase + TILE_U32 * 12 + o;
            CP_ASYNC16(dBh, WTh + gofs);
            CP_ASYNC16(dBl, WTl + gofs);
        }
    };

    load_chunk(0, 0);
    CP_COMMIT();

    for (int ch = 0; ch < nch; ch++) {
        if (ch + 1 < nch) {
            load_chunk(ch + 1, (ch + 1) & 1);
            CP_COMMIT();
            CP_WAIT(1);
        } else {
            CP_WAIT(0);
        }
        __syncthreads();

        const uint32_t stg_b = sb + (ch & 1) * (STAGE_U32 * 4);
        const uint32_t aAh = stg_b;
        const uint32_t aAl = stg_b + TILE_U32 * 4;
        const uint32_t aBh = stg_b + TILE_U32 * 8;
        const uint32_t aBl = stg_b + TILE_U32 * 12;

#pragma unroll
        for (int ks = 0; ks < 2; ks++) {
            const uint32_t kofs = (uint32_t)ks * 32;
            uint32_t ah[4][4], al[4][4], bh[4][2], bl[4][2];
#pragma unroll
            for (int mt = 0; mt < 4; mt++) {
                uint32_t rb = (uint32_t)(wm * 64 + mt * 16) * SROWB +
                              a_row_off + kofs;
                ldsm_x4(ah[mt], aAh + rb);
                ldsm_x4(al[mt], aAl + rb);
            }
#pragma unroll
            for (int p = 0; p < 2; p++) {
                uint32_t rb = (uint32_t)(wn * 32 + p * 16) * SROWB +
                              b_row_off + kofs;
                uint32_t t[4];
                ldsm_x4(t, aBh + rb);
                bh[2 * p][0] = t[0]; bh[2 * p][1] = t[1];
                bh[2 * p + 1][0] = t[2]; bh[2 * p + 1][1] = t[3];
                ldsm_x4(t, aBl + rb);
                bl[2 * p][0] = t[0]; bl[2 * p][1] = t[1];
                bl[2 * p + 1][0] = t[2]; bl[2 * p + 1][1] = t[3];
            }
            // pass-major: maximize accumulator reuse distance
#pragma unroll
            for (int mt = 0; mt < 4; mt++)
#pragma unroll
                for (int nt = 0; nt < 4; nt++)
                    mma16816(acc[mt][nt], ah[mt], bh[nt]);
#pragma unroll
            for (int mt = 0; mt < 4; mt++)
#pragma unroll
                for (int nt = 0; nt < 4; nt++)
                    mma16816(acc[mt][nt], ah[mt], bl[nt]);
#pragma unroll
            for (int mt = 0; mt < 4; mt++)
#pragma unroll
                for (int nt = 0; nt < 4; nt++)
                    mma16816(acc[mt][nt], al[mt], bh[nt]);
        }
        __syncthreads();
    }

    // ---- epilogue ----
#pragma unroll
    for (int mt = 0; mt < 4; mt++) {
        int r0 = bm + wm * 64 + mt * 16 + g;
#pragma unroll
        for (int nt = 0; nt < 4; nt++) {
            int c = bn + wn * 32 + nt * 8 + tg * 2;
            float b0 = 0.f, b1 = 0.f;
            float* dst;
            int cc = c;
            if (c >= 256) {
                cc = c - 256;
                b0 = bias[cc];
                b1 = bias[cc + 1];
                dst = g_bufB;
            } else {
                dst = g_bufA;
            }
            if (r0 < M) {
                float2 v = make_float2(acc[mt][nt][0] + b0, acc[mt][nt][1] + b1);
                *(float2*)(dst + (size_t)r0 * HID + cc) = v;
            }
            if (r0 + 8 < M) {
                float2 v = make_float2(acc[mt][nt][2] + b0, acc[mt][nt][3] + b1);
                *(float2*)(dst + (size_t)(r0 + 8) * HID + cc) = v;
            }
        }
    }
}

// ---- aggregation ----
__global__ void sage_aggregate() {
    int i = blockIdx.x;
    int c = threadIdx.x;  // 256
    int s0 = g_rowstart[i];
    int s1 = g_rowstart[i + 1];
    float acc = 0.f;
    for (int j = s0; j < s1; j++) {
        int s = g_csr[j];
        acc += g_bufA[(size_t)s * HID + c];
    }
    int d = s1 - s0;
    float inv = 1.0f / (float)(d > 0 ? d : 1);
    float v = acc * inv + g_bufB[(size_t)i * HID + c];
    v = fmaxf(v, 0.f);
    size_t o = (size_t)i * HID + c;
    g_bufC[o] = v;
    __nv_bfloat16 h = __float2bfloat16(v);
    g_Ah[o] = h;
    g_Al[o] = __float2bfloat16(v - __bfloat162float(h));
}

// ---------------- pooling / head ----------------
__device__ __forceinline__ int lower_bound_idx(const void* a, int n,
                                               int v, int is64) {
    int lo = 0, hi = n;
    while (lo < hi) {
        int mid = (lo + hi) >> 1;
        if (getIdx(a, mid, is64) < v) lo = mid + 1; else hi = mid;
    }
    return lo;
}

__global__ void pool_kernel(const void* __restrict__ batch, int n) {
    int g = blockIdx.x;
    int s = blockIdx.y;
    int S = gridDim.y;
    int is64 = (g_bad == 0);
    int lo = lower_bound_idx(batch, n, g, is64);
    int hi = lower_bound_idx(batch, n, g + 1, is64);
    int cnt = hi - lo;
    int chunk = (cnt + S - 1) / S;
    int a = lo + s * chunk;
    int b = a + chunk;
    if (b > hi) b = hi;
    int c = threadIdx.x;
    float acc = 0.f;
    for (int i = a; i < b; i++) acc += g_bufC[(size_t)i * HID + c];
    if (a < b) atomicAdd(&g_pool[g * HID + c], acc);
}

__global__ void head_kernel(const void* __restrict__ batch, int n,
                            const float* __restrict__ fc1w,
                            const float* __restrict__ fc1b,
                            const float* __restrict__ fc2w,
                            const float* __restrict__ fc2b,
                            float* __restrict__ out) {
    __shared__ float pooled[HID];
    __shared__ float t1[HID / 2];
    int t = threadIdx.x;  // 256
    int is64 = (g_bad == 0);
    for (int g = 0; g < NUM_GRAPHS; g++) {
        int lo = lower_bound_idx(batch, n, g, is64);
        int hi = lower_bound_idx(batch, n, g + 1, is64);
        float cnt = fmaxf((float)(hi - lo), 1.0f);
        pooled[t] = g_pool[g * HID + t] / cnt;
        __syncthreads();
        if (t < HID / 2) {
            float s = fc1b[t];
            for (int c = 0; c < HID; c++) s += pooled[c] * fc1w[c * (HID / 2) + t];
            t1[t] = fmaxf(s, 0.f);
        }
        __syncthreads();
        if (t < 2) {
            float s = fc2b[t];
            for (int j = 0; j < HID / 2; j++) s += t1[j] * fc2w[j * 2 + t];
            out[g * 2 + t] = s;
        }
        __syncthreads();
    }
}

// ---------------- launch ----------------
extern "C" void kernel_launch(void* const* d_in, const int* in_sizes, int n_in,
                              void* d_out, int out_size) {
    const float* x = (const float*)d_in[0];
    const void* ei = d_in[1];
    const void* batch = d_in[2];
    const float* W1n = (const float*)d_in[3];
    const float* W1s = (const float*)d_in[4];
    const float* b1 = (const float*)d_in[5];
    const float* W2n = (const float*)d_in[6];
    const float* W2s = (const float*)d_in[7];
    const float* b2 = (const float*)d_in[8];
    const float* fc1w = (const float*)d_in[9];
    const float* fc1b = (const float*)d_in[10];
    const float* fc2w = (const float*)d_in[11];
    const float* fc2b = (const float*)d_in[12];
    float* out = (float*)d_out;

    const int n = in_sizes[2];            // 20000 nodes
    const int in_dim = in_sizes[0] / n;   // 512
    const int ne = in_sizes[1] / 2;       // 160000 edges

    static int attr_set = 0;
    if (!attr_set) {
        cudaFuncSetAttribute(gemm_mma,
                             cudaFuncAttributeMaxDynamicSharedMemorySize,
                             GEMM_SMEM);
        attr_set = 1;
    }

    const int nb = (n + SCB - 1) / SCB;

    zero_kernel<<<(n + 255) / 256, 256>>>(n);
    probe_dtype<<<160, 256>>>(ei, ne, n);
    edge_hist<<<(ne + 255) / 256, 256>>>(ei, ne);
    block_sums<<<nb, SCB>>>(n);
    scan_bsums<<<1, 128>>>(nb);
    fill_rows<<<nb, SCB>>>(n);
    csr_fill<<<(ne + 255) / 256, 256>>>(ei, ne);
    prep_w<<<(512 * (in_dim + HID) + 255) / 256, 256>>>(W1n, W1s, W2n, W2s,
                                                        in_dim);
    split_x<<<(n * in_dim / 4 + 255) / 256, 256>>>(x, n * in_dim / 4);

    dim3 g1((n + 127) / 128, 4);

    gemm_mma<<<g1, 256, GEMM_SMEM>>>(n, in_dim, 0, b1);
    sage_aggregate<<<n, HID>>>();

    gemm_mma<<<g1, 256, GEMM_SMEM>>>(n, HID, 1, b2);
    sage_aggregate<<<n, HID>>>();

    dim3 gp(NUM_GRAPHS, 32);
    pool_kernel<<<gp, HID>>>(batch, n);
    head_kernel<<<1, HID>>>(batch, n, fc1w, fc1b, fc2w, fc2b, out);
}

// round 10
// speedup vs baseline: 2.5653x; 1.2933x over previous
#include <cuda_runtime.h>
#include <cuda_bf16.h>
#include <cstdint>

#define MAX_NODES 20000
#define MAX_EDGES 160000
#define HID 256
#define NUM_GRAPHS 16

// ---------------- device scratch (static, no runtime alloc) ----------------
__device__ float g_bufA[MAX_NODES * HID];   // y_nbr projections
__device__ float g_bufB[MAX_NODES * HID];   // y_self projections (+bias)
__device__ float g_bufC[MAX_NODES * HID];   // h (fp32, for pooling)
__device__ int   g_deg[MAX_NODES];
__device__ int   g_rowstart[MAX_NODES + 1];
__device__ int   g_cursor[MAX_NODES];
__device__ int   g_csr[MAX_EDGES];
__device__ float g_pool[NUM_GRAPHS * HID];
__device__ int   g_bad;                     // !=0 -> index inputs are int32
__device__ int   g_bsum[128];

// A operand, bf16 hi/lo split (padded to full 128-row tiles: no edge branch)
#define PAD_ROWS (MAX_NODES + 128)
__device__ __nv_bfloat16 g_Ah[PAD_ROWS * 512];
__device__ __nv_bfloat16 g_Al[PAD_ROWS * 512];

// transposed + hi/lo-split weights
__device__ __nv_bfloat16 g_WT1h[512 * 512];
__device__ __nv_bfloat16 g_WT1l[512 * 512];
__device__ __nv_bfloat16 g_WT2h[512 * 256];
__device__ __nv_bfloat16 g_WT2l[512 * 256];

// ---------------- helpers ----------------
__device__ __forceinline__ uint32_t smem_u32(const void* p) {
    uint32_t a;
    asm("{ .reg .u64 t; cvta.to.shared.u64 t, %1; cvt.u32.u64 %0, t; }"
        : "=r"(a) : "l"(p));
    return a;
}
#define CP_ASYNC16(dst_u32, src_ptr) \
    asm volatile("cp.async.cg.shared.global [%0], [%1], 16;" \
                 :: "r"(dst_u32), "l"(src_ptr))
#define CP_COMMIT() asm volatile("cp.async.commit_group;" ::: "memory")
#define CP_WAIT(N) asm volatile("cp.async.wait_group %0;" :: "n"(N) : "memory")

__device__ __forceinline__ void ldsm_x4(uint32_t* r, uint32_t addr) {
    asm volatile(
        "ldmatrix.sync.aligned.m8n8.x4.shared.b16 {%0,%1,%2,%3}, [%4];"
        : "=r"(r[0]), "=r"(r[1]), "=r"(r[2]), "=r"(r[3]) : "r"(addr));
}

__device__ __forceinline__ int getIdx(const void* p, int i, int is64) {
    if (is64) return (int)((const long long*)p)[i];
    return ((const int*)p)[i];
}

// ---------------- probe + zero ----------------
__global__ void zero_kernel(int n_nodes) {
    int i = blockIdx.x * blockDim.x + threadIdx.x;
    if (i < n_nodes) g_deg[i] = 0;
    if (i < NUM_GRAPHS * HID) g_pool[i] = 0.0f;
    if (i == 0) g_bad = 0;
}

__global__ void probe_dtype(const void* ei, int ne, int n) {
    int i = blockIdx.x * blockDim.x + threadIdx.x;
    int stride = gridDim.x * blockDim.x;
    int local = 0;
    for (int e = i; e < ne; e += stride) {
        long long v = ((const long long*)ei)[e];
        if (v < 0 || v >= (long long)n) local = 1;
    }
    if (__syncthreads_or(local)) {
        if (threadIdx.x == 0) atomicOr(&g_bad, 1);
    }
}

// ---------------- CSR build ----------------
__global__ void edge_hist(const void* __restrict__ ei, int ne) {
    int e = blockIdx.x * blockDim.x + threadIdx.x;
    int is64 = (g_bad == 0);
    if (e < ne) {
        int d = getIdx(ei, ne + e, is64);
        atomicAdd(&g_deg[d], 1);
    }
}

#define SCB 256
__global__ void block_sums(int n) {
    __shared__ int sh[SCB];
    int i = blockIdx.x * SCB + threadIdx.x;
    sh[threadIdx.x] = (i < n) ? g_deg[i] : 0;
    __syncthreads();
    for (int off = SCB / 2; off > 0; off >>= 1) {
        if (threadIdx.x < off) sh[threadIdx.x] += sh[threadIdx.x + off];
        __syncthreads();
    }
    if (threadIdx.x == 0) g_bsum[blockIdx.x] = sh[0];
}

// fill rowstart/cursor; each block computes its own base from g_bsum
__global__ void fill_rows(int n, int nb) {
    __shared__ int sh[SCB];
    __shared__ int sbase;
    int t = threadIdx.x;
    // exclusive prefix of bsums up to blockIdx.x (nb <= 128, one warp enough)
    if (t == 0) {
        int b = 0;
        for (int j = 0; j < (int)blockIdx.x; j++) b += g_bsum[j];
        sbase = b;
    }
    int i = blockIdx.x * SCB + t;
    int d = (i < n) ? g_deg[i] : 0;
    sh[t] = d;
    __syncthreads();
    for (int off = 1; off < SCB; off <<= 1) {
        int v = (t >= off) ? sh[t - off] : 0;
        __syncthreads();
        sh[t] += v;
        __syncthreads();
    }
    int excl = sh[t] - d;
    int base = sbase;
    if (i < n) {
        g_rowstart[i] = base + excl;
        g_cursor[i] = base + excl;
        if (i == n - 1) g_rowstart[n] = base + excl + d;
    }
}

__global__ void csr_fill(const void* __restrict__ ei, int ne) {
    int e = blockIdx.x * blockDim.x + threadIdx.x;
    int is64 = (g_bad == 0);
    if (e < ne) {
        int s = getIdx(ei, e, is64);
        int d = getIdx(ei, ne + e, is64);
        int p = atomicAdd(&g_cursor[d], 1);
        g_csr[p] = s;
    }
}

// ---------------- operand prep (weights + x split, one launch) -------------
__global__ void prep_all(const float* __restrict__ W1n,
                         const float* __restrict__ W1s,
                         const float* __restrict__ W2n,
                         const float* __restrict__ W2s,
                         const float* __restrict__ x, int K1, int nx4) {
    const int t1 = 512 * K1;
    const int tw = t1 + 512 * HID;
    const int total = tw + nx4;
    int stride = gridDim.x * blockDim.x;
    for (int idx = blockIdx.x * blockDim.x + threadIdx.x; idx < total;
         idx += stride) {
        if (idx < tw) {
            float v;
            __nv_bfloat16 *dh, *dl;
            int o;
            if (idx < t1) {
                int nrow = idx / K1, k = idx % K1;
                v = (nrow < 256) ? W1n[(size_t)k * 256 + nrow]
                                 : W1s[(size_t)k * 256 + (nrow - 256)];
                dh = g_WT1h; dl = g_WT1l; o = idx;
            } else {
                int j = idx - t1;
                int nrow = j / HID, k = j % HID;
                v = (nrow < 256) ? W2n[(size_t)k * 256 + nrow]
                                 : W2s[(size_t)k * 256 + (nrow - 256)];
                dh = g_WT2h; dl = g_WT2l; o = j;
            }
            __nv_bfloat16 h = __float2bfloat16(v);
            dh[o] = h;
            dl[o] = __float2bfloat16(v - __bfloat162float(h));
        } else {
            int i = idx - tw;
            float4 v = ((const float4*)x)[i];
            __nv_bfloat16 h0 = __float2bfloat16(v.x);
            __nv_bfloat16 h1 = __float2bfloat16(v.y);
            __nv_bfloat16 h2 = __float2bfloat16(v.z);
            __nv_bfloat16 h3 = __float2bfloat16(v.w);
            uint32_t uh0 = (uint32_t)__bfloat16_as_ushort(h0) |
                           ((uint32_t)__bfloat16_as_ushort(h1) << 16);
            uint32_t uh1 = (uint32_t)__bfloat16_as_ushort(h2) |
                           ((uint32_t)__bfloat16_as_ushort(h3) << 16);
            __nv_bfloat16 l0 = __float2bfloat16(v.x - __bfloat162float(h0));
            __nv_bfloat16 l1 = __float2bfloat16(v.y - __bfloat162float(h1));
            __nv_bfloat16 l2 = __float2bfloat16(v.z - __bfloat162float(h2));
            __nv_bfloat16 l3 = __float2bfloat16(v.w - __bfloat162float(h3));
            uint32_t ul0 = (uint32_t)__bfloat16_as_ushort(l0) |
                           ((uint32_t)__bfloat16_as_ushort(l1) << 16);
            uint32_t ul1 = (uint32_t)__bfloat16_as_ushort(l2) |
                           ((uint32_t)__bfloat16_as_ushort(l3) << 16);
            ((uint2*)g_Ah)[i] = make_uint2(uh0, uh1);
            ((uint2*)g_Al)[i] = make_uint2(ul0, ul1);
        }
    }
}

// ---------------- HMMA dual GEMM, cp.async + ldmatrix ----------------
__device__ __forceinline__ void mma16816(float* c, const uint32_t* a,
                                         const uint32_t* b) {
    asm volatile(
        "mma.sync.aligned.m16n8k16.row.col.f32.bf16.bf16.f32 "
        "{%0,%1,%2,%3}, {%4,%5,%6,%7}, {%8,%9}, {%0,%1,%2,%3};"
        : "+f"(c[0]), "+f"(c[1]), "+f"(c[2]), "+f"(c[3])
        : "r"(a[0]), "r"(a[1]), "r"(a[2]), "r"(a[3]), "r"(b[0]), "r"(b[1]));
}

#define SROW 20                       // u32 per row (80 B)
#define SROWB 80
#define TILE_U32 (128 * SROW)
#define STAGE_U32 (4 * TILE_U32)
#define GEMM_SMEM (2 * STAGE_U32 * 4) // 81920 B

__global__ __launch_bounds__(256, 2) void gemm_mma(
    int M, int K, int layer, const float* __restrict__ bias) {
    extern __shared__ uint32_t smem[];
    const uint32_t sb = smem_u32(smem);

    const __nv_bfloat16* Ah = g_Ah;
    const __nv_bfloat16* Al = g_Al;
    const __nv_bfloat16* WTh = layer ? g_WT2h : g_WT1h;
    const __nv_bfloat16* WTl = layer ? g_WT2l : g_WT1l;

    const int tid = threadIdx.x;
    const int wid = tid >> 5;
    const int lane = tid & 31;
    const int g = lane >> 2;
    const int tg = lane & 3;
    const int wm = wid >> 2;
    const int wn = wid & 3;
    const int bm = blockIdx.x * 128;
    const int bn = blockIdx.y * 128;

    const int sub = lane >> 3;
    const int rin = lane & 7;
    const uint32_t a_row_off = (uint32_t)(rin + (sub & 1) * 8) * SROWB +
                               (uint32_t)(sub >> 1) * 16;
    const uint32_t b_row_off = (uint32_t)(rin + (sub >> 1) * 8) * SROWB +
                               (uint32_t)(sub & 1) * 16;

    float acc[4][4][4];
#pragma unroll
    for (int i = 0; i < 4; i++)
#pragma unroll
        for (int j = 0; j < 4; j++)
#pragma unroll
            for (int q = 0; q < 4; q++) acc[i][j][q] = 0.f;

    const int nch = K >> 5;

    auto load_chunk = [&](int ch, int stg) {
        const int k0 = ch << 5;
        const uint32_t sbase = sb + stg * (STAGE_U32 * 4);
#pragma unroll
        for (int r = 0; r < 2; r++) {
            int lin = tid + r * 256;
            int row = lin >> 2;
            int q = lin & 3;
            uint32_t o = (row * SROW + q * 4) * 4;
            int gr = bm + row;   // always valid: g_Ah/g_Al padded
            const __nv_bfloat16* pa = Ah + (size_t)gr * K + k0 + q * 8;
            const __nv_bfloat16* pl = Al + (size_t)gr * K + k0 + q * 8;
            CP_ASYNC16(sbase + o, pa);
            CP_ASYNC16(sbase + TILE_U32 * 4 + o, pl);
            size_t gofs = (size_t)(bn + row) * K + k0 + q * 8;
            CP_ASYNC16(sbase + TILE_U32 * 8 + o, WTh + gofs);
            CP_ASYNC16(sbase + TILE_U32 * 12 + o, WTl + gofs);
        }
    };

    load_chunk(0, 0);
    CP_COMMIT();

    for (int ch = 0; ch < nch; ch++) {
        CP_WAIT(0);
        __syncthreads();
        if (ch + 1 < nch) {
            load_chunk(ch + 1, (ch + 1) & 1);
            CP_COMMIT();
        }

        const uint32_t stg_b = sb + (ch & 1) * (STAGE_U32 * 4);
        const uint32_t aAh = stg_b;
        const uint32_t aAl = stg_b + TILE_U32 * 4;
        const uint32_t aBh = stg_b + TILE_U32 * 8;
        const uint32_t aBl = stg_b + TILE_U32 * 12;

#pragma unroll
        for (int ks = 0; ks < 2; ks++) {
            const uint32_t kofs = (uint32_t)ks * 32;
            uint32_t ah[4][4], al[4][4], bh[4][2], bl[4][2];
#pragma unroll
            for (int mt = 0; mt < 4; mt++) {
                uint32_t rb = (uint32_t)(wm * 64 + mt * 16) * SROWB +
                              a_row_off + kofs;
                ldsm_x4(ah[mt], aAh + rb);
                ldsm_x4(al[mt], aAl + rb);
            }
#pragma unroll
            for (int p = 0; p < 2; p++) {
                uint32_t rb = (uint32_t)(wn * 32 + p * 16) * SROWB +
                              b_row_off + kofs;
                uint32_t t[4];
                ldsm_x4(t, aBh + rb);
                bh[2 * p][0] = t[0]; bh[2 * p][1] = t[1];
                bh[2 * p + 1][0] = t[2]; bh[2 * p + 1][1] = t[3];
                ldsm_x4(t, aBl + rb);
                bl[2 * p][0] = t[0]; bl[2 * p][1] = t[1];
                bl[2 * p + 1][0] = t[2]; bl[2 * p + 1][1] = t[3];
            }
#pragma unroll
            for (int mt = 0; mt < 4; mt++)
#pragma unroll
                for (int nt = 0; nt < 4; nt++)
                    mma16816(acc[mt][nt], ah[mt], bh[nt]);
#pragma unroll
            for (int mt = 0; mt < 4; mt++)
#pragma unroll
                for (int nt = 0; nt < 4; nt++)
                    mma16816(acc[mt][nt], ah[mt], bl[nt]);
#pragma unroll
            for (int mt = 0; mt < 4; mt++)
#pragma unroll
                for (int nt = 0; nt < 4; nt++)
                    mma16816(acc[mt][nt], al[mt], bh[nt]);
        }
    }

    // ---- epilogue ----
#pragma unroll
    for (int mt = 0; mt < 4; mt++) {
        int r0 = bm + wm * 64 + mt * 16 + g;
#pragma unroll
        for (int nt = 0; nt < 4; nt++) {
            int c = bn + wn * 32 + nt * 8 + tg * 2;
            float b0 = 0.f, b1 = 0.f;
            float* dst;
            int cc = c;
            if (c >= 256) {
                cc = c - 256;
                b0 = bias[cc];
                b1 = bias[cc + 1];
                dst = g_bufB;
            } else {
                dst = g_bufA;
            }
            if (r0 < M) {
                float2 v = make_float2(acc[mt][nt][0] + b0, acc[mt][nt][1] + b1);
                *(float2*)(dst + (size_t)r0 * HID + cc) = v;
            }
            if (r0 + 8 < M) {
                float2 v = make_float2(acc[mt][nt][2] + b0, acc[mt][nt][3] + b1);
                *(float2*)(dst + (size_t)(r0 + 8) * HID + cc) = v;
            }
        }
    }
}

// ---- aggregation ----
__global__ void sage_aggregate() {
    int i = blockIdx.x;
    int c = threadIdx.x;  // 256
    int s0 = g_rowstart[i];
    int s1 = g_rowstart[i + 1];
    float acc = 0.f;
    for (int j = s0; j < s1; j++) {
        int s = g_csr[j];
        acc += g_bufA[(size_t)s * HID + c];
    }
    int d = s1 - s0;
    float inv = 1.0f / (float)(d > 0 ? d : 1);
    float v = acc * inv + g_bufB[(size_t)i * HID + c];
    v = fmaxf(v, 0.f);
    size_t o = (size_t)i * HID + c;
    g_bufC[o] = v;
    __nv_bfloat16 h = __float2bfloat16(v);
    g_Ah[o] = h;
    g_Al[o] = __float2bfloat16(v - __bfloat162float(h));
}

// ---------------- pooling / head ----------------
__device__ __forceinline__ int lower_bound_idx(const void* a, int n,
                                               int v, int is64) {
    int lo = 0, hi = n;
    while (lo < hi) {
        int mid = (lo + hi) >> 1;
        if (getIdx(a, mid, is64) < v) lo = mid + 1; else hi = mid;
    }
    return lo;
}

__global__ void pool_kernel(const void* __restrict__ batch, int n) {
    int g = blockIdx.x;
    int s = blockIdx.y;
    int S = gridDim.y;
    int is64 = (g_bad == 0);
    int lo = lower_bound_idx(batch, n, g, is64);
    int hi = lower_bound_idx(batch, n, g + 1, is64);
    int cnt = hi - lo;
    int chunk = (cnt + S - 1) / S;
    int a = lo + s * chunk;
    int b = a + chunk;
    if (b > hi) b = hi;
    int c = threadIdx.x;
    float acc = 0.f;
    for (int i = a; i < b; i++) acc += g_bufC[(size_t)i * HID + c];
    if (a < b) atomicAdd(&g_pool[g * HID + c], acc);
}

__global__ void head_kernel(const void* __restrict__ batch, int n,
                            const float* __restrict__ fc1w,
                            const float* __restrict__ fc1b,
                            const float* __restrict__ fc2w,
                            const float* __restrict__ fc2b,
                            float* __restrict__ out) {
    __shared__ float pooled[HID];
    __shared__ float t1[HID / 2];
    int t = threadIdx.x;  // 256
    int g = blockIdx.x;   // 16 blocks
    int is64 = (g_bad == 0);
    int lo = lower_bound_idx(batch, n, g, is64);
    int hi = lower_bound_idx(batch, n, g + 1, is64);
    float cnt = fmaxf((float)(hi - lo), 1.0f);
    pooled[t] = g_pool[g * HID + t] / cnt;
    __syncthreads();
    if (t < HID / 2) {
        float s = fc1b[t];
        for (int c = 0; c < HID; c++) s += pooled[c] * fc1w[c * (HID / 2) + t];
        t1[t] = fmaxf(s, 0.f);
    }
    __syncthreads();
    if (t < 2) {
        float s = fc2b[t];
        for (int j = 0; j < HID / 2; j++) s += t1[j] * fc2w[j * 2 + t];
        out[g * 2 + t] = s;
    }
}

// ---------------- launch ----------------
extern "C" void kernel_launch(void* const* d_in, const int* in_sizes, int n_in,
                              void* d_out, int out_size) {
    const float* x = (const float*)d_in[0];
    const void* ei = d_in[1];
    const void* batch = d_in[2];
    const float* W1n = (const float*)d_in[3];
    const float* W1s = (const float*)d_in[4];
    const float* b1 = (const float*)d_in[5];
    const float* W2n = (const float*)d_in[6];
    const float* W2s = (const float*)d_in[7];
    const float* b2 = (const float*)d_in[8];
    const float* fc1w = (const float*)d_in[9];
    const float* fc1b = (const float*)d_in[10];
    const float* fc2w = (const float*)d_in[11];
    const float* fc2b = (const float*)d_in[12];
    float* out = (float*)d_out;

    const int n = in_sizes[2];            // 20000 nodes
    const int in_dim = in_sizes[0] / n;   // 512
    const int ne = in_sizes[1] / 2;       // 160000 edges

    static int attr_set = 0;
    if (!attr_set) {
        cudaFuncSetAttribute(gemm_mma,
                             cudaFuncAttributeMaxDynamicSharedMemorySize,
                             GEMM_SMEM);
        attr_set = 1;
    }

    const int nb = (n + SCB - 1) / SCB;

    zero_kernel<<<(n + 255) / 256, 256>>>(n);
    probe_dtype<<<160, 256>>>(ei, ne, n);
    edge_hist<<<(ne + 255) / 256, 256>>>(ei, ne);
    block_sums<<<nb, SCB>>>(n);
    fill_rows<<<nb, SCB>>>(n, nb);
    csr_fill<<<(ne + 255) / 256, 256>>>(ei, ne);
    prep_all<<<592, 256>>>(W1n, W1s, W2n, W2s, x, in_dim, n * in_dim / 4);

    dim3 g1((n + 127) / 128, 4);

    gemm_mma<<<g1, 256, GEMM_SMEM>>>(n, in_dim, 0, b1);
    sage_aggregate<<<n, HID>>>();

    gemm_mma<<<g1, 256, GEMM_SMEM>>>(n, HID, 1, b2);
    sage_aggregate<<<n, HID>>>();

    dim3 gp(NUM_GRAPHS, 32);
    pool_kernel<<<gp, HID>>>(batch, n);
    head_kernel<<<NUM_GRAPHS, HID>>>(batch, n, fc1w, fc1b, fc2w, fc2b, out);
}

// round 11
// speedup vs baseline: 3.0140x; 1.1749x over previous
#include <cuda_runtime.h>
#include <cuda_bf16.h>
#include <cstdint>

#define MAX_NODES 20000
#define MAX_EDGES 160000
#define HID 256
#define NUM_GRAPHS 16

// ---------------- device scratch (static, no runtime alloc) ----------------
__device__ float g_bufA[MAX_NODES * HID];   // y_nbr projections
__device__ float g_bufB[MAX_NODES * HID];   // y_self projections (+bias)
__device__ float g_bufC[MAX_NODES * HID];   // h2 (fp32, for pooling)
__device__ int   g_deg[MAX_NODES];
__device__ int   g_rowstart[MAX_NODES];
__device__ int   g_cursor[MAX_NODES];
__device__ int   g_csr[MAX_EDGES];
__device__ float g_pool[NUM_GRAPHS * HID];
__device__ int   g_bad;                     // !=0 -> index inputs are int32
__device__ int   g_base;                    // CSR allocation ticket

// A operand, bf16 hi/lo split (padded to full 128-row tiles: no edge branch)
#define PAD_ROWS (MAX_NODES + 128)
__device__ __nv_bfloat16 g_Ah[PAD_ROWS * 512];
__device__ __nv_bfloat16 g_Al[PAD_ROWS * 512];

// transposed + hi/lo-split weights
__device__ __nv_bfloat16 g_WT1h[512 * 512];
__device__ __nv_bfloat16 g_WT1l[512 * 512];
__device__ __nv_bfloat16 g_WT2h[512 * 256];
__device__ __nv_bfloat16 g_WT2l[512 * 256];

// ---------------- helpers ----------------
__device__ __forceinline__ uint32_t smem_u32(const void* p) {
    uint32_t a;
    asm("{ .reg .u64 t; cvta.to.shared.u64 t, %1; cvt.u32.u64 %0, t; }"
        : "=r"(a) : "l"(p));
    return a;
}
#define CP_ASYNC16(dst_u32, src_ptr) \
    asm volatile("cp.async.cg.shared.global [%0], [%1], 16;" \
                 :: "r"(dst_u32), "l"(src_ptr))
#define CP_COMMIT() asm volatile("cp.async.commit_group;" ::: "memory")
#define CP_WAIT(N) asm volatile("cp.async.wait_group %0;" :: "n"(N) : "memory")

__device__ __forceinline__ void ldsm_x4(uint32_t* r, uint32_t addr) {
    asm volatile(
        "ldmatrix.sync.aligned.m8n8.x4.shared.b16 {%0,%1,%2,%3}, [%4];"
        : "=r"(r[0]), "=r"(r[1]), "=r"(r[2]), "=r"(r[3]) : "r"(addr));
}

__device__ __forceinline__ int getIdx(const void* p, int i, int is64) {
    if (is64) return (int)((const long long*)p)[i];
    return ((const int*)p)[i];
}

// ---------------- init: zero + dtype probe (one launch) ----------------
__global__ void init_kernel(const void* ei, int ne, int n) {
    int i = blockIdx.x * blockDim.x + threadIdx.x;
    int stride = gridDim.x * blockDim.x;
    if (i == 0) { g_base = 0; }
    for (int j = i; j < n; j += stride) g_deg[j] = 0;
    for (int j = i; j < NUM_GRAPHS * HID; j += stride) g_pool[j] = 0.0f;
    int local = 0;
    for (int e = i; e < ne; e += stride) {
        long long v = ((const long long*)ei)[e];
        if (v < 0 || v >= (long long)n) local = 1;
    }
    if (i == 0) g_bad = 0;        // note: written before any block reads it
    __threadfence();
    if (__syncthreads_or(local)) {
        if (threadIdx.x == 0) atomicOr(&g_bad, 1);
    }
}

// ---------------- CSR build ----------------
__global__ void edge_hist(const void* __restrict__ ei, int ne) {
    int e = blockIdx.x * blockDim.x + threadIdx.x;
    int is64 = (g_bad == 0);
    if (e < ne) {
        int d = getIdx(ei, ne + e, is64);
        atomicAdd(&g_deg[d], 1);
    }
}

#define SCB 256
// per-block scan + atomic base ticket (CSR ranges disjoint; order irrelevant)
__global__ void build_rows(int n) {
    __shared__ int sh[SCB];
    __shared__ int sbase;
    int t = threadIdx.x;
    int i = blockIdx.x * SCB + t;
    int d = (i < n) ? g_deg[i] : 0;
    sh[t] = d;
    __syncthreads();
    for (int off = 1; off < SCB; off <<= 1) {
        int v = (t >= off) ? sh[t - off] : 0;
        __syncthreads();
        sh[t] += v;
        __syncthreads();
    }
    if (t == SCB - 1) sbase = atomicAdd(&g_base, sh[SCB - 1]);
    __syncthreads();
    int excl = sh[t] - d;
    if (i < n) {
        g_rowstart[i] = sbase + excl;
        g_cursor[i] = sbase + excl;
    }
}

__global__ void csr_fill(const void* __restrict__ ei, int ne) {
    int e = blockIdx.x * blockDim.x + threadIdx.x;
    int is64 = (g_bad == 0);
    if (e < ne) {
        int s = getIdx(ei, e, is64);
        int d = getIdx(ei, ne + e, is64);
        int p = atomicAdd(&g_cursor[d], 1);
        g_csr[p] = s;
    }
}

// ---------------- operand prep (weights + x split, one launch) -------------
__global__ void prep_all(const float* __restrict__ W1n,
                         const float* __restrict__ W1s,
                         const float* __restrict__ W2n,
                         const float* __restrict__ W2s,
                         const float* __restrict__ x, int K1, int nx4) {
    const int t1 = 512 * K1;
    const int tw = t1 + 512 * HID;
    const int total = tw + nx4;
    int stride = gridDim.x * blockDim.x;
    for (int idx = blockIdx.x * blockDim.x + threadIdx.x; idx < total;
         idx += stride) {
        if (idx < tw) {
            float v;
            __nv_bfloat16 *dh, *dl;
            int o;
            if (idx < t1) {
                int nrow = idx / K1, k = idx % K1;
                v = (nrow < 256) ? W1n[(size_t)k * 256 + nrow]
                                 : W1s[(size_t)k * 256 + (nrow - 256)];
                dh = g_WT1h; dl = g_WT1l; o = idx;
            } else {
                int j = idx - t1;
                int nrow = j / HID, k = j % HID;
                v = (nrow < 256) ? W2n[(size_t)k * 256 + nrow]
                                 : W2s[(size_t)k * 256 + (nrow - 256)];
                dh = g_WT2h; dl = g_WT2l; o = j;
            }
            __nv_bfloat16 h = __float2bfloat16(v);
            dh[o] = h;
            dl[o] = __float2bfloat16(v - __bfloat162float(h));
        } else {
            int i = idx - tw;
            float4 v = ((const float4*)x)[i];
            __nv_bfloat16 h0 = __float2bfloat16(v.x);
            __nv_bfloat16 h1 = __float2bfloat16(v.y);
            __nv_bfloat16 h2 = __float2bfloat16(v.z);
            __nv_bfloat16 h3 = __float2bfloat16(v.w);
            uint32_t uh0 = (uint32_t)__bfloat16_as_ushort(h0) |
                           ((uint32_t)__bfloat16_as_ushort(h1) << 16);
            uint32_t uh1 = (uint32_t)__bfloat16_as_ushort(h2) |
                           ((uint32_t)__bfloat16_as_ushort(h3) << 16);
            __nv_bfloat16 l0 = __float2bfloat16(v.x - __bfloat162float(h0));
            __nv_bfloat16 l1 = __float2bfloat16(v.y - __bfloat162float(h1));
            __nv_bfloat16 l2 = __float2bfloat16(v.z - __bfloat162float(h2));
            __nv_bfloat16 l3 = __float2bfloat16(v.w - __bfloat162float(h3));
            uint32_t ul0 = (uint32_t)__bfloat16_as_ushort(l0) |
                           ((uint32_t)__bfloat16_as_ushort(l1) << 16);
            uint32_t ul1 = (uint32_t)__bfloat16_as_ushort(l2) |
                           ((uint32_t)__bfloat16_as_ushort(l3) << 16);
            ((uint2*)g_Ah)[i] = make_uint2(uh0, uh1);
            ((uint2*)g_Al)[i] = make_uint2(ul0, ul1);
        }
    }
}

// ---------------- HMMA dual GEMM, cp.async + ldmatrix ----------------
__device__ __forceinline__ void mma16816(float* c, const uint32_t* a,
                                         const uint32_t* b) {
    asm volatile(
        "mma.sync.aligned.m16n8k16.row.col.f32.bf16.bf16.f32 "
        "{%0,%1,%2,%3}, {%4,%5,%6,%7}, {%8,%9}, {%0,%1,%2,%3};"
        : "+f"(c[0]), "+f"(c[1]), "+f"(c[2]), "+f"(c[3])
        : "r"(a[0]), "r"(a[1]), "r"(a[2]), "r"(a[3]), "r"(b[0]), "r"(b[1]));
}

#define SROW 20                       // u32 per row (80 B)
#define SROWB 80
#define TILE_U32 (128 * SROW)
#define STAGE_U32 (4 * TILE_U32)
#define GEMM_SMEM (2 * STAGE_U32 * 4) // 81920 B

__global__ __launch_bounds__(256, 2) void gemm_mma(
    int M, int K, int layer, const float* __restrict__ bias) {
    extern __shared__ uint32_t smem[];
    const uint32_t sb = smem_u32(smem);

    const __nv_bfloat16* Ah = g_Ah;
    const __nv_bfloat16* Al = g_Al;
    const __nv_bfloat16* WTh = layer ? g_WT2h : g_WT1h;
    const __nv_bfloat16* WTl = layer ? g_WT2l : g_WT1l;

    const int tid = threadIdx.x;
    const int wid = tid >> 5;
    const int lane = tid & 31;
    const int g = lane >> 2;
    const int tg = lane & 3;
    const int wm = wid >> 2;
    const int wn = wid & 3;
    const int bm = blockIdx.x * 128;
    const int bn = blockIdx.y * 128;

    const int sub = lane >> 3;
    const int rin = lane & 7;
    const uint32_t a_row_off = (uint32_t)(rin + (sub & 1) * 8) * SROWB +
                               (uint32_t)(sub >> 1) * 16;
    const uint32_t b_row_off = (uint32_t)(rin + (sub >> 1) * 8) * SROWB +
                               (uint32_t)(sub & 1) * 16;

    float acc[4][4][4];
#pragma unroll
    for (int i = 0; i < 4; i++)
#pragma unroll
        for (int j = 0; j < 4; j++)
#pragma unroll
            for (int q = 0; q < 4; q++) acc[i][j][q] = 0.f;

    const int nch = K >> 5;

    auto load_chunk = [&](int ch, int stg) {
        const int k0 = ch << 5;
        const uint32_t sbase = sb + stg * (STAGE_U32 * 4);
#pragma unroll
        for (int r = 0; r < 2; r++) {
            int lin = tid + r * 256;
            int row = lin >> 2;
            int q = lin & 3;
            uint32_t o = (row * SROW + q * 4) * 4;
            int gr = bm + row;   // always valid: g_Ah/g_Al padded
            const __nv_bfloat16* pa = Ah + (size_t)gr * K + k0 + q * 8;
            const __nv_bfloat16* pl = Al + (size_t)gr * K + k0 + q * 8;
            CP_ASYNC16(sbase + o, pa);
            CP_ASYNC16(sbase + TILE_U32 * 4 + o, pl);
            size_t gofs = (size_t)(bn + row) * K + k0 + q * 8;
            CP_ASYNC16(sbase + TILE_U32 * 8 + o, WTh + gofs);
            CP_ASYNC16(sbase + TILE_U32 * 12 + o, WTl + gofs);
        }
    };

    load_chunk(0, 0);
    CP_COMMIT();

    for (int ch = 0; ch < nch; ch++) {
        CP_WAIT(0);
        __syncthreads();
        if (ch + 1 < nch) {
            load_chunk(ch + 1, (ch + 1) & 1);
            CP_COMMIT();
        }

        const uint32_t stg_b = sb + (ch & 1) * (STAGE_U32 * 4);
        const uint32_t aAh = stg_b;
        const uint32_t aAl = stg_b + TILE_U32 * 4;
        const uint32_t aBh = stg_b + TILE_U32 * 8;
        const uint32_t aBl = stg_b + TILE_U32 * 12;

#pragma unroll
        for (int ks = 0; ks < 2; ks++) {
            const uint32_t kofs = (uint32_t)ks * 32;
            uint32_t ah[4][4], al[4][4], bh[4][2], bl[4][2];
#pragma unroll
            for (int mt = 0; mt < 4; mt++) {
                uint32_t rb = (uint32_t)(wm * 64 + mt * 16) * SROWB +
                              a_row_off + kofs;
                ldsm_x4(ah[mt], aAh + rb);
                ldsm_x4(al[mt], aAl + rb);
            }
#pragma unroll
            for (int p = 0; p < 2; p++) {
                uint32_t rb = (uint32_t)(wn * 32 + p * 16) * SROWB +
                              b_row_off + kofs;
                uint32_t t[4];
                ldsm_x4(t, aBh + rb);
                bh[2 * p][0] = t[0]; bh[2 * p][1] = t[1];
                bh[2 * p + 1][0] = t[2]; bh[2 * p + 1][1] = t[3];
                ldsm_x4(t, aBl + rb);
                bl[2 * p][0] = t[0]; bl[2 * p][1] = t[1];
                bl[2 * p + 1][0] = t[2]; bl[2 * p + 1][1] = t[3];
            }
#pragma unroll
            for (int mt = 0; mt < 4; mt++)
#pragma unroll
                for (int nt = 0; nt < 4; nt++)
                    mma16816(acc[mt][nt], ah[mt], bh[nt]);
#pragma unroll
            for (int mt = 0; mt < 4; mt++)
#pragma unroll
                for (int nt = 0; nt < 4; nt++)
                    mma16816(acc[mt][nt], ah[mt], bl[nt]);
#pragma unroll
            for (int mt = 0; mt < 4; mt++)
#pragma unroll
                for (int nt = 0; nt < 4; nt++)
                    mma16816(acc[mt][nt], al[mt], bh[nt]);
        }
    }

    // ---- epilogue ----
#pragma unroll
    for (int mt = 0; mt < 4; mt++) {
        int r0 = bm + wm * 64 + mt * 16 + g;
#pragma unroll
        for (int nt = 0; nt < 4; nt++) {
            int c = bn + wn * 32 + nt * 8 + tg * 2;
            float b0 = 0.f, b1 = 0.f;
            float* dst;
            int cc = c;
            if (c >= 256) {
                cc = c - 256;
                b0 = bias[cc];
                b1 = bias[cc + 1];
                dst = g_bufB;
            } else {
                dst = g_bufA;
            }
            if (r0 < M) {
                float2 v = make_float2(acc[mt][nt][0] + b0, acc[mt][nt][1] + b1);
                *(float2*)(dst + (size_t)r0 * HID + cc) = v;
            }
            if (r0 + 8 < M) {
                float2 v = make_float2(acc[mt][nt][2] + b0, acc[mt][nt][3] + b1);
                *(float2*)(dst + (size_t)(r0 + 8) * HID + cc) = v;
            }
        }
    }
}

// ---- aggregation: 4 nodes/block x 64 threads, float4 ----
// last==0: write bf16 hi/lo split (feeds next GEMM)
// last==1: write fp32 h to g_bufC (feeds pooling)
__global__ void sage_aggregate(int n, int last) {
    int node = blockIdx.x * 4 + (threadIdx.x >> 6);
    int c = (threadIdx.x & 63) * 4;
    if (node >= n) return;
    int s0 = g_rowstart[node];
    int d = g_deg[node];
    float4 acc = make_float4(0.f, 0.f, 0.f, 0.f);
    for (int j = 0; j < d; j++) {
        int s = g_csr[s0 + j];
        float4 v = *(const float4*)(g_bufA + (size_t)s * HID + c);
        acc.x += v.x; acc.y += v.y; acc.z += v.z; acc.w += v.w;
    }
    float inv = 1.0f / (float)(d > 0 ? d : 1);
    float4 w = *(const float4*)(g_bufB + (size_t)node * HID + c);
    float4 h;
    h.x = fmaxf(acc.x * inv + w.x, 0.f);
    h.y = fmaxf(acc.y * inv + w.y, 0.f);
    h.z = fmaxf(acc.z * inv + w.z, 0.f);
    h.w = fmaxf(acc.w * inv + w.w, 0.f);
    size_t o = (size_t)node * HID + c;
    if (last) {
        *(float4*)(g_bufC + o) = h;
    } else {
        __nv_bfloat16 h0 = __float2bfloat16(h.x);
        __nv_bfloat16 h1 = __float2bfloat16(h.y);
        __nv_bfloat16 h2 = __float2bfloat16(h.z);
        __nv_bfloat16 h3 = __float2bfloat16(h.w);
        uint32_t uh0 = (uint32_t)__bfloat16_as_ushort(h0) |
                       ((uint32_t)__bfloat16_as_ushort(h1) << 16);
        uint32_t uh1 = (uint32_t)__bfloat16_as_ushort(h2) |
                       ((uint32_t)__bfloat16_as_ushort(h3) << 16);
        __nv_bfloat16 l0 = __float2bfloat16(h.x - __bfloat162float(h0));
        __nv_bfloat16 l1 = __float2bfloat16(h.y - __bfloat162float(h1));
        __nv_bfloat16 l2 = __float2bfloat16(h.z - __bfloat162float(h2));
        __nv_bfloat16 l3 = __float2bfloat16(h.w - __bfloat162float(h3));
        uint32_t ul0 = (uint32_t)__bfloat16_as_ushort(l0) |
                       ((uint32_t)__bfloat16_as_ushort(l1) << 16);
        uint32_t ul1 = (uint32_t)__bfloat16_as_ushort(l2) |
                       ((uint32_t)__bfloat16_as_ushort(l3) << 16);
        *(uint2*)(g_Ah + o) = make_uint2(uh0, uh1);
        *(uint2*)(g_Al + o) = make_uint2(ul0, ul1);
    }
}

// ---------------- pooling / head ----------------
__device__ __forceinline__ int lower_bound_idx(const void* a, int n,
                                               int v, int is64) {
    int lo = 0, hi = n;
    while (lo < hi) {
        int mid = (lo + hi) >> 1;
        if (getIdx(a, mid, is64) < v) lo = mid + 1; else hi = mid;
    }
    return lo;
}

__global__ void pool_kernel(const void* __restrict__ batch, int n) {
    int g = blockIdx.x;
    int s = blockIdx.y;
    int S = gridDim.y;
    int is64 = (g_bad == 0);
    int lo = lower_bound_idx(batch, n, g, is64);
    int hi = lower_bound_idx(batch, n, g + 1, is64);
    int cnt = hi - lo;
    int chunk = (cnt + S - 1) / S;
    int a = lo + s * chunk;
    int b = a + chunk;
    if (b > hi) b = hi;
    int c = threadIdx.x;
    float acc = 0.f;
    for (int i = a; i < b; i++) acc += g_bufC[(size_t)i * HID + c];
    if (a < b) atomicAdd(&g_pool[g * HID + c], acc);
}

__global__ void head_kernel(const void* __restrict__ batch, int n,
                            const float* __restrict__ fc1w,
                            const float* __restrict__ fc1b,
                            const float* __restrict__ fc2w,
                            const float* __restrict__ fc2b,
                            float* __restrict__ out) {
    __shared__ float pooled[HID];
    __shared__ float t1[HID / 2];
    int t = threadIdx.x;  // 256
    int g = blockIdx.x;   // 16 blocks
    int is64 = (g_bad == 0);
    int lo = lower_bound_idx(batch, n, g, is64);
    int hi = lower_bound_idx(batch, n, g + 1, is64);
    float cnt = fmaxf((float)(hi - lo), 1.0f);
    pooled[t] = g_pool[g * HID + t] / cnt;
    __syncthreads();
    if (t < HID / 2) {
        float s = fc1b[t];
        for (int c = 0; c < HID; c++) s += pooled[c] * fc1w[c * (HID / 2) + t];
        t1[t] = fmaxf(s, 0.f);
    }
    __syncthreads();
    if (t < 2) {
        float s = fc2b[t];
        for (int j = 0; j < HID / 2; j++) s += t1[j] * fc2w[j * 2 + t];
        out[g * 2 + t] = s;
    }
}

// ---------------- launch ----------------
extern "C" void kernel_launch(void* const* d_in, const int* in_sizes, int n_in,
                              void* d_out, int out_size) {
    const float* x = (const float*)d_in[0];
    const void* ei = d_in[1];
    const void* batch = d_in[2];
    const float* W1n = (const float*)d_in[3];
    const float* W1s = (const float*)d_in[4];
    const float* b1 = (const float*)d_in[5];
    const float* W2n = (const float*)d_in[6];
    const float* W2s = (const float*)d_in[7];
    const float* b2 = (const float*)d_in[8];
    const float* fc1w = (const float*)d_in[9];
    const float* fc1b = (const float*)d_in[10];
    const float* fc2w = (const float*)d_in[11];
    const float* fc2b = (const float*)d_in[12];
    float* out = (float*)d_out;

    const int n = in_sizes[2];            // 20000 nodes
    const int in_dim = in_sizes[0] / n;   // 512
    const int ne = in_sizes[1] / 2;       // 160000 edges

    static int attr_set = 0;
    if (!attr_set) {
        cudaFuncSetAttribute(gemm_mma,
                             cudaFuncAttributeMaxDynamicSharedMemorySize,
                             GEMM_SMEM);
        attr_set = 1;
    }

    const int nb = (n + SCB - 1) / SCB;

    init_kernel<<<160, 256>>>(ei, ne, n);
    edge_hist<<<(ne + 255) / 256, 256>>>(ei, ne);
    build_rows<<<nb, SCB>>>(n);
    csr_fill<<<(ne + 255) / 256, 256>>>(ei, ne);
    prep_all<<<592, 256>>>(W1n, W1s, W2n, W2s, x, in_dim, n * in_dim / 4);

    dim3 g1((n + 127) / 128, 4);

    gemm_mma<<<g1, 256, GEMM_SMEM>>>(n, in_dim, 0, b1);
    sage_aggregate<<<(n + 3) / 4, 256>>>(n, 0);

    gemm_mma<<<g1, 256, GEMM_SMEM>>>(n, HID, 1, b2);
    sage_aggregate<<<(n + 3) / 4, 256>>>(n, 1);

    dim3 gp(NUM_GRAPHS, 32);
    pool_kernel<<<gp, HID>>>(batch, n);
    head_kernel<<<NUM_GRAPHS, HID>>>(batch, n, fc1w, fc1b, fc2w, fc2b, out);
}

// round 12
// speedup vs baseline: 3.0788x; 1.0215x over previous
#include <cuda_runtime.h>
#include <cuda_bf16.h>
#include <cstdint>

#define MAX_NODES 20000
#define MAX_EDGES 160000
#define HID 256
#define NUM_GRAPHS 16

// ---------------- device scratch (static, no runtime alloc) ----------------
__device__ float g_bufA[MAX_NODES * HID];   // y_nbr projections
__device__ float g_bufB[MAX_NODES * HID];   // y_self projections (+bias)
__device__ float g_bufC[MAX_NODES * HID];   // h2 (fp32, for pooling)
__device__ int   g_deg[MAX_NODES];
__device__ int   g_rowstart[MAX_NODES];
__device__ int   g_cursor[MAX_NODES];
__device__ int   g_csr[MAX_EDGES];
__device__ float g_pool[NUM_GRAPHS * HID];
__device__ int   g_bad;                     // !=0 -> index inputs are int32
__device__ int   g_base;                    // CSR allocation ticket

// A operand, bf16 hi/lo split (padded to full 128-row tiles: no edge branch)
#define PAD_ROWS (MAX_NODES + 128)
__device__ __nv_bfloat16 g_Ah[PAD_ROWS * 512];
__device__ __nv_bfloat16 g_Al[PAD_ROWS * 512];

// transposed + hi/lo-split weights
__device__ __nv_bfloat16 g_WT1h[512 * 512];
__device__ __nv_bfloat16 g_WT1l[512 * 512];
__device__ __nv_bfloat16 g_WT2h[512 * 256];
__device__ __nv_bfloat16 g_WT2l[512 * 256];

// ---------------- helpers ----------------
__device__ __forceinline__ uint32_t smem_u32(const void* p) {
    uint32_t a;
    asm("{ .reg .u64 t; cvta.to.shared.u64 t, %1; cvt.u32.u64 %0, t; }"
        : "=r"(a) : "l"(p));
    return a;
}
#define CP_ASYNC16(dst_u32, src_ptr) \
    asm volatile("cp.async.cg.shared.global [%0], [%1], 16;" \
                 :: "r"(dst_u32), "l"(src_ptr))
#define CP_COMMIT() asm volatile("cp.async.commit_group;" ::: "memory")
#define CP_WAIT(N) asm volatile("cp.async.wait_group %0;" :: "n"(N) : "memory")

__device__ __forceinline__ void ldsm_x4(uint32_t* r, uint32_t addr) {
    asm volatile(
        "ldmatrix.sync.aligned.m8n8.x4.shared.b16 {%0,%1,%2,%3}, [%4];"
        : "=r"(r[0]), "=r"(r[1]), "=r"(r[2]), "=r"(r[3]) : "r"(addr));
}

__device__ __forceinline__ int getIdx(const void* p, int i, int is64) {
    if (is64) return (int)((const long long*)p)[i];
    return ((const int*)p)[i];
}

// ---------------- init: zero + dtype probe (one launch) ----------------
__global__ void init_kernel(const void* ei, int ne, int n) {
    int i = blockIdx.x * blockDim.x + threadIdx.x;
    int stride = gridDim.x * blockDim.x;
    if (i == 0) { g_base = 0; }
    for (int j = i; j < n; j += stride) g_deg[j] = 0;
    for (int j = i; j < NUM_GRAPHS * HID; j += stride) g_pool[j] = 0.0f;
    int local = 0;
    for (int e = i; e < ne; e += stride) {
        long long v = ((const long long*)ei)[e];
        if (v < 0 || v >= (long long)n) local = 1;
    }
    if (i == 0) g_bad = 0;        // note: written before any block reads it
    __threadfence();
    if (__syncthreads_or(local)) {
        if (threadIdx.x == 0) atomicOr(&g_bad, 1);
    }
}

// ---------------- CSR build ----------------
__global__ void edge_hist(const void* __restrict__ ei, int ne) {
    int e = blockIdx.x * blockDim.x + threadIdx.x;
    int is64 = (g_bad == 0);
    if (e < ne) {
        int d = getIdx(ei, ne + e, is64);
        atomicAdd(&g_deg[d], 1);
    }
}

#define SCB 256
// per-block scan + atomic base ticket (CSR ranges disjoint; order irrelevant)
__global__ void build_rows(int n) {
    __shared__ int sh[SCB];
    __shared__ int sbase;
    int t = threadIdx.x;
    int i = blockIdx.x * SCB + t;
    int d = (i < n) ? g_deg[i] : 0;
    sh[t] = d;
    __syncthreads();
    for (int off = 1; off < SCB; off <<= 1) {
        int v = (t >= off) ? sh[t - off] : 0;
        __syncthreads();
        sh[t] += v;
        __syncthreads();
    }
    if (t == SCB - 1) sbase = atomicAdd(&g_base, sh[SCB - 1]);
    __syncthreads();
    int excl = sh[t] - d;
    if (i < n) {
        g_rowstart[i] = sbase + excl;
        g_cursor[i] = sbase + excl;
    }
}

__global__ void csr_fill(const void* __restrict__ ei, int ne) {
    int e = blockIdx.x * blockDim.x + threadIdx.x;
    int is64 = (g_bad == 0);
    if (e < ne) {
        int s = getIdx(ei, e, is64);
        int d = getIdx(ei, ne + e, is64);
        int p = atomicAdd(&g_cursor[d], 1);
        g_csr[p] = s;
    }
}

// ---------------- operand prep (weights + x split, one launch) -------------
__global__ void prep_all(const float* __restrict__ W1n,
                         const float* __restrict__ W1s,
                         const float* __restrict__ W2n,
                         const float* __restrict__ W2s,
                         const float* __restrict__ x, int K1, int nx4) {
    const int t1 = 512 * K1;
    const int tw = t1 + 512 * HID;
    const int total = tw + nx4;
    int stride = gridDim.x * blockDim.x;
    for (int idx = blockIdx.x * blockDim.x + threadIdx.x; idx < total;
         idx += stride) {
        if (idx < tw) {
            float v;
            __nv_bfloat16 *dh, *dl;
            int o;
            if (idx < t1) {
                int nrow = idx / K1, k = idx % K1;
                v = (nrow < 256) ? W1n[(size_t)k * 256 + nrow]
                                 : W1s[(size_t)k * 256 + (nrow - 256)];
                dh = g_WT1h; dl = g_WT1l; o = idx;
            } else {
                int j = idx - t1;
                int nrow = j / HID, k = j % HID;
                v = (nrow < 256) ? W2n[(size_t)k * 256 + nrow]
                                 : W2s[(size_t)k * 256 + (nrow - 256)];
                dh = g_WT2h; dl = g_WT2l; o = j;
            }
            __nv_bfloat16 h = __float2bfloat16(v);
            dh[o] = h;
            dl[o] = __float2bfloat16(v - __bfloat162float(h));
        } else {
            int i = idx - tw;
            float4 v = ((const float4*)x)[i];
            __nv_bfloat16 h0 = __float2bfloat16(v.x);
            __nv_bfloat16 h1 = __float2bfloat16(v.y);
            __nv_bfloat16 h2 = __float2bfloat16(v.z);
            __nv_bfloat16 h3 = __float2bfloat16(v.w);
            uint32_t uh0 = (uint32_t)__bfloat16_as_ushort(h0) |
                           ((uint32_t)__bfloat16_as_ushort(h1) << 16);
            uint32_t uh1 = (uint32_t)__bfloat16_as_ushort(h2) |
                           ((uint32_t)__bfloat16_as_ushort(h3) << 16);
            __nv_bfloat16 l0 = __float2bfloat16(v.x - __bfloat162float(h0));
            __nv_bfloat16 l1 = __float2bfloat16(v.y - __bfloat162float(h1));
            __nv_bfloat16 l2 = __float2bfloat16(v.z - __bfloat162float(h2));
            __nv_bfloat16 l3 = __float2bfloat16(v.w - __bfloat162float(h3));
            uint32_t ul0 = (uint32_t)__bfloat16_as_ushort(l0) |
                           ((uint32_t)__bfloat16_as_ushort(l1) << 16);
            uint32_t ul1 = (uint32_t)__bfloat16_as_ushort(l2) |
                           ((uint32_t)__bfloat16_as_ushort(l3) << 16);
            ((uint2*)g_Ah)[i] = make_uint2(uh0, uh1);
            ((uint2*)g_Al)[i] = make_uint2(ul0, ul1);
        }
    }
}

// ---------------- HMMA dual GEMM, cp.async + ldmatrix ----------------
__device__ __forceinline__ void mma16816(float* c, const uint32_t* a,
                                         const uint32_t* b) {
    asm volatile(
        "mma.sync.aligned.m16n8k16.row.col.f32.bf16.bf16.f32 "
        "{%0,%1,%2,%3}, {%4,%5,%6,%7}, {%8,%9}, {%0,%1,%2,%3};"
        : "+f"(c[0]), "+f"(c[1]), "+f"(c[2]), "+f"(c[3])
        : "r"(a[0]), "r"(a[1]), "r"(a[2]), "r"(a[3]), "r"(b[0]), "r"(b[1]));
}

#define SROW 20                       // u32 per row (80 B)
#define SROWB 80
#define TILE_U32 (128 * SROW)
#define STAGE_U32 (4 * TILE_U32)
#define GEMM_SMEM (2 * STAGE_U32 * 4) // 81920 B

__global__ __launch_bounds__(256, 2) void gemm_mma(
    int M, int K, int layer, const float* __restrict__ bias) {
    extern __shared__ uint32_t smem[];
    const uint32_t sb = smem_u32(smem);

    const __nv_bfloat16* Ah = g_Ah;
    const __nv_bfloat16* Al = g_Al;
    const __nv_bfloat16* WTh = layer ? g_WT2h : g_WT1h;
    const __nv_bfloat16* WTl = layer ? g_WT2l : g_WT1l;

    const int tid = threadIdx.x;
    const int wid = tid >> 5;
    const int lane = tid & 31;
    const int g = lane >> 2;
    const int tg = lane & 3;
    const int wm = wid >> 2;
    const int wn = wid & 3;
    const int bm = blockIdx.x * 128;
    const int bn = blockIdx.y * 128;

    const int sub = lane >> 3;
    const int rin = lane & 7;
    const uint32_t a_row_off = (uint32_t)(rin + (sub & 1) * 8) * SROWB +
                               (uint32_t)(sub >> 1) * 16;
    const uint32_t b_row_off = (uint32_t)(rin + (sub >> 1) * 8) * SROWB +
                               (uint32_t)(sub & 1) * 16;

    float acc[4][4][4];
#pragma unroll
    for (int i = 0; i < 4; i++)
#pragma unroll
        for (int j = 0; j < 4; j++)
#pragma unroll
            for (int q = 0; q < 4; q++) acc[i][j][q] = 0.f;

    const int nch = K >> 5;

    auto load_chunk = [&](int ch, int stg) {
        const int k0 = ch << 5;
        const uint32_t sbase = sb + stg * (STAGE_U32 * 4);
#pragma unroll
        for (int r = 0; r < 2; r++) {
            int lin = tid + r * 256;
            int row = lin >> 2;
            int q = lin & 3;
            uint32_t o = (row * SROW + q * 4) * 4;
            int gr = bm + row;   // always valid: g_Ah/g_Al padded
            const __nv_bfloat16* pa = Ah + (size_t)gr * K + k0 + q * 8;
            const __nv_bfloat16* pl = Al + (size_t)gr * K + k0 + q * 8;
            CP_ASYNC16(sbase + o, pa);
            CP_ASYNC16(sbase + TILE_U32 * 4 + o, pl);
            size_t gofs = (size_t)(bn + row) * K + k0 + q * 8;
            CP_ASYNC16(sbase + TILE_U32 * 8 + o, WTh + gofs);
            CP_ASYNC16(sbase + TILE_U32 * 12 + o, WTl + gofs);
        }
    };

    load_chunk(0, 0);
    CP_COMMIT();

    for (int ch = 0; ch < nch; ch++) {
        CP_WAIT(0);
        __syncthreads();
        if (ch + 1 < nch) {
            load_chunk(ch + 1, (ch + 1) & 1);
            CP_COMMIT();
        }

        const uint32_t stg_b = sb + (ch & 1) * (STAGE_U32 * 4);
        const uint32_t aAh = stg_b;
        const uint32_t aAl = stg_b + TILE_U32 * 4;
        const uint32_t aBh = stg_b + TILE_U32 * 8;
        const uint32_t aBl = stg_b + TILE_U32 * 12;

#pragma unroll
        for (int ks = 0; ks < 2; ks++) {
            const uint32_t kofs = (uint32_t)ks * 32;
            uint32_t ah[4][4], al[4][4], bh[4][2], bl[4][2];
#pragma unroll
            for (int mt = 0; mt < 4; mt++) {
                uint32_t rb = (uint32_t)(wm * 64 + mt * 16) * SROWB +
                              a_row_off + kofs;
                ldsm_x4(ah[mt], aAh + rb);
                ldsm_x4(al[mt], aAl + rb);
            }
#pragma unroll
            for (int p = 0; p < 2; p++) {
                uint32_t rb = (uint32_t)(wn * 32 + p * 16) * SROWB +
                              b_row_off + kofs;
                uint32_t t[4];
                ldsm_x4(t, aBh + rb);
                bh[2 * p][0] = t[0]; bh[2 * p][1] = t[1];
                bh[2 * p + 1][0] = t[2]; bh[2 * p + 1][1] = t[3];
                ldsm_x4(t, aBl + rb);
                bl[2 * p][0] = t[0]; bl[2 * p][1] = t[1];
                bl[2 * p + 1][0] = t[2]; bl[2 * p + 1][1] = t[3];
            }
#pragma unroll
            for (int mt = 0; mt < 4; mt++)
#pragma unroll
                for (int nt = 0; nt < 4; nt++)
                    mma16816(acc[mt][nt], ah[mt], bh[nt]);
#pragma unroll
            for (int mt = 0; mt < 4; mt++)
#pragma unroll
                for (int nt = 0; nt < 4; nt++)
                    mma16816(acc[mt][nt], ah[mt], bl[nt]);
#pragma unroll
            for (int mt = 0; mt < 4; mt++)
#pragma unroll
                for (int nt = 0; nt < 4; nt++)
                    mma16816(acc[mt][nt], al[mt], bh[nt]);
        }
    }

    // ---- epilogue ----
#pragma unroll
    for (int mt = 0; mt < 4; mt++) {
        int r0 = bm + wm * 64 + mt * 16 + g;
#pragma unroll
        for (int nt = 0; nt < 4; nt++) {
            int c = bn + wn * 32 + nt * 8 + tg * 2;
            float b0 = 0.f, b1 = 0.f;
            float* dst;
            int cc = c;
            if (c >= 256) {
                cc = c - 256;
                b0 = bias[cc];
                b1 = bias[cc + 1];
                dst = g_bufB;
            } else {
                dst = g_bufA;
            }
            if (r0 < M) {
                float2 v = make_float2(acc[mt][nt][0] + b0, acc[mt][nt][1] + b1);
                *(float2*)(dst + (size_t)r0 * HID + cc) = v;
            }
            if (r0 + 8 < M) {
                float2 v = make_float2(acc[mt][nt][2] + b0, acc[mt][nt][3] + b1);
                *(float2*)(dst + (size_t)(r0 + 8) * HID + cc) = v;
            }
        }
    }
}

// ---- aggregation: 4 nodes/block x 64 threads, float4 ----
// last==0: write bf16 hi/lo split (feeds next GEMM)
// last==1: write fp32 h to g_bufC (feeds pooling)
__global__ void sage_aggregate(int n, int last) {
    int node = blockIdx.x * 4 + (threadIdx.x >> 6);
    int c = (threadIdx.x & 63) * 4;
    if (node >= n) return;
    int s0 = g_rowstart[node];
    int d = g_deg[node];
    float4 acc = make_float4(0.f, 0.f, 0.f, 0.f);
#pragma unroll 4
    for (int j = 0; j < d; j++) {
        int s = g_csr[s0 + j];
        float4 v = *(const float4*)(g_bufA + (size_t)s * HID + c);
        acc.x += v.x; acc.y += v.y; acc.z += v.z; acc.w += v.w;
    }
    float inv = 1.0f / (float)(d > 0 ? d : 1);
    float4 w = *(const float4*)(g_bufB + (size_t)node * HID + c);
    float4 h;
    h.x = fmaxf(acc.x * inv + w.x, 0.f);
    h.y = fmaxf(acc.y * inv + w.y, 0.f);
    h.z = fmaxf(acc.z * inv + w.z, 0.f);
    h.w = fmaxf(acc.w * inv + w.w, 0.f);
    size_t o = (size_t)node * HID + c;
    if (last) {
        *(float4*)(g_bufC + o) = h;
    } else {
        __nv_bfloat16 h0 = __float2bfloat16(h.x);
        __nv_bfloat16 h1 = __float2bfloat16(h.y);
        __nv_bfloat16 h2 = __float2bfloat16(h.z);
        __nv_bfloat16 h3 = __float2bfloat16(h.w);
        uint32_t uh0 = (uint32_t)__bfloat16_as_ushort(h0) |
                       ((uint32_t)__bfloat16_as_ushort(h1) << 16);
        uint32_t uh1 = (uint32_t)__bfloat16_as_ushort(h2) |
                       ((uint32_t)__bfloat16_as_ushort(h3) << 16);
        __nv_bfloat16 l0 = __float2bfloat16(h.x - __bfloat162float(h0));
        __nv_bfloat16 l1 = __float2bfloat16(h.y - __bfloat162float(h1));
        __nv_bfloat16 l2 = __float2bfloat16(h.z - __bfloat162float(h2));
        __nv_bfloat16 l3 = __float2bfloat16(h.w - __bfloat162float(h3));
        uint32_t ul0 = (uint32_t)__bfloat16_as_ushort(l0) |
                       ((uint32_t)__bfloat16_as_ushort(l1) << 16);
        uint32_t ul1 = (uint32_t)__bfloat16_as_ushort(l2) |
                       ((uint32_t)__bfloat16_as_ushort(l3) << 16);
        *(uint2*)(g_Ah + o) = make_uint2(uh0, uh1);
        *(uint2*)(g_Al + o) = make_uint2(ul0, ul1);
    }
}

// ---------------- pooling / head ----------------
__device__ __forceinline__ int lower_bound_idx(const void* a, int n,
                                               int v, int is64) {
    int lo = 0, hi = n;
    while (lo < hi) {
        int mid = (lo + hi) >> 1;
        if (getIdx(a, mid, is64) < v) lo = mid + 1; else hi = mid;
    }
    return lo;
}

__global__ void pool_kernel(const void* __restrict__ batch, int n) {
    int g = blockIdx.x;
    int s = blockIdx.y;
    int S = gridDim.y;
    int is64 = (g_bad == 0);
    int lo = lower_bound_idx(batch, n, g, is64);
    int hi = lower_bound_idx(batch, n, g + 1, is64);
    int cnt = hi - lo;
    int chunk = (cnt + S - 1) / S;
    int a = lo + s * chunk;
    int b = a + chunk;
    if (b > hi) b = hi;
    int c = threadIdx.x;
    float acc = 0.f;
    for (int i = a; i < b; i++) acc += g_bufC[(size_t)i * HID + c];
    if (a < b) atomicAdd(&g_pool[g * HID + c], acc);
}

__global__ void head_kernel(const void* __restrict__ batch, int n,
                            const float* __restrict__ fc1w,
                            const float* __restrict__ fc1b,
                            const float* __restrict__ fc2w,
                            const float* __restrict__ fc2b,
                            float* __restrict__ out) {
    __shared__ float pooled[HID];
    __shared__ float t1[HID / 2];
    int t = threadIdx.x;  // 256
    int g = blockIdx.x;   // 16 blocks
    int is64 = (g_bad == 0);
    int lo = lower_bound_idx(batch, n, g, is64);
    int hi = lower_bound_idx(batch, n, g + 1, is64);
    float cnt = fmaxf((float)(hi - lo), 1.0f);
    pooled[t] = g_pool[g * HID + t] / cnt;
    __syncthreads();
    if (t < HID / 2) {
        float s = fc1b[t];
        for (int c = 0; c < HID; c++) s += pooled[c] * fc1w[c * (HID / 2) + t];
        t1[t] = fmaxf(s, 0.f);
    }
    __syncthreads();
    if (t < 2) {
        float s = fc2b[t];
        for (int j = 0; j < HID / 2; j++) s += t1[j] * fc2w[j * 2 + t];
        out[g * 2 + t] = s;
    }
}

// ---------------- launch ----------------
extern "C" void kernel_launch(void* const* d_in, const int* in_sizes, int n_in,
                              void* d_out, int out_size) {
    const float* x = (const float*)d_in[0];
    const void* ei = d_in[1];
    const void* batch = d_in[2];
    const float* W1n = (const float*)d_in[3];
    const float* W1s = (const float*)d_in[4];
    const float* b1 = (const float*)d_in[5];
    const float* W2n = (const float*)d_in[6];
    const float* W2s = (const float*)d_in[7];
    const float* b2 = (const float*)d_in[8];
    const float* fc1w = (const float*)d_in[9];
    const float* fc1b = (const float*)d_in[10];
    const float* fc2w = (const float*)d_in[11];
    const float* fc2b = (const float*)d_in[12];
    float* out = (float*)d_out;

    const int n = in_sizes[2];            // 20000 nodes
    const int in_dim = in_sizes[0] / n;   // 512
    const int ne = in_sizes[1] / 2;       // 160000 edges

    static cudaStream_t s2 = nullptr;
    static cudaEvent_t evF = nullptr, evJ = nullptr;
    static int attr_set = 0;
    if (!attr_set) {
        cudaFuncSetAttribute(gemm_mma,
                             cudaFuncAttributeMaxDynamicSharedMemorySize,
                             GEMM_SMEM);
        cudaStreamCreateWithFlags(&s2, cudaStreamNonBlocking);
        cudaEventCreateWithFlags(&evF, cudaEventDisableTiming);
        cudaEventCreateWithFlags(&evJ, cudaEventDisableTiming);
        attr_set = 1;
    }

    const int nb = (n + SCB - 1) / SCB;

    // main stream: init -> hist -> prep -> gemm1
    init_kernel<<<160, 256>>>(ei, ne, n);
    edge_hist<<<(ne + 255) / 256, 256>>>(ei, ne);

    // fork: CSR finishing (rows + fill) runs concurrently with prep+gemm1
    cudaEventRecord(evF, 0);
    cudaStreamWaitEvent(s2, evF, 0);
    build_rows<<<nb, SCB, 0, s2>>>(n);
    csr_fill<<<(ne + 255) / 256, 256, 0, s2>>>(ei, ne);
    cudaEventRecord(evJ, s2);

    prep_all<<<592, 256>>>(W1n, W1s, W2n, W2s, x, in_dim, n * in_dim / 4);

    dim3 g1((n + 127) / 128, 4);
    gemm_mma<<<g1, 256, GEMM_SMEM>>>(n, in_dim, 0, b1);

    // join: aggregation needs the CSR
    cudaStreamWaitEvent(0, evJ, 0);
    sage_aggregate<<<(n + 3) / 4, 256>>>(n, 0);

    gemm_mma<<<g1, 256, GEMM_SMEM>>>(n, HID, 1, b2);
    sage_aggregate<<<(n + 3) / 4, 256>>>(n, 1);

    dim3 gp(NUM_GRAPHS, 32);
    pool_kernel<<<gp, HID>>>(batch, n);
    head_kernel<<<NUM_GRAPHS, HID>>>(batch, n, fc1w, fc1b, fc2w, fc2b, out);
}

// round 13
// speedup vs baseline: 3.7144x; 1.2065x over previous
#include <cuda_runtime.h>
#include <cuda_fp16.h>
#include <cstdint>

#define MAX_NODES 20000
#define MAX_EDGES 160000
#define HID 256
#define NUM_GRAPHS 16

// ---------------- device scratch (static, no runtime alloc) ----------------
__device__ float g_bufA[MAX_NODES * HID];   // y_nbr projections
__device__ float g_bufB[MAX_NODES * HID];   // y_self projections (+bias)
__device__ float g_bufC[MAX_NODES * HID];   // h2 (fp32, for pooling)
__device__ int   g_deg[MAX_NODES];
__device__ int   g_rowstart[MAX_NODES];
__device__ int   g_cursor[MAX_NODES];
__device__ int   g_csr[MAX_EDGES];
__device__ float g_pool[NUM_GRAPHS * HID];
__device__ int   g_bad;                     // !=0 -> index inputs are int32
__device__ int   g_base;                    // CSR allocation ticket

// A operand, fp16 hi/lo split (padded to full 128-row tiles)
#define PAD_ROWS (MAX_NODES + 128)
__device__ __half g_Ah[PAD_ROWS * 512];
__device__ __half g_Al[PAD_ROWS * 512];

// transposed fp16 weights: WT[n][k], n in [0,512)
__device__ __half g_WT1h[512 * 512];
__device__ __half g_WT2h[512 * 256];

// ---------------- helpers ----------------
__device__ __forceinline__ uint32_t smem_u32(const void* p) {
    uint32_t a;
    asm("{ .reg .u64 t; cvta.to.shared.u64 t, %1; cvt.u32.u64 %0, t; }"
        : "=r"(a) : "l"(p));
    return a;
}
#define CP_ASYNC16(dst_u32, src_ptr) \
    asm volatile("cp.async.cg.shared.global [%0], [%1], 16;" \
                 :: "r"(dst_u32), "l"(src_ptr))
#define CP_COMMIT() asm volatile("cp.async.commit_group;" ::: "memory")
#define CP_WAIT(N) asm volatile("cp.async.wait_group %0;" :: "n"(N) : "memory")

__device__ __forceinline__ void ldsm_x4(uint32_t* r, uint32_t addr) {
    asm volatile(
        "ldmatrix.sync.aligned.m8n8.x4.shared.b16 {%0,%1,%2,%3}, [%4];"
        : "=r"(r[0]), "=r"(r[1]), "=r"(r[2]), "=r"(r[3]) : "r"(addr));
}

__device__ __forceinline__ int getIdx(const void* p, int i, int is64) {
    if (is64) return (int)((const long long*)p)[i];
    return ((const int*)p)[i];
}

// ---------------- init: zero + dtype probe (one launch) ----------------
__global__ void init_kernel(const void* ei, int ne, int n) {
    int i = blockIdx.x * blockDim.x + threadIdx.x;
    int stride = gridDim.x * blockDim.x;
    if (i == 0) { g_base = 0; }
    for (int j = i; j < n; j += stride) g_deg[j] = 0;
    for (int j = i; j < NUM_GRAPHS * HID; j += stride) g_pool[j] = 0.0f;
    int local = 0;
    for (int e = i; e < ne; e += stride) {
        long long v = ((const long long*)ei)[e];
        if (v < 0 || v >= (long long)n) local = 1;
    }
    if (i == 0) g_bad = 0;
    __threadfence();
    if (__syncthreads_or(local)) {
        if (threadIdx.x == 0) atomicOr(&g_bad, 1);
    }
}

// ---------------- CSR build ----------------
__global__ void edge_hist(const void* __restrict__ ei, int ne) {
    int e = blockIdx.x * blockDim.x + threadIdx.x;
    int is64 = (g_bad == 0);
    if (e < ne) {
        int d = getIdx(ei, ne + e, is64);
        atomicAdd(&g_deg[d], 1);
    }
}

#define SCB 256
__global__ void build_rows(int n) {
    __shared__ int sh[SCB];
    __shared__ int sbase;
    int t = threadIdx.x;
    int i = blockIdx.x * SCB + t;
    int d = (i < n) ? g_deg[i] : 0;
    sh[t] = d;
    __syncthreads();
    for (int off = 1; off < SCB; off <<= 1) {
        int v = (t >= off) ? sh[t - off] : 0;
        __syncthreads();
        sh[t] += v;
        __syncthreads();
    }
    if (t == SCB - 1) sbase = atomicAdd(&g_base, sh[SCB - 1]);
    __syncthreads();
    int excl = sh[t] - d;
    if (i < n) {
        g_rowstart[i] = sbase + excl;
        g_cursor[i] = sbase + excl;
    }
}

__global__ void csr_fill(const void* __restrict__ ei, int ne) {
    int e = blockIdx.x * blockDim.x + threadIdx.x;
    int is64 = (g_bad == 0);
    if (e < ne) {
        int s = getIdx(ei, e, is64);
        int d = getIdx(ei, ne + e, is64);
        int p = atomicAdd(&g_cursor[d], 1);
        g_csr[p] = s;
    }
}

// ---------------- operand prep (weights + x split, one launch) -------------
__global__ void prep_all(const float* __restrict__ W1n,
                         const float* __restrict__ W1s,
                         const float* __restrict__ W2n,
                         const float* __restrict__ W2s,
                         const float* __restrict__ x, int K1, int nx4) {
    const int t1 = 512 * K1;
    const int tw = t1 + 512 * HID;
    const int total = tw + nx4;
    int stride = gridDim.x * blockDim.x;
    for (int idx = blockIdx.x * blockDim.x + threadIdx.x; idx < total;
         idx += stride) {
        if (idx < tw) {
            float v;
            __half* dh;
            int o;
            if (idx < t1) {
                int nrow = idx / K1, k = idx % K1;
                v = (nrow < 256) ? W1n[(size_t)k * 256 + nrow]
                                 : W1s[(size_t)k * 256 + (nrow - 256)];
                dh = g_WT1h; o = idx;
            } else {
                int j = idx - t1;
                int nrow = j / HID, k = j % HID;
                v = (nrow < 256) ? W2n[(size_t)k * 256 + nrow]
                                 : W2s[(size_t)k * 256 + (nrow - 256)];
                dh = g_WT2h; o = j;
            }
            dh[o] = __float2half(v);
        } else {
            int i = idx - tw;
            float4 v = ((const float4*)x)[i];
            __half h0 = __float2half(v.x);
            __half h1 = __float2half(v.y);
            __half h2 = __float2half(v.z);
            __half h3 = __float2half(v.w);
            uint32_t uh0 = (uint32_t)__half_as_ushort(h0) |
                           ((uint32_t)__half_as_ushort(h1) << 16);
            uint32_t uh1 = (uint32_t)__half_as_ushort(h2) |
                           ((uint32_t)__half_as_ushort(h3) << 16);
            __half l0 = __float2half(v.x - __half2float(h0));
            __half l1 = __float2half(v.y - __half2float(h1));
            __half l2 = __float2half(v.z - __half2float(h2));
            __half l3 = __float2half(v.w - __half2float(h3));
            uint32_t ul0 = (uint32_t)__half_as_ushort(l0) |
                           ((uint32_t)__half_as_ushort(l1) << 16);
            uint32_t ul1 = (uint32_t)__half_as_ushort(l2) |
                           ((uint32_t)__half_as_ushort(l3) << 16);
            ((uint2*)g_Ah)[i] = make_uint2(uh0, uh1);
            ((uint2*)g_Al)[i] = make_uint2(ul0, ul1);
        }
    }
}

// ---------------- HMMA dual GEMM, fp16 2-pass, cp.async + ldmatrix ---------
__device__ __forceinline__ void mma16816(float* c, const uint32_t* a,
                                         const uint32_t* b) {
    asm volatile(
        "mma.sync.aligned.m16n8k16.row.col.f32.f16.f16.f32 "
        "{%0,%1,%2,%3}, {%4,%5,%6,%7}, {%8,%9}, {%0,%1,%2,%3};"
        : "+f"(c[0]), "+f"(c[1]), "+f"(c[2]), "+f"(c[3])
        : "r"(a[0]), "r"(a[1]), "r"(a[2]), "r"(a[3]), "r"(b[0]), "r"(b[1]));
}

#define SROW 20                       // u32 per row (80 B)
#define SROWB 80
#define TILE_U32 (128 * SROW)
#define STAGE_U32 (3 * TILE_U32)      // Ah, Al, Bh
#define GEMM_SMEM (2 * STAGE_U32 * 4) // 61440 B

__global__ __launch_bounds__(256, 2) void gemm_mma(
    int M, int K, int layer, const float* __restrict__ bias) {
    extern __shared__ uint32_t smem[];
    const uint32_t sb = smem_u32(smem);

    const __half* Ah = g_Ah;
    const __half* Al = g_Al;
    const __half* WTh = layer ? g_WT2h : g_WT1h;

    const int tid = threadIdx.x;
    const int wid = tid >> 5;
    const int lane = tid & 31;
    const int g = lane >> 2;
    const int tg = lane & 3;
    const int wm = wid >> 2;
    const int wn = wid & 3;
    const int bm = blockIdx.x * 128;
    const int bn = blockIdx.y * 128;

    const int sub = lane >> 3;
    const int rin = lane & 7;
    const uint32_t a_row_off = (uint32_t)(rin + (sub & 1) * 8) * SROWB +
                               (uint32_t)(sub >> 1) * 16;
    const uint32_t b_row_off = (uint32_t)(rin + (sub >> 1) * 8) * SROWB +
                               (uint32_t)(sub & 1) * 16;

    float acc[4][4][4];
#pragma unroll
    for (int i = 0; i < 4; i++)
#pragma unroll
        for (int j = 0; j < 4; j++)
#pragma unroll
            for (int q = 0; q < 4; q++) acc[i][j][q] = 0.f;

    const int nch = K >> 5;

    auto load_chunk = [&](int ch, int stg) {
        const int k0 = ch << 5;
        const uint32_t sbase = sb + stg * (STAGE_U32 * 4);
#pragma unroll
        for (int r = 0; r < 2; r++) {
            int lin = tid + r * 256;
            int row = lin >> 2;
            int q = lin & 3;
            uint32_t o = (row * SROW + q * 4) * 4;
            int gr = bm + row;   // always valid: g_Ah/g_Al padded
            const __half* pa = Ah + (size_t)gr * K + k0 + q * 8;
            const __half* pl = Al + (size_t)gr * K + k0 + q * 8;
            CP_ASYNC16(sbase + o, pa);
            CP_ASYNC16(sbase + TILE_U32 * 4 + o, pl);
            size_t gofs = (size_t)(bn + row) * K + k0 + q * 8;
            CP_ASYNC16(sbase + TILE_U32 * 8 + o, WTh + gofs);
        }
    };

    load_chunk(0, 0);
    CP_COMMIT();

    for (int ch = 0; ch < nch; ch++) {
        CP_WAIT(0);
        __syncthreads();
        if (ch + 1 < nch) {
            load_chunk(ch + 1, (ch + 1) & 1);
            CP_COMMIT();
        }

        const uint32_t stg_b = sb + (ch & 1) * (STAGE_U32 * 4);
        const uint32_t aAh = stg_b;
        const uint32_t aAl = stg_b + TILE_U32 * 4;
        const uint32_t aBh = stg_b + TILE_U32 * 8;

#pragma unroll
        for (int ks = 0; ks < 2; ks++) {
            const uint32_t kofs = (uint32_t)ks * 32;
            uint32_t ah[4][4], al[4][4], bh[4][2];
#pragma unroll
            for (int mt = 0; mt < 4; mt++) {
                uint32_t rb = (uint32_t)(wm * 64 + mt * 16) * SROWB +
                              a_row_off + kofs;
                ldsm_x4(ah[mt], aAh + rb);
                ldsm_x4(al[mt], aAl + rb);
            }
#pragma unroll
            for (int p = 0; p < 2; p++) {
                uint32_t rb = (uint32_t)(wn * 32 + p * 16) * SROWB +
                              b_row_off + kofs;
                uint32_t t[4];
                ldsm_x4(t, aBh + rb);
                bh[2 * p][0] = t[0]; bh[2 * p][1] = t[1];
                bh[2 * p + 1][0] = t[2]; bh[2 * p + 1][1] = t[3];
            }
            // pass-major: hi then lo
#pragma unroll
            for (int mt = 0; mt < 4; mt++)
#pragma unroll
                for (int nt = 0; nt < 4; nt++)
                    mma16816(acc[mt][nt], ah[mt], bh[nt]);
#pragma unroll
            for (int mt = 0; mt < 4; mt++)
#pragma unroll
                for (int nt = 0; nt < 4; nt++)
                    mma16816(acc[mt][nt], al[mt], bh[nt]);
        }
    }

    // ---- epilogue ----
#pragma unroll
    for (int mt = 0; mt < 4; mt++) {
        int r0 = bm + wm * 64 + mt * 16 + g;
#pragma unroll
        for (int nt = 0; nt < 4; nt++) {
            int c = bn + wn * 32 + nt * 8 + tg * 2;
            float b0 = 0.f, b1 = 0.f;
            float* dst;
            int cc = c;
            if (c >= 256) {
                cc = c - 256;
                b0 = bias[cc];
                b1 = bias[cc + 1];
                dst = g_bufB;
            } else {
                dst = g_bufA;
            }
            if (r0 < M) {
                float2 v = make_float2(acc[mt][nt][0] + b0, acc[mt][nt][1] + b1);
                *(float2*)(dst + (size_t)r0 * HID + cc) = v;
            }
            if (r0 + 8 < M) {
                float2 v = make_float2(acc[mt][nt][2] + b0, acc[mt][nt][3] + b1);
                *(float2*)(dst + (size_t)(r0 + 8) * HID + cc) = v;
            }
        }
    }
}

// ---- aggregation: 4 nodes/block x 64 threads, float4 ----
__global__ void sage_aggregate(int n, int last) {
    int node = blockIdx.x * 4 + (threadIdx.x >> 6);
    int c = (threadIdx.x & 63) * 4;
    if (node >= n) return;
    int s0 = g_rowstart[node];
    int d = g_deg[node];
    float4 acc = make_float4(0.f, 0.f, 0.f, 0.f);
#pragma unroll 4
    for (int j = 0; j < d; j++) {
        int s = g_csr[s0 + j];
        float4 v = *(const float4*)(g_bufA + (size_t)s * HID + c);
        acc.x += v.x; acc.y += v.y; acc.z += v.z; acc.w += v.w;
    }
    float inv = 1.0f / (float)(d > 0 ? d : 1);
    float4 w = *(const float4*)(g_bufB + (size_t)node * HID + c);
    float4 h;
    h.x = fmaxf(acc.x * inv + w.x, 0.f);
    h.y = fmaxf(acc.y * inv + w.y, 0.f);
    h.z = fmaxf(acc.z * inv + w.z, 0.f);
    h.w = fmaxf(acc.w * inv + w.w, 0.f);
    size_t o = (size_t)node * HID + c;
    if (last) {
        *(float4*)(g_bufC + o) = h;
    } else {
        __half h0 = __float2half(h.x);
        __half h1 = __float2half(h.y);
        __half h2 = __float2half(h.z);
        __half h3 = __float2half(h.w);
        uint32_t uh0 = (uint32_t)__half_as_ushort(h0) |
                       ((uint32_t)__half_as_ushort(h1) << 16);
        uint32_t uh1 = (uint32_t)__half_as_ushort(h2) |
                       ((uint32_t)__half_as_ushort(h3) << 16);
        __half l0 = __float2half(h.x - __half2float(h0));
        __half l1 = __float2half(h.y - __half2float(h1));
        __half l2 = __float2half(h.z - __half2float(h2));
        __half l3 = __float2half(h.w - __half2float(h3));
        uint32_t ul0 = (uint32_t)__half_as_ushort(l0) |
                       ((uint32_t)__half_as_ushort(l1) << 16);
        uint32_t ul1 = (uint32_t)__half_as_ushort(l2) |
                       ((uint32_t)__half_as_ushort(l3) << 16);
        *(uint2*)(g_Ah + o) = make_uint2(uh0, uh1);
        *(uint2*)(g_Al + o) = make_uint2(ul0, ul1);
    }
}

// ---------------- pooling / head ----------------
__device__ __forceinline__ int lower_bound_idx(const void* a, int n,
                                               int v, int is64) {
    int lo = 0, hi = n;
    while (lo < hi) {
        int mid = (lo + hi) >> 1;
        if (getIdx(a, mid, is64) < v) lo = mid + 1; else hi = mid;
    }
    return lo;
}

__global__ void pool_kernel(const void* __restrict__ batch, int n) {
    int g = blockIdx.x;
    int s = blockIdx.y;
    int S = gridDim.y;
    int is64 = (g_bad == 0);
    int lo = lower_bound_idx(batch, n, g, is64);
    int hi = lower_bound_idx(batch, n, g + 1, is64);
    int cnt = hi - lo;
    int chunk = (cnt + S - 1) / S;
    int a = lo + s * chunk;
    int b = a + chunk;
    if (b > hi) b = hi;
    int c = threadIdx.x;
    float acc = 0.f;
    for (int i = a; i < b; i++) acc += g_bufC[(size_t)i * HID + c];
    if (a < b) atomicAdd(&g_pool[g * HID + c], acc);
}

__global__ void head_kernel(const void* __restrict__ batch, int n,
                            const float* __restrict__ fc1w,
                            const float* __restrict__ fc1b,
                            const float* __restrict__ fc2w,
                            const float* __restrict__ fc2b,
                            float* __restrict__ out) {
    __shared__ float pooled[HID];
    __shared__ float t1[HID / 2];
    int t = threadIdx.x;  // 256
    int g = blockIdx.x;   // 16 blocks
    int is64 = (g_bad == 0);
    int lo = lower_bound_idx(batch, n, g, is64);
    int hi = lower_bound_idx(batch, n, g + 1, is64);
    float cnt = fmaxf((float)(hi - lo), 1.0f);
    pooled[t] = g_pool[g * HID + t] / cnt;
    __syncthreads();
    if (t < HID / 2) {
        float s = fc1b[t];
        for (int c = 0; c < HID; c++) s += pooled[c] * fc1w[c * (HID / 2) + t];
        t1[t] = fmaxf(s, 0.f);
    }
    __syncthreads();
    if (t < 2) {
        float s = fc2b[t];
        for (int j = 0; j < HID / 2; j++) s += t1[j] * fc2w[j * 2 + t];
        out[g * 2 + t] = s;
    }
}

// ---------------- launch ----------------
extern "C" void kernel_launch(void* const* d_in, const int* in_sizes, int n_in,
                              void* d_out, int out_size) {
    const float* x = (const float*)d_in[0];
    const void* ei = d_in[1];
    const void* batch = d_in[2];
    const float* W1n = (const float*)d_in[3];
    const float* W1s = (const float*)d_in[4];
    const float* b1 = (const float*)d_in[5];
    const float* W2n = (const float*)d_in[6];
    const float* W2s = (const float*)d_in[7];
    const float* b2 = (const float*)d_in[8];
    const float* fc1w = (const float*)d_in[9];
    const float* fc1b = (const float*)d_in[10];
    const float* fc2w = (const float*)d_in[11];
    const float* fc2b = (const float*)d_in[12];
    float* out = (float*)d_out;

    const int n = in_sizes[2];            // 20000 nodes
    const int in_dim = in_sizes[0] / n;   // 512
    const int ne = in_sizes[1] / 2;       // 160000 edges

    static cudaStream_t s2 = nullptr;
    static cudaEvent_t evF = nullptr, evJ = nullptr;
    static int attr_set = 0;
    if (!attr_set) {
        cudaFuncSetAttribute(gemm_mma,
                             cudaFuncAttributeMaxDynamicSharedMemorySize,
                             GEMM_SMEM);
        cudaStreamCreateWithFlags(&s2, cudaStreamNonBlocking);
        cudaEventCreateWithFlags(&evF, cudaEventDisableTiming);
        cudaEventCreateWithFlags(&evJ, cudaEventDisableTiming);
        attr_set = 1;
    }

    const int nb = (n + SCB - 1) / SCB;

    // main stream: init -> hist -> prep -> gemm1
    init_kernel<<<160, 256>>>(ei, ne, n);
    edge_hist<<<(ne + 255) / 256, 256>>>(ei, ne);

    // fork: CSR finishing (rows + fill) runs concurrently with prep+gemm1
    cudaEventRecord(evF, 0);
    cudaStreamWaitEvent(s2, evF, 0);
    build_rows<<<nb, SCB, 0, s2>>>(n);
    csr_fill<<<(ne + 255) / 256, 256, 0, s2>>>(ei, ne);
    cudaEventRecord(evJ, s2);

    prep_all<<<592, 256>>>(W1n, W1s, W2n, W2s, x, in_dim, n * in_dim / 4);

    dim3 g1((n + 127) / 128, 4);
    gemm_mma<<<g1, 256, GEMM_SMEM>>>(n, in_dim, 0, b1);

    // join: aggregation needs the CSR
    cudaStreamWaitEvent(0, evJ, 0);
    sage_aggregate<<<(n + 3) / 4, 256>>>(n, 0);

    gemm_mma<<<g1, 256, GEMM_SMEM>>>(n, HID, 1, b2);
    sage_aggregate<<<(n + 3) / 4, 256>>>(n, 1);

    dim3 gp(NUM_GRAPHS, 32);
    pool_kernel<<<gp, HID>>>(batch, n);
    head_kernel<<<NUM_GRAPHS, HID>>>(batch, n, fc1w, fc1b, fc2w, fc2b, out);
}

// round 14
// speedup vs baseline: 4.7710x; 1.2845x over previous
#include <cuda_runtime.h>
#include <cuda_fp16.h>
#include <cstdint>

#define MAX_NODES 20000
#define MAX_EDGES 160000
#define HID 256
#define NUM_GRAPHS 16

// ---------------- device scratch (static, no runtime alloc) ----------------
__device__ float g_bufA[MAX_NODES * HID];   // y_nbr projections
__device__ float g_bufB[MAX_NODES * HID];   // y_self projections (+bias)
__device__ float g_bufC[MAX_NODES * HID];   // h2 (fp32, for pooling)
__device__ int   g_deg[MAX_NODES];
__device__ int   g_rowstart[MAX_NODES];
__device__ int   g_cursor[MAX_NODES];
__device__ int   g_csr[MAX_EDGES];
__device__ float g_pool[NUM_GRAPHS * HID];
__device__ int   g_bad;                     // !=0 -> index inputs are int32
__device__ int   g_base;                    // CSR allocation ticket

// A operand fp16 (padded to full 128-row tiles)
#define PAD_ROWS (MAX_NODES + 128)
__device__ __half g_Ah[PAD_ROWS * 512];

// transposed fp16 weights: WT[n][k], n in [0,512)
__device__ __half g_WT1h[512 * 512];
__device__ __half g_WT2h[512 * 256];

// ---------------- helpers ----------------
__device__ __forceinline__ uint32_t smem_u32(const void* p) {
    uint32_t a;
    asm("{ .reg .u64 t; cvta.to.shared.u64 t, %1; cvt.u32.u64 %0, t; }"
        : "=r"(a) : "l"(p));
    return a;
}
#define CP_ASYNC16(dst_u32, src_ptr) \
    asm volatile("cp.async.cg.shared.global [%0], [%1], 16;" \
                 :: "r"(dst_u32), "l"(src_ptr))
#define CP_COMMIT() asm volatile("cp.async.commit_group;" ::: "memory")
#define CP_WAIT(N) asm volatile("cp.async.wait_group %0;" :: "n"(N) : "memory")

__device__ __forceinline__ void ldsm_x4(uint32_t* r, uint32_t addr) {
    asm volatile(
        "ldmatrix.sync.aligned.m8n8.x4.shared.b16 {%0,%1,%2,%3}, [%4];"
        : "=r"(r[0]), "=r"(r[1]), "=r"(r[2]), "=r"(r[3]) : "r"(addr));
}

__device__ __forceinline__ int getIdx(const void* p, int i, int is64) {
    if (is64) return (int)((const long long*)p)[i];
    return ((const int*)p)[i];
}

// ---------------- init: zero + dtype probe (one launch) ----------------
__global__ void init_kernel(const void* ei, int ne, int n) {
    int i = blockIdx.x * blockDim.x + threadIdx.x;
    int stride = gridDim.x * blockDim.x;
    if (i == 0) { g_base = 0; }
    for (int j = i; j < n; j += stride) g_deg[j] = 0;
    for (int j = i; j < NUM_GRAPHS * HID; j += stride) g_pool[j] = 0.0f;
    int local = 0;
    for (int e = i; e < ne; e += stride) {
        long long v = ((const long long*)ei)[e];
        if (v < 0 || v >= (long long)n) local = 1;
    }
    if (i == 0) g_bad = 0;
    __threadfence();
    if (__syncthreads_or(local)) {
        if (threadIdx.x == 0) atomicOr(&g_bad, 1);
    }
}

// ---------------- CSR build ----------------
__global__ void edge_hist(const void* __restrict__ ei, int ne) {
    int e = blockIdx.x * blockDim.x + threadIdx.x;
    int is64 = (g_bad == 0);
    if (e < ne) {
        int d = getIdx(ei, ne + e, is64);
        atomicAdd(&g_deg[d], 1);
    }
}

#define SCB 256
__global__ void build_rows(int n) {
    __shared__ int sh[SCB];
    __shared__ int sbase;
    int t = threadIdx.x;
    int i = blockIdx.x * SCB + t;
    int d = (i < n) ? g_deg[i] : 0;
    sh[t] = d;
    __syncthreads();
    for (int off = 1; off < SCB; off <<= 1) {
        int v = (t >= off) ? sh[t - off] : 0;
        __syncthreads();
        sh[t] += v;
        __syncthreads();
    }
    if (t == SCB - 1) sbase = atomicAdd(&g_base, sh[SCB - 1]);
    __syncthreads();
    int excl = sh[t] - d;
    if (i < n) {
        g_rowstart[i] = sbase + excl;
        g_cursor[i] = sbase + excl;
    }
}

__global__ void csr_fill(const void* __restrict__ ei, int ne) {
    int e = blockIdx.x * blockDim.x + threadIdx.x;
    int is64 = (g_bad == 0);
    if (e < ne) {
        int s = getIdx(ei, e, is64);
        int d = getIdx(ei, ne + e, is64);
        int p = atomicAdd(&g_cursor[d], 1);
        g_csr[p] = s;
    }
}

// ---------------- operand prep (weights + x convert, one launch) -----------
__global__ void prep_all(const float* __restrict__ W1n,
                         const float* __restrict__ W1s,
                         const float* __restrict__ W2n,
                         const float* __restrict__ W2s,
                         const float* __restrict__ x, int K1, int nx4) {
    const int t1 = 512 * K1;
    const int tw = t1 + 512 * HID;
    const int total = tw + nx4;
    int stride = gridDim.x * blockDim.x;
    for (int idx = blockIdx.x * blockDim.x + threadIdx.x; idx < total;
         idx += stride) {
        if (idx < tw) {
            float v;
            __half* dh;
            int o;
            if (idx < t1) {
                int nrow = idx / K1, k = idx % K1;
                v = (nrow < 256) ? W1n[(size_t)k * 256 + nrow]
                                 : W1s[(size_t)k * 256 + (nrow - 256)];
                dh = g_WT1h; o = idx;
            } else {
                int j = idx - t1;
                int nrow = j / HID, k = j % HID;
                v = (nrow < 256) ? W2n[(size_t)k * 256 + nrow]
                                 : W2s[(size_t)k * 256 + (nrow - 256)];
                dh = g_WT2h; o = j;
            }
            dh[o] = __float2half(v);
        } else {
            int i = idx - tw;
            float4 v = ((const float4*)x)[i];
            __half h0 = __float2half(v.x);
            __half h1 = __float2half(v.y);
            __half h2 = __float2half(v.z);
            __half h3 = __float2half(v.w);
            uint32_t uh0 = (uint32_t)__half_as_ushort(h0) |
                           ((uint32_t)__half_as_ushort(h1) << 16);
            uint32_t uh1 = (uint32_t)__half_as_ushort(h2) |
                           ((uint32_t)__half_as_ushort(h3) << 16);
            ((uint2*)g_Ah)[i] = make_uint2(uh0, uh1);
        }
    }
}

// ---------------- HMMA dual GEMM, fp16 1-pass, 3-stage cp.async ------------
__device__ __forceinline__ void mma16816(float* c, const uint32_t* a,
                                         const uint32_t* b) {
    asm volatile(
        "mma.sync.aligned.m16n8k16.row.col.f32.f16.f16.f32 "
        "{%0,%1,%2,%3}, {%4,%5,%6,%7}, {%8,%9}, {%0,%1,%2,%3};"
        : "+f"(c[0]), "+f"(c[1]), "+f"(c[2]), "+f"(c[3])
        : "r"(a[0]), "r"(a[1]), "r"(a[2]), "r"(a[3]), "r"(b[0]), "r"(b[1]));
}

#define SROW 20                       // u32 per row (80 B)
#define SROWB 80
#define TILE_U32 (128 * SROW)
#define STAGE_U32 (2 * TILE_U32)      // A, B
#define NSTAGE 3
#define GEMM_SMEM (NSTAGE * STAGE_U32 * 4) // 61440 B

__global__ __launch_bounds__(256, 2) void gemm_mma(
    int M, int K, int layer, const float* __restrict__ bias) {
    extern __shared__ uint32_t smem[];
    const uint32_t sb = smem_u32(smem);

    const __half* Ah = g_Ah;
    const __half* WTh = layer ? g_WT2h : g_WT1h;

    const int tid = threadIdx.x;
    const int wid = tid >> 5;
    const int lane = tid & 31;
    const int g = lane >> 2;
    const int tg = lane & 3;
    const int wm = wid >> 2;
    const int wn = wid & 3;
    const int bm = blockIdx.x * 128;
    const int bn = blockIdx.y * 128;

    const int sub = lane >> 3;
    const int rin = lane & 7;
    const uint32_t a_row_off = (uint32_t)(rin + (sub & 1) * 8) * SROWB +
                               (uint32_t)(sub >> 1) * 16;
    const uint32_t b_row_off = (uint32_t)(rin + (sub >> 1) * 8) * SROWB +
                               (uint32_t)(sub & 1) * 16;

    float acc[4][4][4];
#pragma unroll
    for (int i = 0; i < 4; i++)
#pragma unroll
        for (int j = 0; j < 4; j++)
#pragma unroll
            for (int q = 0; q < 4; q++) acc[i][j][q] = 0.f;

    const int nch = K >> 5;

    auto load_chunk = [&](int ch, int stg) {
        const int k0 = ch << 5;
        const uint32_t sbase = sb + stg * (STAGE_U32 * 4);
#pragma unroll
        for (int r = 0; r < 2; r++) {
            int lin = tid + r * 256;
            int row = lin >> 2;
            int q = lin & 3;
            uint32_t o = (row * SROW + q * 4) * 4;
            int gr = bm + row;   // always valid: g_Ah padded
            const __half* pa = Ah + (size_t)gr * K + k0 + q * 8;
            CP_ASYNC16(sbase + o, pa);
            size_t gofs = (size_t)(bn + row) * K + k0 + q * 8;
            CP_ASYNC16(sbase + TILE_U32 * 4 + o, WTh + gofs);
        }
    };

    load_chunk(0, 0);
    CP_COMMIT();
    if (nch > 1) {
        load_chunk(1, 1);
        CP_COMMIT();
    }

    for (int ch = 0; ch < nch; ch++) {
        if (ch + 1 < nch) CP_WAIT(1); else CP_WAIT(0);
        __syncthreads();
        if (ch + 2 < nch) {
            load_chunk(ch + 2, (ch + 2) % NSTAGE);
            CP_COMMIT();
        }

        const uint32_t stg_b = sb + (ch % NSTAGE) * (STAGE_U32 * 4);
        const uint32_t aAh = stg_b;
        const uint32_t aBh = stg_b + TILE_U32 * 4;

#pragma unroll
        for (int ks = 0; ks < 2; ks++) {
            const uint32_t kofs = (uint32_t)ks * 32;
            uint32_t ah[4][4], bh[4][2];
#pragma unroll
            for (int mt = 0; mt < 4; mt++) {
                uint32_t rb = (uint32_t)(wm * 64 + mt * 16) * SROWB +
                              a_row_off + kofs;
                ldsm_x4(ah[mt], aAh + rb);
            }
#pragma unroll
            for (int p = 0; p < 2; p++) {
                uint32_t rb = (uint32_t)(wn * 32 + p * 16) * SROWB +
                              b_row_off + kofs;
                uint32_t t[4];
                ldsm_x4(t, aBh + rb);
                bh[2 * p][0] = t[0]; bh[2 * p][1] = t[1];
                bh[2 * p + 1][0] = t[2]; bh[2 * p + 1][1] = t[3];
            }
#pragma unroll
            for (int mt = 0; mt < 4; mt++)
#pragma unroll
                for (int nt = 0; nt < 4; nt++)
                    mma16816(acc[mt][nt], ah[mt], bh[nt]);
        }
    }

    // ---- epilogue ----
#pragma unroll
    for (int mt = 0; mt < 4; mt++) {
        int r0 = bm + wm * 64 + mt * 16 + g;
#pragma unroll
        for (int nt = 0; nt < 4; nt++) {
            int c = bn + wn * 32 + nt * 8 + tg * 2;
            float b0 = 0.f, b1 = 0.f;
            float* dst;
            int cc = c;
            if (c >= 256) {
                cc = c - 256;
                b0 = bias[cc];
                b1 = bias[cc + 1];
                dst = g_bufB;
            } else {
                dst = g_bufA;
            }
            if (r0 < M) {
                float2 v = make_float2(acc[mt][nt][0] + b0, acc[mt][nt][1] + b1);
                *(float2*)(dst + (size_t)r0 * HID + cc) = v;
            }
            if (r0 + 8 < M) {
                float2 v = make_float2(acc[mt][nt][2] + b0, acc[mt][nt][3] + b1);
                *(float2*)(dst + (size_t)(r0 + 8) * HID + cc) = v;
            }
        }
    }
}

// ---- aggregation: 4 nodes/block x 64 threads, float4 ----
__global__ void sage_aggregate(int n, int last) {
    int node = blockIdx.x * 4 + (threadIdx.x >> 6);
    int c = (threadIdx.x & 63) * 4;
    if (node >= n) return;
    int s0 = g_rowstart[node];
    int d = g_deg[node];
    float4 acc = make_float4(0.f, 0.f, 0.f, 0.f);
#pragma unroll 4
    for (int j = 0; j < d; j++) {
        int s = g_csr[s0 + j];
        float4 v = *(const float4*)(g_bufA + (size_t)s * HID + c);
        acc.x += v.x; acc.y += v.y; acc.z += v.z; acc.w += v.w;
    }
    float inv = 1.0f / (float)(d > 0 ? d : 1);
    float4 w = *(const float4*)(g_bufB + (size_t)node * HID + c);
    float4 h;
    h.x = fmaxf(acc.x * inv + w.x, 0.f);
    h.y = fmaxf(acc.y * inv + w.y, 0.f);
    h.z = fmaxf(acc.z * inv + w.z, 0.f);
    h.w = fmaxf(acc.w * inv + w.w, 0.f);
    size_t o = (size_t)node * HID + c;
    if (last) {
        *(float4*)(g_bufC + o) = h;
    } else {
        __half h0 = __float2half(h.x);
        __half h1 = __float2half(h.y);
        __half h2 = __float2half(h.z);
        __half h3 = __float2half(h.w);
        uint32_t uh0 = (uint32_t)__half_as_ushort(h0) |
                       ((uint32_t)__half_as_ushort(h1) << 16);
        uint32_t uh1 = (uint32_t)__half_as_ushort(h2) |
                       ((uint32_t)__half_as_ushort(h3) << 16);
        *(uint2*)(g_Ah + o) = make_uint2(uh0, uh1);
    }
}

// ---------------- pooling / head ----------------
__device__ __forceinline__ int lower_bound_idx(const void* a, int n,
                                               int v, int is64) {
    int lo = 0, hi = n;
    while (lo < hi) {
        int mid = (lo + hi) >> 1;
        if (getIdx(a, mid, is64) < v) lo = mid + 1; else hi = mid;
    }
    return lo;
}

__global__ void pool_kernel(const void* __restrict__ batch, int n) {
    int g = blockIdx.x;
    int s = blockIdx.y;
    int S = gridDim.y;
    int is64 = (g_bad == 0);
    int lo = lower_bound_idx(batch, n, g, is64);
    int hi = lower_bound_idx(batch, n, g + 1, is64);
    int cnt = hi - lo;
    int chunk = (cnt + S - 1) / S;
    int a = lo + s * chunk;
    int b = a + chunk;
    if (b > hi) b = hi;
    int c = threadIdx.x;
    float acc = 0.f;
    for (int i = a; i < b; i++) acc += g_bufC[(size_t)i * HID + c];
    if (a < b) atomicAdd(&g_pool[g * HID + c], acc);
}

__global__ void head_kernel(const void* __restrict__ batch, int n,
                            const float* __restrict__ fc1w,
                            const float* __restrict__ fc1b,
                            const float* __restrict__ fc2w,
                            const float* __restrict__ fc2b,
                            float* __restrict__ out) {
    __shared__ float pooled[HID];
    __shared__ float t1[HID / 2];
    int t = threadIdx.x;  // 256
    int g = blockIdx.x;   // 16 blocks
    int is64 = (g_bad == 0);
    int lo = lower_bound_idx(batch, n, g, is64);
    int hi = lower_bound_idx(batch, n, g + 1, is64);
    float cnt = fmaxf((float)(hi - lo), 1.0f);
    pooled[t] = g_pool[g * HID + t] / cnt;
    __syncthreads();
    if (t < HID / 2) {
        float s = fc1b[t];
        for (int c = 0; c < HID; c++) s += pooled[c] * fc1w[c * (HID / 2) + t];
        t1[t] = fmaxf(s, 0.f);
    }
    __syncthreads();
    if (t < 2) {
        float s = fc2b[t];
        for (int j = 0; j < HID / 2; j++) s += t1[j] * fc2w[j * 2 + t];
        out[g * 2 + t] = s;
    }
}

// ---------------- launch ----------------
extern "C" void kernel_launch(void* const* d_in, const int* in_sizes, int n_in,
                              void* d_out, int out_size) {
    const float* x = (const float*)d_in[0];
    const void* ei = d_in[1];
    const void* batch = d_in[2];
    const float* W1n = (const float*)d_in[3];
    const float* W1s = (const float*)d_in[4];
    const float* b1 = (const float*)d_in[5];
    const float* W2n = (const float*)d_in[6];
    const float* W2s = (const float*)d_in[7];
    const float* b2 = (const float*)d_in[8];
    const float* fc1w = (const float*)d_in[9];
    const float* fc1b = (const float*)d_in[10];
    const float* fc2w = (const float*)d_in[11];
    const float* fc2b = (const float*)d_in[12];
    float* out = (float*)d_out;

    const int n = in_sizes[2];            // 20000 nodes
    const int in_dim = in_sizes[0] / n;   // 512
    const int ne = in_sizes[1] / 2;       // 160000 edges

    static cudaStream_t s2 = nullptr;
    static cudaEvent_t evF = nullptr, evJ = nullptr;
    static int attr_set = 0;
    if (!attr_set) {
        cudaFuncSetAttribute(gemm_mma,
                             cudaFuncAttributeMaxDynamicSharedMemorySize,
                             GEMM_SMEM);
        cudaStreamCreateWithFlags(&s2, cudaStreamNonBlocking);
        cudaEventCreateWithFlags(&evF, cudaEventDisableTiming);
        cudaEventCreateWithFlags(&evJ, cudaEventDisableTiming);
        attr_set = 1;
    }

    const int nb = (n + SCB - 1) / SCB;

    // main stream: init -> hist -> prep -> gemm1
    init_kernel<<<160, 256>>>(ei, ne, n);
    edge_hist<<<(ne + 255) / 256, 256>>>(ei, ne);

    // fork: CSR finishing (rows + fill) runs concurrently with prep+gemm1
    cudaEventRecord(evF, 0);
    cudaStreamWaitEvent(s2, evF, 0);
    build_rows<<<nb, SCB, 0, s2>>>(n);
    csr_fill<<<(ne + 255) / 256, 256, 0, s2>>>(ei, ne);
    cudaEventRecord(evJ, s2);

    prep_all<<<592, 256>>>(W1n, W1s, W2n, W2s, x, in_dim, n * in_dim / 4);

    dim3 g1((n + 127) / 128, 4);
    gemm_mma<<<g1, 256, GEMM_SMEM>>>(n, in_dim, 0, b1);

    // join: aggregation needs the CSR
    cudaStreamWaitEvent(0, evJ, 0);
    sage_aggregate<<<(n + 3) / 4, 256>>>(n, 0);

    gemm_mma<<<g1, 256, GEMM_SMEM>>>(n, HID, 1, b2);
    sage_aggregate<<<(n + 3) / 4, 256>>>(n, 1);

    dim3 gp(NUM_GRAPHS, 32);
    pool_kernel<<<gp, HID>>>(batch, n);
    head_kernel<<<NUM_GRAPHS, HID>>>(batch, n, fc1w, fc1b, fc2w, fc2b, out);
}

// round 15
// speedup vs baseline: 4.9057x; 1.0282x over previous
#include <cuda_runtime.h>
#include <cuda_fp16.h>
#include <cstdint>

#define MAX_NODES 20000
#define MAX_EDGES 160000
#define HID 256
#define NUM_GRAPHS 16

// ---------------- device scratch (static, no runtime alloc) ----------------
__device__ __half g_bufA[MAX_NODES * HID];  // y_nbr projections (fp16)
__device__ __half g_bufB[MAX_NODES * HID];  // y_self projections +bias (fp16)
__device__ float  g_bufC[MAX_NODES * HID];  // h2 (fp32, for pooling)
__device__ int    g_deg[MAX_NODES];
__device__ int    g_rowstart[MAX_NODES];
__device__ int    g_cursor[MAX_NODES];
__device__ int    g_csr[MAX_EDGES];
__device__ float  g_pool[NUM_GRAPHS * HID];
__device__ int    g_bad;                    // !=0 -> index inputs are int32
__device__ int    g_base;                   // CSR allocation ticket

// A operand fp16 (padded to full 128-row tiles)
#define PAD_ROWS (MAX_NODES + 128)
__device__ __half g_Ah[PAD_ROWS * 512];

// transposed fp16 weights: WT[n][k], n in [0,512)
__device__ __half g_WT1h[512 * 512];
__device__ __half g_WT2h[512 * 256];

// ---------------- helpers ----------------
__device__ __forceinline__ uint32_t smem_u32(const void* p) {
    uint32_t a;
    asm("{ .reg .u64 t; cvta.to.shared.u64 t, %1; cvt.u32.u64 %0, t; }"
        : "=r"(a) : "l"(p));
    return a;
}
#define CP_ASYNC16(dst_u32, src_ptr) \
    asm volatile("cp.async.cg.shared.global [%0], [%1], 16;" \
                 :: "r"(dst_u32), "l"(src_ptr))
#define CP_COMMIT() asm volatile("cp.async.commit_group;" ::: "memory")
#define CP_WAIT(N) asm volatile("cp.async.wait_group %0;" :: "n"(N) : "memory")

__device__ __forceinline__ void ldsm_x4(uint32_t* r, uint32_t addr) {
    asm volatile(
        "ldmatrix.sync.aligned.m8n8.x4.shared.b16 {%0,%1,%2,%3}, [%4];"
        : "=r"(r[0]), "=r"(r[1]), "=r"(r[2]), "=r"(r[3]) : "r"(addr));
}

__device__ __forceinline__ int getIdx(const void* p, int i, int is64) {
    if (is64) return (int)((const long long*)p)[i];
    return ((const int*)p)[i];
}

// ---------------- init: zero + dtype probe (one launch) ----------------
__global__ void init_kernel(const void* ei, int ne, int n) {
    int i = blockIdx.x * blockDim.x + threadIdx.x;
    int stride = gridDim.x * blockDim.x;
    if (i == 0) { g_base = 0; }
    for (int j = i; j < n; j += stride) g_deg[j] = 0;
    for (int j = i; j < NUM_GRAPHS * HID; j += stride) g_pool[j] = 0.0f;
    int local = 0;
    for (int e = i; e < ne; e += stride) {
        long long v = ((const long long*)ei)[e];
        if (v < 0 || v >= (long long)n) local = 1;
    }
    if (i == 0) g_bad = 0;
    __threadfence();
    if (__syncthreads_or(local)) {
        if (threadIdx.x == 0) atomicOr(&g_bad, 1);
    }
}

// ---------------- CSR build ----------------
__global__ void edge_hist(const void* __restrict__ ei, int ne) {
    int e = blockIdx.x * blockDim.x + threadIdx.x;
    int is64 = (g_bad == 0);
    if (e < ne) {
        int d = getIdx(ei, ne + e, is64);
        atomicAdd(&g_deg[d], 1);
    }
}

#define SCB 256
__global__ void build_rows(int n) {
    __shared__ int sh[SCB];
    __shared__ int sbase;
    int t = threadIdx.x;
    int i = blockIdx.x * SCB + t;
    int d = (i < n) ? g_deg[i] : 0;
    sh[t] = d;
    __syncthreads();
    for (int off = 1; off < SCB; off <<= 1) {
        int v = (t >= off) ? sh[t - off] : 0;
        __syncthreads();
        sh[t] += v;
        __syncthreads();
    }
    if (t == SCB - 1) sbase = atomicAdd(&g_base, sh[SCB - 1]);
    __syncthreads();
    int excl = sh[t] - d;
    if (i < n) {
        g_rowstart[i] = sbase + excl;
        g_cursor[i] = sbase + excl;
    }
}

__global__ void csr_fill(const void* __restrict__ ei, int ne) {
    int e = blockIdx.x * blockDim.x + threadIdx.x;
    int is64 = (g_bad == 0);
    if (e < ne) {
        int s = getIdx(ei, e, is64);
        int d = getIdx(ei, ne + e, is64);
        int p = atomicAdd(&g_cursor[d], 1);
        g_csr[p] = s;
    }
}

// ---------------- operand prep (weights + x convert, one launch) -----------
__global__ void prep_all(const float* __restrict__ W1n,
                         const float* __restrict__ W1s,
                         const float* __restrict__ W2n,
                         const float* __restrict__ W2s,
                         const float* __restrict__ x, int K1, int nx4) {
    const int t1 = 512 * K1;
    const int tw = t1 + 512 * HID;
    const int total = tw + nx4;
    int stride = gridDim.x * blockDim.x;
    for (int idx = blockIdx.x * blockDim.x + threadIdx.x; idx < total;
         idx += stride) {
        if (idx < tw) {
            float v;
            __half* dh;
            int o;
            if (idx < t1) {
                int nrow = idx / K1, k = idx % K1;
                v = (nrow < 256) ? W1n[(size_t)k * 256 + nrow]
                                 : W1s[(size_t)k * 256 + (nrow - 256)];
                dh = g_WT1h; o = idx;
            } else {
                int j = idx - t1;
                int nrow = j / HID, k = j % HID;
                v = (nrow < 256) ? W2n[(size_t)k * 256 + nrow]
                                 : W2s[(size_t)k * 256 + (nrow - 256)];
                dh = g_WT2h; o = j;
            }
            dh[o] = __float2half(v);
        } else {
            int i = idx - tw;
            float4 v = ((const float4*)x)[i];
            __half h0 = __float2half(v.x);
            __half h1 = __float2half(v.y);
            __half h2 = __float2half(v.z);
            __half h3 = __float2half(v.w);
            uint32_t uh0 = (uint32_t)__half_as_ushort(h0) |
                           ((uint32_t)__half_as_ushort(h1) << 16);
            uint32_t uh1 = (uint32_t)__half_as_ushort(h2) |
                           ((uint32_t)__half_as_ushort(h3) << 16);
            ((uint2*)g_Ah)[i] = make_uint2(uh0, uh1);
        }
    }
}

// ---------------- HMMA dual GEMM, fp16 1-pass, 3-stage cp.async ------------
__device__ __forceinline__ void mma16816(float* c, const uint32_t* a,
                                         const uint32_t* b) {
    asm volatile(
        "mma.sync.aligned.m16n8k16.row.col.f32.f16.f16.f32 "
        "{%0,%1,%2,%3}, {%4,%5,%6,%7}, {%8,%9}, {%0,%1,%2,%3};"
        : "+f"(c[0]), "+f"(c[1]), "+f"(c[2]), "+f"(c[3])
        : "r"(a[0]), "r"(a[1]), "r"(a[2]), "r"(a[3]), "r"(b[0]), "r"(b[1]));
}

#define SROW 20                       // u32 per row (80 B)
#define SROWB 80
#define TILE_U32 (128 * SROW)
#define STAGE_U32 (2 * TILE_U32)      // A, B
#define NSTAGE 3
#define GEMM_SMEM (NSTAGE * STAGE_U32 * 4) // 61440 B

__global__ __launch_bounds__(256, 2) void gemm_mma(
    int M, int K, int layer, const float* __restrict__ bias) {
    extern __shared__ uint32_t smem[];
    const uint32_t sb = smem_u32(smem);

    const __half* Ah = g_Ah;
    const __half* WTh = layer ? g_WT2h : g_WT1h;

    const int tid = threadIdx.x;
    const int wid = tid >> 5;
    const int lane = tid & 31;
    const int g = lane >> 2;
    const int tg = lane & 3;
    const int wm = wid >> 2;
    const int wn = wid & 3;
    const int bm = blockIdx.x * 128;
    const int bn = blockIdx.y * 128;

    const int sub = lane >> 3;
    const int rin = lane & 7;
    const uint32_t a_row_off = (uint32_t)(rin + (sub & 1) * 8) * SROWB +
                               (uint32_t)(sub >> 1) * 16;
    const uint32_t b_row_off = (uint32_t)(rin + (sub >> 1) * 8) * SROWB +
                               (uint32_t)(sub & 1) * 16;

    float acc[4][4][4];
#pragma unroll
    for (int i = 0; i < 4; i++)
#pragma unroll
        for (int j = 0; j < 4; j++)
#pragma unroll
            for (int q = 0; q < 4; q++) acc[i][j][q] = 0.f;

    const int nch = K >> 5;

    auto load_chunk = [&](int ch, int stg) {
        const int k0 = ch << 5;
        const uint32_t sbase = sb + stg * (STAGE_U32 * 4);
#pragma unroll
        for (int r = 0; r < 2; r++) {
            int lin = tid + r * 256;
            int row = lin >> 2;
            int q = lin & 3;
            uint32_t o = (row * SROW + q * 4) * 4;
            int gr = bm + row;   // always valid: g_Ah padded
            const __half* pa = Ah + (size_t)gr * K + k0 + q * 8;
            CP_ASYNC16(sbase + o, pa);
            size_t gofs = (size_t)(bn + row) * K + k0 + q * 8;
            CP_ASYNC16(sbase + TILE_U32 * 4 + o, WTh + gofs);
        }
    };

    load_chunk(0, 0);
    CP_COMMIT();
    if (nch > 1) {
        load_chunk(1, 1);
        CP_COMMIT();
    }

    for (int ch = 0; ch < nch; ch++) {
        if (ch + 1 < nch) CP_WAIT(1); else CP_WAIT(0);
        __syncthreads();
        if (ch + 2 < nch) {
            load_chunk(ch + 2, (ch + 2) % NSTAGE);
            CP_COMMIT();
        }

        const uint32_t stg_b = sb + (ch % NSTAGE) * (STAGE_U32 * 4);
        const uint32_t aAh = stg_b;
        const uint32_t aBh = stg_b + TILE_U32 * 4;

#pragma unroll
        for (int ks = 0; ks < 2; ks++) {
            const uint32_t kofs = (uint32_t)ks * 32;
            uint32_t ah[4][4], bh[4][2];
#pragma unroll
            for (int mt = 0; mt < 4; mt++) {
                uint32_t rb = (uint32_t)(wm * 64 + mt * 16) * SROWB +
                              a_row_off + kofs;
                ldsm_x4(ah[mt], aAh + rb);
            }
#pragma unroll
            for (int p = 0; p < 2; p++) {
                uint32_t rb = (uint32_t)(wn * 32 + p * 16) * SROWB +
                              b_row_off + kofs;
                uint32_t t[4];
                ldsm_x4(t, aBh + rb);
                bh[2 * p][0] = t[0]; bh[2 * p][1] = t[1];
                bh[2 * p + 1][0] = t[2]; bh[2 * p + 1][1] = t[3];
            }
#pragma unroll
            for (int mt = 0; mt < 4; mt++)
#pragma unroll
                for (int nt = 0; nt < 4; nt++)
                    mma16816(acc[mt][nt], ah[mt], bh[nt]);
        }
    }

    // ---- epilogue: packed half2 stores ----
#pragma unroll
    for (int mt = 0; mt < 4; mt++) {
        int r0 = bm + wm * 64 + mt * 16 + g;
#pragma unroll
        for (int nt = 0; nt < 4; nt++) {
            int c = bn + wn * 32 + nt * 8 + tg * 2;
            float b0 = 0.f, b1 = 0.f;
            __half* dst;
            int cc = c;
            if (c >= 256) {
                cc = c - 256;
                b0 = bias[cc];
                b1 = bias[cc + 1];
                dst = g_bufB;
            } else {
                dst = g_bufA;
            }
            if (r0 < M) {
                __half2 v = __floats2half2_rn(acc[mt][nt][0] + b0,
                                              acc[mt][nt][1] + b1);
                *(__half2*)(dst + (size_t)r0 * HID + cc) = v;
            }
            if (r0 + 8 < M) {
                __half2 v = __floats2half2_rn(acc[mt][nt][2] + b0,
                                              acc[mt][nt][3] + b1);
                *(__half2*)(dst + (size_t)(r0 + 8) * HID + cc) = v;
            }
        }
    }
}

// ---- aggregation: 4 nodes/block x 64 threads; fp16 gathers, fp32 accum ----
__global__ void sage_aggregate(int n, int last) {
    int node = blockIdx.x * 4 + (threadIdx.x >> 6);
    int c = (threadIdx.x & 63) * 4;
    if (node >= n) return;
    int s0 = g_rowstart[node];
    int d = g_deg[node];
    float4 acc = make_float4(0.f, 0.f, 0.f, 0.f);
#pragma unroll 4
    for (int j = 0; j < d; j++) {
        int s = g_csr[s0 + j];
        uint2 u = *(const uint2*)(g_bufA + (size_t)s * HID + c);
        float2 f0 = __half22float2(*(__half2*)&u.x);
        float2 f1 = __half22float2(*(__half2*)&u.y);
        acc.x += f0.x; acc.y += f0.y; acc.z += f1.x; acc.w += f1.y;
    }
    float inv = 1.0f / (float)(d > 0 ? d : 1);
    uint2 uw = *(const uint2*)(g_bufB + (size_t)node * HID + c);
    float2 w0 = __half22float2(*(__half2*)&uw.x);
    float2 w1 = __half22float2(*(__half2*)&uw.y);
    float4 h;
    h.x = fmaxf(acc.x * inv + w0.x, 0.f);
    h.y = fmaxf(acc.y * inv + w0.y, 0.f);
    h.z = fmaxf(acc.z * inv + w1.x, 0.f);
    h.w = fmaxf(acc.w * inv + w1.y, 0.f);
    size_t o = (size_t)node * HID + c;
    if (last) {
        *(float4*)(g_bufC + o) = h;
    } else {
        __half2 p0 = __floats2half2_rn(h.x, h.y);
        __half2 p1 = __floats2half2_rn(h.z, h.w);
        uint32_t u0 = *(uint32_t*)&p0;
        uint32_t u1 = *(uint32_t*)&p1;
        *(uint2*)(g_Ah + o) = make_uint2(u0, u1);
    }
}

// ---------------- pooling / head ----------------
__device__ __forceinline__ int lower_bound_idx(const void* a, int n,
                                               int v, int is64) {
    int lo = 0, hi = n;
    while (lo < hi) {
        int mid = (lo + hi) >> 1;
        if (getIdx(a, mid, is64) < v) lo = mid + 1; else hi = mid;
    }
    return lo;
}

__global__ void pool_kernel(const void* __restrict__ batch, int n) {
    int g = blockIdx.x;
    int s = blockIdx.y;
    int S = gridDim.y;
    int is64 = (g_bad == 0);
    int lo = lower_bound_idx(batch, n, g, is64);
    int hi = lower_bound_idx(batch, n, g + 1, is64);
    int cnt = hi - lo;
    int chunk = (cnt + S - 1) / S;
    int a = lo + s * chunk;
    int b = a + chunk;
    if (b > hi) b = hi;
    int c = threadIdx.x;
    float acc = 0.f;
    for (int i = a; i < b; i++) acc += g_bufC[(size_t)i * HID + c];
    if (a < b) atomicAdd(&g_pool[g * HID + c], acc);
}

__global__ void head_kernel(const void* __restrict__ batch, int n,
                            const float* __restrict__ fc1w,
                            const float* __restrict__ fc1b,
                            const float* __restrict__ fc2w,
                            const float* __restrict__ fc2b,
                            float* __restrict__ out) {
    __shared__ float pooled[HID];
    __shared__ float t1[HID / 2];
    int t = threadIdx.x;  // 256
    int g = blockIdx.x;   // 16 blocks
    int is64 = (g_bad == 0);
    int lo = lower_bound_idx(batch, n, g, is64);
    int hi = lower_bound_idx(batch, n, g + 1, is64);
    float cnt = fmaxf((float)(hi - lo), 1.0f);
    pooled[t] = g_pool[g * HID + t] / cnt;
    __syncthreads();
    if (t < HID / 2) {
        float s = fc1b[t];
        for (int c = 0; c < HID; c++) s += pooled[c] * fc1w[c * (HID / 2) + t];
        t1[t] = fmaxf(s, 0.f);
    }
    __syncthreads();
    if (t < 2) {
        float s = fc2b[t];
        for (int j = 0; j < HID / 2; j++) s += t1[j] * fc2w[j * 2 + t];
        out[g * 2 + t] = s;
    }
}

// ---------------- launch ----------------
extern "C" void kernel_launch(void* const* d_in, const int* in_sizes, int n_in,
                              void* d_out, int out_size) {
    const float* x = (const float*)d_in[0];
    const void* ei = d_in[1];
    const void* batch = d_in[2];
    const float* W1n = (const float*)d_in[3];
    const float* W1s = (const float*)d_in[4];
    const float* b1 = (const float*)d_in[5];
    const float* W2n = (const float*)d_in[6];
    const float* W2s = (const float*)d_in[7];
    const float* b2 = (const float*)d_in[8];
    const float* fc1w = (const float*)d_in[9];
    const float* fc1b = (const float*)d_in[10];
    const float* fc2w = (const float*)d_in[11];
    const float* fc2b = (const float*)d_in[12];
    float* out = (float*)d_out;

    const int n = in_sizes[2];            // 20000 nodes
    const int in_dim = in_sizes[0] / n;   // 512
    const int ne = in_sizes[1] / 2;       // 160000 edges

    static cudaStream_t s2 = nullptr;
    static cudaEvent_t evF = nullptr, evJ = nullptr;
    static int attr_set = 0;
    if (!attr_set) {
        cudaFuncSetAttribute(gemm_mma,
                             cudaFuncAttributeMaxDynamicSharedMemorySize,
                             GEMM_SMEM);
        cudaStreamCreateWithFlags(&s2, cudaStreamNonBlocking);
        cudaEventCreateWithFlags(&evF, cudaEventDisableTiming);
        cudaEventCreateWithFlags(&evJ, cudaEventDisableTiming);
        attr_set = 1;
    }

    const int nb = (n + SCB - 1) / SCB;

    // main stream: init -> hist -> prep -> gemm1
    init_kernel<<<160, 256>>>(ei, ne, n);
    edge_hist<<<(ne + 255) / 256, 256>>>(ei, ne);

    // fork: CSR finishing (rows + fill) runs concurrently with prep+gemm1
    cudaEventRecord(evF, 0);
    cudaStreamWaitEvent(s2, evF, 0);
    build_rows<<<nb, SCB, 0, s2>>>(n);
    csr_fill<<<(ne + 255) / 256, 256, 0, s2>>>(ei, ne);
    cudaEventRecord(evJ, s2);

    prep_all<<<592, 256>>>(W1n, W1s, W2n, W2s, x, in_dim, n * in_dim / 4);

    dim3 g1((n + 127) / 128, 4);
    gemm_mma<<<g1, 256, GEMM_SMEM>>>(n, in_dim, 0, b1);

    // join: aggregation needs the CSR
    cudaStreamWaitEvent(0, evJ, 0);
    sage_aggregate<<<(n + 3) / 4, 256>>>(n, 0);

    gemm_mma<<<g1, 256, GEMM_SMEM>>>(n, HID, 1, b2);
    sage_aggregate<<<(n + 3) / 4, 256>>>(n, 1);

    dim3 gp(NUM_GRAPHS, 32);
    pool_kernel<<<gp, HID>>>(batch, n);
    head_kernel<<<NUM_GRAPHS, HID>>>(batch, n, fc1w, fc1b, fc2w, fc2b, out);
}